// round 2
// baseline (speedup 1.0000x reference)
#include <cuda_runtime.h>
#include <math.h>

#define HEADS 12
#define DIM   64
#define BATCH 2
#define SEQ   2048
#define EMB   768
#define QKVN  (3 * HEADS * DIM)   // 2304
#define ROWS  (BATCH * SEQ)       // 4096
#define MASKN (BATCH * SEQ * SEQ) // 8388608

// Scratch (device globals: allocation-free per harness rules)
__device__ float g_qkv[ROWS * QKVN];          // [B*N, 2304]
__device__ float g_att[ROWS * HEADS * DIM];   // [B*N, 768]
__device__ int   g_mask_esize;                // 1 or 4 bytes per element
__device__ int   g_mask_allones;              // 1 if every mask element is true

// ---------------------------------------------------------------------------
// Mask dtype detection: "true" encodings — uint8: word0=0x01010101,
// int32: 0x00000001, float32: 0x3f800000. In all encodings, an element is
// true iff its word/byte is nonzero.
// ---------------------------------------------------------------------------
__global__ void mask_detect_kernel(const unsigned int* __restrict__ mask) {
    unsigned int w0 = mask[0];
    int esize;
    if (w0 == 0x01010101u) esize = 1;
    else if (w0 == 1u || w0 == 0x3f800000u) esize = 4;
    else if ((w0 & 0xFFu) != 0u || (w0 >> 8) == 0u) esize = 1;  // fallback
    else esize = 4;
    g_mask_esize = esize;
    g_mask_allones = 1;
}

__global__ void mask_scan_kernel(const void* __restrict__ mask) {
    const int esize = g_mask_esize;
    bool any_zero = false;
    if (esize == 4) {
        const unsigned int* m = (const unsigned int*)mask;
        for (long long i = (long long)blockIdx.x * blockDim.x + threadIdx.x;
             i < MASKN; i += (long long)gridDim.x * blockDim.x)
            if (m[i] == 0u) { any_zero = true; break; }
    } else {
        const unsigned int* m = (const unsigned int*)mask;  // 4 elems per word
        for (long long i = (long long)blockIdx.x * blockDim.x + threadIdx.x;
             i < MASKN / 4; i += (long long)gridDim.x * blockDim.x) {
            unsigned int w = m[i];
            if ((w & 0xFFu) == 0 || (w & 0xFF00u) == 0 ||
                (w & 0xFF0000u) == 0 || (w & 0xFF000000u) == 0) { any_zero = true; break; }
        }
    }
    if (any_zero) g_mask_allones = 0;
}

// ---------------------------------------------------------------------------
// Tiled GEMM with bias: C[M,N] = A[M,K] @ B[K,N] + bias[N]
// BM=BN=64, BK=16, 256 threads, 4x4 per-thread micro-tile.
// ---------------------------------------------------------------------------
__global__ void gemm_bias_kernel(const float* __restrict__ A,
                                 const float* __restrict__ Bm,
                                 const float* __restrict__ bias,
                                 float* __restrict__ C,
                                 int M, int N, int K) {
    const int BM = 64, BN = 64, BK = 16;
    __shared__ float As[BK][BM + 4];
    __shared__ float Bs[BK][BN + 4];

    const int tid = threadIdx.x;
    const int tx = tid & 15;
    const int ty = tid >> 4;
    const int m0 = blockIdx.y * BM;
    const int n0 = blockIdx.x * BN;

    const int arow = tid >> 2;
    const int acol = (tid & 3) * 4;
    const int brow = tid >> 4;
    const int bcol = (tid & 15) * 4;

    float c[4][4];
#pragma unroll
    for (int i = 0; i < 4; i++)
#pragma unroll
        for (int j = 0; j < 4; j++) c[i][j] = 0.0f;

    for (int k0 = 0; k0 < K; k0 += BK) {
        __syncthreads();
        float4 av = *reinterpret_cast<const float4*>(&A[(size_t)(m0 + arow) * K + k0 + acol]);
        As[acol + 0][arow] = av.x;
        As[acol + 1][arow] = av.y;
        As[acol + 2][arow] = av.z;
        As[acol + 3][arow] = av.w;
        float4 bv = *reinterpret_cast<const float4*>(&Bm[(size_t)(k0 + brow) * N + n0 + bcol]);
        *reinterpret_cast<float4*>(&Bs[brow][bcol]) = bv;
        __syncthreads();

#pragma unroll
        for (int kk = 0; kk < BK; kk++) {
            float4 a4 = *reinterpret_cast<const float4*>(&As[kk][ty * 4]);
            float4 b4 = *reinterpret_cast<const float4*>(&Bs[kk][tx * 4]);
            float a[4] = {a4.x, a4.y, a4.z, a4.w};
            float b[4] = {b4.x, b4.y, b4.z, b4.w};
#pragma unroll
            for (int i = 0; i < 4; i++)
#pragma unroll
                for (int j = 0; j < 4; j++) c[i][j] = fmaf(a[i], b[j], c[i][j]);
        }
    }

#pragma unroll
    for (int j = 0; j < 4; j++) {
        float bb = bias[n0 + tx * 4 + j];
#pragma unroll
        for (int i = 0; i < 4; i++) c[i][j] += bb;
    }

#pragma unroll
    for (int i = 0; i < 4; i++) {
        float4 out = make_float4(c[i][0], c[i][1], c[i][2], c[i][3]);
        *reinterpret_cast<float4*>(&C[(size_t)(m0 + ty * 4 + i) * N + n0 + tx * 4]) = out;
    }
}

// ---------------------------------------------------------------------------
// Flash-attention style kernel. One block = (batch b, head h, 64-query tile).
// ---------------------------------------------------------------------------
#define SPAD 68
__global__ void attn_kernel(const float* __restrict__ qkv,
                            const void* __restrict__ mask,
                            float* __restrict__ att) {
    extern __shared__ float sm[];
    float* Qs  = sm;
    float* Kts = Qs  + 64 * SPAD;
    float* Vs  = Kts + 64 * SPAD;
    float* Ps  = Vs  + 64 * SPAD;

    const int tid = threadIdx.x;
    const int tx = tid & 15;
    const int ty = tid >> 4;
    const int qt = blockIdx.x;
    const int h  = blockIdx.y;
    const int b  = blockIdx.z;
    const int q0 = qt * 64;

    const int mask_allones = g_mask_allones;
    const int mask_esize   = g_mask_esize;

    const size_t qkv_row_base = (size_t)b * SEQ * QKVN;
    const int hoff = h * DIM;

    for (int idx = tid; idx < 64 * 64; idx += 256) {
        int i = idx >> 6, d = idx & 63;
        Qs[i * SPAD + d] = qkv[qkv_row_base + (size_t)(q0 + i) * QKVN + hoff + d];
    }

    float acc[4][4];
    float mrow[4], lrow[4];
#pragma unroll
    for (int i = 0; i < 4; i++) {
        mrow[i] = -1e30f;
        lrow[i] = 0.0f;
#pragma unroll
        for (int j = 0; j < 4; j++) acc[i][j] = 0.0f;
    }

    const float scale = 0.125f; // 1/sqrt(64)
    const size_t mask_base = (size_t)b * SEQ * SEQ;

    for (int kt = 0; kt < SEQ / 64; kt++) {
        const int k0 = kt * 64;
        __syncthreads();
        for (int idx = tid; idx < 64 * 64; idx += 256) {
            int n = idx >> 6, d = idx & 63;
            size_t row = qkv_row_base + (size_t)(k0 + n) * QKVN + hoff;
            Kts[d * SPAD + n] = qkv[row + 768 + d];
            Vs[n * SPAD + d]  = qkv[row + 1536 + d];
        }
        __syncthreads();

        float s[4][4];
#pragma unroll
        for (int i = 0; i < 4; i++)
#pragma unroll
            for (int j = 0; j < 4; j++) s[i][j] = 0.0f;

#pragma unroll 8
        for (int d = 0; d < 64; d++) {
            float4 kv = *reinterpret_cast<const float4*>(&Kts[d * SPAD + tx * 4]);
            float kk[4] = {kv.x, kv.y, kv.z, kv.w};
#pragma unroll
            for (int i = 0; i < 4; i++) {
                float q = Qs[(ty * 4 + i) * SPAD + d];
#pragma unroll
                for (int j = 0; j < 4; j++) s[i][j] = fmaf(q, kk[j], s[i][j]);
            }
        }

        if (mask_allones) {
            // fast path: mask is all-true, just scale
#pragma unroll
            for (int i = 0; i < 4; i++)
#pragma unroll
                for (int j = 0; j < 4; j++) s[i][j] *= scale;
        } else {
#pragma unroll
            for (int i = 0; i < 4; i++) {
                size_t eidx = mask_base + (size_t)(q0 + ty * 4 + i) * SEQ + k0 + tx * 4;
                bool mk[4];
                if (mask_esize == 4) {
                    uint4 w = *reinterpret_cast<const uint4*>((const unsigned int*)mask + eidx);
                    mk[0] = w.x != 0; mk[1] = w.y != 0; mk[2] = w.z != 0; mk[3] = w.w != 0;
                } else {
                    uchar4 w = *reinterpret_cast<const uchar4*>((const unsigned char*)mask + eidx);
                    mk[0] = w.x != 0; mk[1] = w.y != 0; mk[2] = w.z != 0; mk[3] = w.w != 0;
                }
#pragma unroll
                for (int j = 0; j < 4; j++)
                    s[i][j] = mk[j] ? s[i][j] * scale : -1e9f;
            }
        }

        // online softmax update
#pragma unroll
        for (int i = 0; i < 4; i++) {
            float mt = fmaxf(fmaxf(s[i][0], s[i][1]), fmaxf(s[i][2], s[i][3]));
            mt = fmaxf(mt, __shfl_xor_sync(0xffffffff, mt, 1));
            mt = fmaxf(mt, __shfl_xor_sync(0xffffffff, mt, 2));
            mt = fmaxf(mt, __shfl_xor_sync(0xffffffff, mt, 4));
            mt = fmaxf(mt, __shfl_xor_sync(0xffffffff, mt, 8));
            float mnew = fmaxf(mrow[i], mt);
            float alpha = __expf(mrow[i] - mnew);
            mrow[i] = mnew;

            float p0 = __expf(s[i][0] - mnew);
            float p1 = __expf(s[i][1] - mnew);
            float p2 = __expf(s[i][2] - mnew);
            float p3 = __expf(s[i][3] - mnew);
            float lt = (p0 + p1) + (p2 + p3);
            lt += __shfl_xor_sync(0xffffffff, lt, 1);
            lt += __shfl_xor_sync(0xffffffff, lt, 2);
            lt += __shfl_xor_sync(0xffffffff, lt, 4);
            lt += __shfl_xor_sync(0xffffffff, lt, 8);
            lrow[i] = lrow[i] * alpha + lt;
#pragma unroll
            for (int j = 0; j < 4; j++) acc[i][j] *= alpha;

            float* prow = &Ps[(ty * 4 + i) * SPAD + tx * 4];
            prow[0] = p0; prow[1] = p1; prow[2] = p2; prow[3] = p3;
        }
        __syncthreads();

#pragma unroll 8
        for (int n = 0; n < 64; n++) {
            float4 vv = *reinterpret_cast<const float4*>(&Vs[n * SPAD + tx * 4]);
            float v[4] = {vv.x, vv.y, vv.z, vv.w};
#pragma unroll
            for (int i = 0; i < 4; i++) {
                float p = Ps[(ty * 4 + i) * SPAD + n];
#pragma unroll
                for (int j = 0; j < 4; j++) acc[i][j] = fmaf(p, v[j], acc[i][j]);
            }
        }
    }

#pragma unroll
    for (int i = 0; i < 4; i++) {
        float inv = 1.0f / lrow[i];
        float4 out = make_float4(acc[i][0] * inv, acc[i][1] * inv,
                                 acc[i][2] * inv, acc[i][3] * inv);
        size_t row = (size_t)b * SEQ + q0 + ty * 4 + i;
        *reinterpret_cast<float4*>(&g_att[row * (HEADS * DIM) + hoff + tx * 4]) = out;
    }
}

// ---------------------------------------------------------------------------
extern "C" void kernel_launch(void* const* d_in, const int* in_sizes, int n_in,
                              void* d_out, int out_size) {
    const float* x      = (const float*)d_in[0];
    const void*  mask   = d_in[1];
    const float* W_pre  = (const float*)d_in[2];
    const float* b_pre  = (const float*)d_in[3];
    const float* W_proj = (const float*)d_in[4];
    const float* b_proj = (const float*)d_in[5];
    float* out = (float*)d_out;

    float* qkv;
    float* att;
    cudaGetSymbolAddress((void**)&qkv, g_qkv);
    cudaGetSymbolAddress((void**)&att, g_att);

    // 0) Mask dtype detection + all-ones scan
    mask_detect_kernel<<<1, 1>>>((const unsigned int*)mask);
    mask_scan_kernel<<<256, 256>>>(mask);

    // 1) QKV GEMM: [4096,768] @ [768,2304] + b_pre
    {
        dim3 grid(QKVN / 64, ROWS / 64);
        gemm_bias_kernel<<<grid, 256>>>(x, W_pre, b_pre, qkv, ROWS, QKVN, EMB);
    }

    // 2) Attention
    {
        int smem = 4 * 64 * SPAD * sizeof(float);  // 69632 B
        cudaFuncSetAttribute(attn_kernel,
                             cudaFuncAttributeMaxDynamicSharedMemorySize, smem);
        dim3 grid(SEQ / 64, HEADS, BATCH);
        attn_kernel<<<grid, 256, smem>>>(qkv, mask, att);
    }

    // 3) Projection GEMM: [4096,768] @ [768,768] + b_proj -> out
    {
        dim3 grid(EMB / 64, ROWS / 64);
        gemm_bias_kernel<<<grid, 256>>>(att, W_proj, b_proj, out, ROWS, EMB, EMB);
    }
}

// round 4
// speedup vs baseline: 1.0577x; 1.0577x over previous
#include <cuda_runtime.h>
#include <math.h>
#include <stdint.h>

#define HEADS 12
#define DIM   64
#define BATCH 2
#define SEQ   2048
#define EMB   768
#define QKVN  (3 * HEADS * DIM)   // 2304
#define ROWS  (BATCH * SEQ)       // 4096
#define MASKN (BATCH * SEQ * SEQ) // 8388608

__device__ float g_qkv[ROWS * QKVN];
__device__ float g_att[ROWS * HEADS * DIM];
__device__ int   g_mask_esize;
__device__ int   g_mask_allones;

// ============================ helpers =======================================
__device__ __forceinline__ void split_tf32(float x, uint32_t& hi, uint32_t& lo) {
    asm("cvt.rna.tf32.f32 %0, %1;" : "=r"(hi) : "f"(x));
    float r = x - __uint_as_float(hi);
    asm("cvt.rna.tf32.f32 %0, %1;" : "=r"(lo) : "f"(r));
}

__device__ __forceinline__ void mma_tf32(float c[4],
                                         uint32_t a0, uint32_t a1, uint32_t a2, uint32_t a3,
                                         uint32_t b0, uint32_t b1) {
    asm volatile(
        "mma.sync.aligned.m16n8k8.row.col.f32.tf32.tf32.f32 "
        "{%0,%1,%2,%3}, {%4,%5,%6,%7}, {%8,%9}, {%0,%1,%2,%3};"
        : "+f"(c[0]), "+f"(c[1]), "+f"(c[2]), "+f"(c[3])
        : "r"(a0), "r"(a1), "r"(a2), "r"(a3), "r"(b0), "r"(b1));
}

// ============================ tf32 mma.sync GEMM ============================
// C[M,N] = A[M,K] @ B[K,N] + bias. 3xTF32 split => ~fp32 accuracy.
// CTA tile 128x64, BK=32, 256 threads (8 warps), warp tile 32x32.
// SMEM: Ahi/Alo [128][36], Bhi/Blo [64][36] (B stored [n][k]).
#define ASTR 36
#define SM_AHI 0
#define SM_ALO (128 * ASTR)
#define SM_BHI (SM_ALO + 128 * ASTR)
#define SM_BLO (SM_BHI + 64 * ASTR)
#define GSM_FLOATS (SM_BLO + 64 * ASTR)
#define GSM_BYTES  (GSM_FLOATS * 4)    // 55296

__global__ void __launch_bounds__(256)
gemm_tf32_kernel(const float* __restrict__ A, const float* __restrict__ B,
                 const float* __restrict__ bias, float* __restrict__ C,
                 int M, int N, int K) {
    extern __shared__ float sh[];
    float* sAhi = sh + SM_AHI;
    float* sAlo = sh + SM_ALO;
    float* sBhi = sh + SM_BHI;
    float* sBlo = sh + SM_BLO;

    const int tid = threadIdx.x;
    const int wid = tid >> 5;
    const int lane = tid & 31;
    const int g  = lane >> 2;        // group id 0..7
    const int tq = lane & 3;         // 0..3
    const int wm = wid >> 1;         // 0..3 (m), 32 rows each
    const int wn = wid & 1;          // 0..1 (n), 32 cols each
    const int m0 = blockIdx.y * 128;
    const int n0 = blockIdx.x * 64;

    float acc[2][4][4];
#pragma unroll
    for (int i = 0; i < 2; i++)
#pragma unroll
        for (int j = 0; j < 4; j++)
#pragma unroll
            for (int r = 0; r < 4; r++) acc[i][j][r] = 0.0f;

    // prefetch registers
    float4 aReg[4];
    float4 bReg[2];

    const int nkt = K / 32;

    // preload tile 0
    {
        const float* Ab = A + (size_t)m0 * K;
#pragma unroll
        for (int p = 0; p < 4; p++) {
            int idx = p * 256 + tid;
            int r = idx >> 3, c = idx & 7;
            aReg[p] = *reinterpret_cast<const float4*>(Ab + (size_t)r * K + c * 4);
        }
        const float* Bb = B + n0;
#pragma unroll
        for (int p = 0; p < 2; p++) {
            int idx = p * 256 + tid;
            int kr = idx >> 4, c = idx & 15;
            bReg[p] = *reinterpret_cast<const float4*>(Bb + (size_t)kr * N + c * 4);
        }
    }

    for (int kt = 0; kt < nkt; kt++) {
        __syncthreads();
        // ---- store prefetched tile into smem (with tf32 split) ----
#pragma unroll
        for (int p = 0; p < 4; p++) {
            int idx = p * 256 + tid;
            int r = idx >> 3, c = idx & 7;
            uint32_t hx, lx, hy, ly, hz, lz, hw, lw;
            split_tf32(aReg[p].x, hx, lx); split_tf32(aReg[p].y, hy, ly);
            split_tf32(aReg[p].z, hz, lz); split_tf32(aReg[p].w, hw, lw);
            *reinterpret_cast<uint4*>(&sAhi[r * ASTR + c * 4]) = make_uint4(hx, hy, hz, hw);
            *reinterpret_cast<uint4*>(&sAlo[r * ASTR + c * 4]) = make_uint4(lx, ly, lz, lw);
        }
#pragma unroll
        for (int p = 0; p < 2; p++) {
            int idx = p * 256 + tid;
            int kr = idx >> 4, c = idx & 15;
            float vv[4] = {bReg[p].x, bReg[p].y, bReg[p].z, bReg[p].w};
#pragma unroll
            for (int jj = 0; jj < 4; jj++) {
                uint32_t hi, lo;
                split_tf32(vv[jj], hi, lo);
                sBhi[(c * 4 + jj) * ASTR + kr] = __uint_as_float(hi);
                sBlo[(c * 4 + jj) * ASTR + kr] = __uint_as_float(lo);
            }
        }
        __syncthreads();

        // ---- prefetch next tile ----
        if (kt + 1 < nkt) {
            const float* Ab = A + (size_t)m0 * K + (kt + 1) * 32;
#pragma unroll
            for (int p = 0; p < 4; p++) {
                int idx = p * 256 + tid;
                int r = idx >> 3, c = idx & 7;
                aReg[p] = *reinterpret_cast<const float4*>(Ab + (size_t)r * K + c * 4);
            }
            const float* Bb = B + (size_t)((kt + 1) * 32) * N + n0;
#pragma unroll
            for (int p = 0; p < 2; p++) {
                int idx = p * 256 + tid;
                int kr = idx >> 4, c = idx & 15;
                bReg[p] = *reinterpret_cast<const float4*>(Bb + (size_t)kr * N + c * 4);
            }
        }

        // ---- MMA over BK=32 (4 k-steps of 8) ----
#pragma unroll
        for (int ks = 0; ks < 4; ks++) {
            const int kb = ks * 8;
            uint32_t ahi[2][4], alo[2][4];
#pragma unroll
            for (int i = 0; i < 2; i++) {
                const int rbase = (wm * 32 + i * 16 + g) * ASTR + kb + tq;
                ahi[i][0] = __float_as_uint(sAhi[rbase]);
                ahi[i][1] = __float_as_uint(sAhi[rbase + 8 * ASTR]);
                ahi[i][2] = __float_as_uint(sAhi[rbase + 4]);
                ahi[i][3] = __float_as_uint(sAhi[rbase + 8 * ASTR + 4]);
                alo[i][0] = __float_as_uint(sAlo[rbase]);
                alo[i][1] = __float_as_uint(sAlo[rbase + 8 * ASTR]);
                alo[i][2] = __float_as_uint(sAlo[rbase + 4]);
                alo[i][3] = __float_as_uint(sAlo[rbase + 8 * ASTR + 4]);
            }
            uint32_t bhi[4][2], blo[4][2];
#pragma unroll
            for (int j = 0; j < 4; j++) {
                const int cbase = (wn * 32 + j * 8 + g) * ASTR + kb + tq;
                bhi[j][0] = __float_as_uint(sBhi[cbase]);
                bhi[j][1] = __float_as_uint(sBhi[cbase + 4]);
                blo[j][0] = __float_as_uint(sBlo[cbase]);
                blo[j][1] = __float_as_uint(sBlo[cbase + 4]);
            }
#pragma unroll
            for (int i = 0; i < 2; i++)
#pragma unroll
                for (int j = 0; j < 4; j++) {
                    mma_tf32(acc[i][j], ahi[i][0], ahi[i][1], ahi[i][2], ahi[i][3],
                             blo[j][0], blo[j][1]);
                    mma_tf32(acc[i][j], alo[i][0], alo[i][1], alo[i][2], alo[i][3],
                             bhi[j][0], bhi[j][1]);
                    mma_tf32(acc[i][j], ahi[i][0], ahi[i][1], ahi[i][2], ahi[i][3],
                             bhi[j][0], bhi[j][1]);
                }
        }
    }

    // ---- epilogue ----
#pragma unroll
    for (int i = 0; i < 2; i++) {
        const int row = m0 + wm * 32 + i * 16 + g;
#pragma unroll
        for (int j = 0; j < 4; j++) {
            const int col = n0 + wn * 32 + j * 8 + 2 * tq;
            const float b0 = bias[col], b1 = bias[col + 1];
            float2 o1 = make_float2(acc[i][j][0] + b0, acc[i][j][1] + b1);
            float2 o2 = make_float2(acc[i][j][2] + b0, acc[i][j][3] + b1);
            *reinterpret_cast<float2*>(&C[(size_t)row * N + col]) = o1;
            *reinterpret_cast<float2*>(&C[(size_t)(row + 8) * N + col]) = o2;
        }
    }
}

// ============================ mask handling =================================
__global__ void mask_detect_kernel(const unsigned int* __restrict__ mask) {
    unsigned int w0 = mask[0];
    int esize;
    if (w0 == 0x01010101u) esize = 1;
    else if (w0 == 1u || w0 == 0x3f800000u) esize = 4;
    else if ((w0 & 0xFFu) != 0u || (w0 >> 8) == 0u) esize = 1;
    else esize = 4;
    g_mask_esize = esize;
    g_mask_allones = 1;
}

__global__ void mask_scan_kernel(const void* __restrict__ mask) {
    const int esize = g_mask_esize;
    bool any_zero = false;
    if (esize == 4) {
        const unsigned int* m = (const unsigned int*)mask;
        for (long long i = (long long)blockIdx.x * blockDim.x + threadIdx.x;
             i < MASKN; i += (long long)gridDim.x * blockDim.x)
            if (m[i] == 0u) { any_zero = true; break; }
    } else {
        const unsigned int* m = (const unsigned int*)mask;
        for (long long i = (long long)blockIdx.x * blockDim.x + threadIdx.x;
             i < MASKN / 4; i += (long long)gridDim.x * blockDim.x) {
            unsigned int w = m[i];
            if ((w & 0xFFu) == 0 || (w & 0xFF00u) == 0 ||
                (w & 0xFF0000u) == 0 || (w & 0xFF000000u) == 0) { any_zero = true; break; }
        }
    }
    if (any_zero) g_mask_allones = 0;
}

// ============================ attention (unchanged, passing) ================
#define SPAD 68
__global__ void attn_kernel(const float* __restrict__ qkv,
                            const void* __restrict__ mask,
                            float* __restrict__ att) {
    extern __shared__ float smf[];
    float* Qs  = smf;
    float* Kts = Qs  + 64 * SPAD;
    float* Vs  = Kts + 64 * SPAD;
    float* Ps  = Vs  + 64 * SPAD;

    const int tid = threadIdx.x;
    const int tx = tid & 15;
    const int ty = tid >> 4;
    const int qt = blockIdx.x;
    const int h  = blockIdx.y;
    const int b  = blockIdx.z;
    const int q0 = qt * 64;

    const int mask_allones = g_mask_allones;
    const int mask_esize   = g_mask_esize;

    const size_t qkv_row_base = (size_t)b * SEQ * QKVN;
    const int hoff = h * DIM;

    for (int idx = tid; idx < 64 * 64; idx += 256) {
        int i = idx >> 6, d = idx & 63;
        Qs[i * SPAD + d] = qkv[qkv_row_base + (size_t)(q0 + i) * QKVN + hoff + d];
    }

    float acc[4][4];
    float mrow[4], lrow[4];
#pragma unroll
    for (int i = 0; i < 4; i++) {
        mrow[i] = -1e30f;
        lrow[i] = 0.0f;
#pragma unroll
        for (int j = 0; j < 4; j++) acc[i][j] = 0.0f;
    }

    const float scale = 0.125f;
    const size_t mask_base = (size_t)b * SEQ * SEQ;

    for (int kt = 0; kt < SEQ / 64; kt++) {
        const int k0 = kt * 64;
        __syncthreads();
        for (int idx = tid; idx < 64 * 64; idx += 256) {
            int n = idx >> 6, d = idx & 63;
            size_t row = qkv_row_base + (size_t)(k0 + n) * QKVN + hoff;
            Kts[d * SPAD + n] = qkv[row + 768 + d];
            Vs[n * SPAD + d]  = qkv[row + 1536 + d];
        }
        __syncthreads();

        float s[4][4];
#pragma unroll
        for (int i = 0; i < 4; i++)
#pragma unroll
            for (int j = 0; j < 4; j++) s[i][j] = 0.0f;

#pragma unroll 8
        for (int d = 0; d < 64; d++) {
            float4 kv = *reinterpret_cast<const float4*>(&Kts[d * SPAD + tx * 4]);
            float kk[4] = {kv.x, kv.y, kv.z, kv.w};
#pragma unroll
            for (int i = 0; i < 4; i++) {
                float q = Qs[(ty * 4 + i) * SPAD + d];
#pragma unroll
                for (int j = 0; j < 4; j++) s[i][j] = fmaf(q, kk[j], s[i][j]);
            }
        }

        if (mask_allones) {
#pragma unroll
            for (int i = 0; i < 4; i++)
#pragma unroll
                for (int j = 0; j < 4; j++) s[i][j] *= scale;
        } else {
#pragma unroll
            for (int i = 0; i < 4; i++) {
                size_t eidx = mask_base + (size_t)(q0 + ty * 4 + i) * SEQ + k0 + tx * 4;
                bool mk[4];
                if (mask_esize == 4) {
                    uint4 w = *reinterpret_cast<const uint4*>((const unsigned int*)mask + eidx);
                    mk[0] = w.x != 0; mk[1] = w.y != 0; mk[2] = w.z != 0; mk[3] = w.w != 0;
                } else {
                    uchar4 w = *reinterpret_cast<const uchar4*>((const unsigned char*)mask + eidx);
                    mk[0] = w.x != 0; mk[1] = w.y != 0; mk[2] = w.z != 0; mk[3] = w.w != 0;
                }
#pragma unroll
                for (int j = 0; j < 4; j++)
                    s[i][j] = mk[j] ? s[i][j] * scale : -1e9f;
            }
        }

#pragma unroll
        for (int i = 0; i < 4; i++) {
            float mt = fmaxf(fmaxf(s[i][0], s[i][1]), fmaxf(s[i][2], s[i][3]));
            mt = fmaxf(mt, __shfl_xor_sync(0xffffffff, mt, 1));
            mt = fmaxf(mt, __shfl_xor_sync(0xffffffff, mt, 2));
            mt = fmaxf(mt, __shfl_xor_sync(0xffffffff, mt, 4));
            mt = fmaxf(mt, __shfl_xor_sync(0xffffffff, mt, 8));
            float mnew = fmaxf(mrow[i], mt);
            float alpha = __expf(mrow[i] - mnew);
            mrow[i] = mnew;

            float p0 = __expf(s[i][0] - mnew);
            float p1 = __expf(s[i][1] - mnew);
            float p2 = __expf(s[i][2] - mnew);
            float p3 = __expf(s[i][3] - mnew);
            float lt = (p0 + p1) + (p2 + p3);
            lt += __shfl_xor_sync(0xffffffff, lt, 1);
            lt += __shfl_xor_sync(0xffffffff, lt, 2);
            lt += __shfl_xor_sync(0xffffffff, lt, 4);
            lt += __shfl_xor_sync(0xffffffff, lt, 8);
            lrow[i] = lrow[i] * alpha + lt;
#pragma unroll
            for (int j = 0; j < 4; j++) acc[i][j] *= alpha;

            float* prow = &Ps[(ty * 4 + i) * SPAD + tx * 4];
            prow[0] = p0; prow[1] = p1; prow[2] = p2; prow[3] = p3;
        }
        __syncthreads();

#pragma unroll 8
        for (int n = 0; n < 64; n++) {
            float4 vv = *reinterpret_cast<const float4*>(&Vs[n * SPAD + tx * 4]);
            float v[4] = {vv.x, vv.y, vv.z, vv.w};
#pragma unroll
            for (int i = 0; i < 4; i++) {
                float p = Ps[(ty * 4 + i) * SPAD + n];
#pragma unroll
                for (int j = 0; j < 4; j++) acc[i][j] = fmaf(p, v[j], acc[i][j]);
            }
        }
    }

#pragma unroll
    for (int i = 0; i < 4; i++) {
        float inv = 1.0f / lrow[i];
        float4 out = make_float4(acc[i][0] * inv, acc[i][1] * inv,
                                 acc[i][2] * inv, acc[i][3] * inv);
        size_t row = (size_t)b * SEQ + q0 + ty * 4 + i;
        *reinterpret_cast<float4*>(&g_att[row * (HEADS * DIM) + hoff + tx * 4]) = out;
    }
}

// ============================================================================
extern "C" void kernel_launch(void* const* d_in, const int* in_sizes, int n_in,
                              void* d_out, int out_size) {
    const float* x      = (const float*)d_in[0];
    const void*  mask   = d_in[1];
    const float* W_pre  = (const float*)d_in[2];
    const float* b_pre  = (const float*)d_in[3];
    const float* W_proj = (const float*)d_in[4];
    const float* b_proj = (const float*)d_in[5];
    float* out = (float*)d_out;

    float* qkv;
    float* att;
    cudaGetSymbolAddress((void**)&qkv, g_qkv);
    cudaGetSymbolAddress((void**)&att, g_att);

    // 0) Mask dtype detection + all-ones scan
    mask_detect_kernel<<<1, 1>>>((const unsigned int*)mask);
    mask_scan_kernel<<<256, 256>>>(mask);

    cudaFuncSetAttribute(gemm_tf32_kernel,
                         cudaFuncAttributeMaxDynamicSharedMemorySize, GSM_BYTES);

    // 1) QKV GEMM (tf32 mma.sync): [4096,768] @ [768,2304] + b_pre
    {
        dim3 grid(QKVN / 64, ROWS / 128);
        gemm_tf32_kernel<<<grid, 256, GSM_BYTES>>>(x, W_pre, b_pre, qkv,
                                                   ROWS, QKVN, EMB);
    }

    // 2) Attention
    {
        int smem = 4 * 64 * SPAD * sizeof(float);
        cudaFuncSetAttribute(attn_kernel,
                             cudaFuncAttributeMaxDynamicSharedMemorySize, smem);
        dim3 grid(SEQ / 64, HEADS, BATCH);
        attn_kernel<<<grid, 256, smem>>>(qkv, mask, att);
    }

    // 3) Projection GEMM (tf32 mma.sync): [4096,768] @ [768,768] + b_proj
    {
        dim3 grid(EMB / 64, ROWS / 128);
        gemm_tf32_kernel<<<grid, 256, GSM_BYTES>>>(att, W_proj, b_proj, out,
                                                   ROWS, EMB, EMB);
    }
}

// round 5
// speedup vs baseline: 1.4264x; 1.3486x over previous
#include <cuda_runtime.h>
#include <math.h>
#include <stdint.h>

#define HEADS 12
#define DIM   64
#define BATCH 2
#define SEQ   2048
#define EMB   768
#define QKVN  (3 * HEADS * DIM)   // 2304
#define ROWS  (BATCH * SEQ)       // 4096
#define MASKN (BATCH * SEQ * SEQ) // 8388608

__device__ float g_qkv[ROWS * QKVN];
__device__ float g_att[ROWS * HEADS * DIM];
__device__ int   g_mask_esize;
__device__ int   g_mask_allones;

// ============================ helpers =======================================
__device__ __forceinline__ uint32_t to_tf32(float x) {
    uint32_t r;
    asm("cvt.rna.tf32.f32 %0, %1;" : "=r"(r) : "f"(x));
    return r;
}
__device__ __forceinline__ void split_tf32(float x, uint32_t& hi, uint32_t& lo) {
    asm("cvt.rna.tf32.f32 %0, %1;" : "=r"(hi) : "f"(x));
    float r = x - __uint_as_float(hi);
    asm("cvt.rna.tf32.f32 %0, %1;" : "=r"(lo) : "f"(r));
}
__device__ __forceinline__ void mma_tf32(float c[4],
                                         uint32_t a0, uint32_t a1, uint32_t a2, uint32_t a3,
                                         uint32_t b0, uint32_t b1) {
    asm volatile(
        "mma.sync.aligned.m16n8k8.row.col.f32.tf32.tf32.f32 "
        "{%0,%1,%2,%3}, {%4,%5,%6,%7}, {%8,%9}, {%0,%1,%2,%3};"
        : "+f"(c[0]), "+f"(c[1]), "+f"(c[2]), "+f"(c[3])
        : "r"(a0), "r"(a1), "r"(a2), "r"(a3), "r"(b0), "r"(b1));
}

// ============================ tf32 mma.sync GEMM (unchanged, passing) =======
#define ASTR 36
#define SM_AHI 0
#define SM_ALO (128 * ASTR)
#define SM_BHI (SM_ALO + 128 * ASTR)
#define SM_BLO (SM_BHI + 64 * ASTR)
#define GSM_FLOATS (SM_BLO + 64 * ASTR)
#define GSM_BYTES  (GSM_FLOATS * 4)

__global__ void __launch_bounds__(256)
gemm_tf32_kernel(const float* __restrict__ A, const float* __restrict__ B,
                 const float* __restrict__ bias, float* __restrict__ C,
                 int M, int N, int K) {
    extern __shared__ float sh[];
    float* sAhi = sh + SM_AHI;
    float* sAlo = sh + SM_ALO;
    float* sBhi = sh + SM_BHI;
    float* sBlo = sh + SM_BLO;

    const int tid = threadIdx.x;
    const int wid = tid >> 5;
    const int lane = tid & 31;
    const int g  = lane >> 2;
    const int tq = lane & 3;
    const int wm = wid >> 1;
    const int wn = wid & 1;
    const int m0 = blockIdx.y * 128;
    const int n0 = blockIdx.x * 64;

    float acc[2][4][4];
#pragma unroll
    for (int i = 0; i < 2; i++)
#pragma unroll
        for (int j = 0; j < 4; j++)
#pragma unroll
            for (int r = 0; r < 4; r++) acc[i][j][r] = 0.0f;

    float4 aReg[4];
    float4 bReg[2];
    const int nkt = K / 32;

    {
        const float* Ab = A + (size_t)m0 * K;
#pragma unroll
        for (int p = 0; p < 4; p++) {
            int idx = p * 256 + tid;
            int r = idx >> 3, c = idx & 7;
            aReg[p] = *reinterpret_cast<const float4*>(Ab + (size_t)r * K + c * 4);
        }
        const float* Bb = B + n0;
#pragma unroll
        for (int p = 0; p < 2; p++) {
            int idx = p * 256 + tid;
            int kr = idx >> 4, c = idx & 15;
            bReg[p] = *reinterpret_cast<const float4*>(Bb + (size_t)kr * N + c * 4);
        }
    }

    for (int kt = 0; kt < nkt; kt++) {
        __syncthreads();
#pragma unroll
        for (int p = 0; p < 4; p++) {
            int idx = p * 256 + tid;
            int r = idx >> 3, c = idx & 7;
            uint32_t hx, lx, hy, ly, hz, lz, hw, lw;
            split_tf32(aReg[p].x, hx, lx); split_tf32(aReg[p].y, hy, ly);
            split_tf32(aReg[p].z, hz, lz); split_tf32(aReg[p].w, hw, lw);
            *reinterpret_cast<uint4*>(&sAhi[r * ASTR + c * 4]) = make_uint4(hx, hy, hz, hw);
            *reinterpret_cast<uint4*>(&sAlo[r * ASTR + c * 4]) = make_uint4(lx, ly, lz, lw);
        }
#pragma unroll
        for (int p = 0; p < 2; p++) {
            int idx = p * 256 + tid;
            int kr = idx >> 4, c = idx & 15;
            float vv[4] = {bReg[p].x, bReg[p].y, bReg[p].z, bReg[p].w};
#pragma unroll
            for (int jj = 0; jj < 4; jj++) {
                uint32_t hi, lo;
                split_tf32(vv[jj], hi, lo);
                sBhi[(c * 4 + jj) * ASTR + kr] = __uint_as_float(hi);
                sBlo[(c * 4 + jj) * ASTR + kr] = __uint_as_float(lo);
            }
        }
        __syncthreads();

        if (kt + 1 < nkt) {
            const float* Ab = A + (size_t)m0 * K + (kt + 1) * 32;
#pragma unroll
            for (int p = 0; p < 4; p++) {
                int idx = p * 256 + tid;
                int r = idx >> 3, c = idx & 7;
                aReg[p] = *reinterpret_cast<const float4*>(Ab + (size_t)r * K + c * 4);
            }
            const float* Bb = B + (size_t)((kt + 1) * 32) * N + n0;
#pragma unroll
            for (int p = 0; p < 2; p++) {
                int idx = p * 256 + tid;
                int kr = idx >> 4, c = idx & 15;
                bReg[p] = *reinterpret_cast<const float4*>(Bb + (size_t)kr * N + c * 4);
            }
        }

#pragma unroll
        for (int ks = 0; ks < 4; ks++) {
            const int kb = ks * 8;
            uint32_t ahi[2][4], alo[2][4];
#pragma unroll
            for (int i = 0; i < 2; i++) {
                const int rbase = (wm * 32 + i * 16 + g) * ASTR + kb + tq;
                ahi[i][0] = __float_as_uint(sAhi[rbase]);
                ahi[i][1] = __float_as_uint(sAhi[rbase + 8 * ASTR]);
                ahi[i][2] = __float_as_uint(sAhi[rbase + 4]);
                ahi[i][3] = __float_as_uint(sAhi[rbase + 8 * ASTR + 4]);
                alo[i][0] = __float_as_uint(sAlo[rbase]);
                alo[i][1] = __float_as_uint(sAlo[rbase + 8 * ASTR]);
                alo[i][2] = __float_as_uint(sAlo[rbase + 4]);
                alo[i][3] = __float_as_uint(sAlo[rbase + 8 * ASTR + 4]);
            }
            uint32_t bhi[4][2], blo[4][2];
#pragma unroll
            for (int j = 0; j < 4; j++) {
                const int cbase = (wn * 32 + j * 8 + g) * ASTR + kb + tq;
                bhi[j][0] = __float_as_uint(sBhi[cbase]);
                bhi[j][1] = __float_as_uint(sBhi[cbase + 4]);
                blo[j][0] = __float_as_uint(sBlo[cbase]);
                blo[j][1] = __float_as_uint(sBlo[cbase + 4]);
            }
#pragma unroll
            for (int i = 0; i < 2; i++)
#pragma unroll
                for (int j = 0; j < 4; j++) {
                    mma_tf32(acc[i][j], ahi[i][0], ahi[i][1], ahi[i][2], ahi[i][3],
                             blo[j][0], blo[j][1]);
                    mma_tf32(acc[i][j], alo[i][0], alo[i][1], alo[i][2], alo[i][3],
                             bhi[j][0], bhi[j][1]);
                    mma_tf32(acc[i][j], ahi[i][0], ahi[i][1], ahi[i][2], ahi[i][3],
                             bhi[j][0], bhi[j][1]);
                }
        }
    }

#pragma unroll
    for (int i = 0; i < 2; i++) {
        const int row = m0 + wm * 32 + i * 16 + g;
#pragma unroll
        for (int j = 0; j < 4; j++) {
            const int col = n0 + wn * 32 + j * 8 + 2 * tq;
            const float b0 = bias[col], b1 = bias[col + 1];
            float2 o1 = make_float2(acc[i][j][0] + b0, acc[i][j][1] + b1);
            float2 o2 = make_float2(acc[i][j][2] + b0, acc[i][j][3] + b1);
            *reinterpret_cast<float2*>(&C[(size_t)row * N + col]) = o1;
            *reinterpret_cast<float2*>(&C[(size_t)(row + 8) * N + col]) = o2;
        }
    }
}

// ============================ mask handling =================================
__global__ void mask_detect_kernel(const unsigned int* __restrict__ mask) {
    unsigned int w0 = mask[0];
    int esize;
    if (w0 == 0x01010101u) esize = 1;
    else if (w0 == 1u || w0 == 0x3f800000u) esize = 4;
    else if ((w0 & 0xFFu) != 0u || (w0 >> 8) == 0u) esize = 1;
    else esize = 4;
    g_mask_esize = esize;
    g_mask_allones = 1;
}

__global__ void mask_scan_kernel(const void* __restrict__ mask) {
    const int esize = g_mask_esize;
    bool any_zero = false;
    if (esize == 4) {
        const unsigned int* m = (const unsigned int*)mask;
        for (long long i = (long long)blockIdx.x * blockDim.x + threadIdx.x;
             i < MASKN; i += (long long)gridDim.x * blockDim.x)
            if (m[i] == 0u) { any_zero = true; break; }
    } else {
        const unsigned int* m = (const unsigned int*)mask;
        for (long long i = (long long)blockIdx.x * blockDim.x + threadIdx.x;
             i < MASKN / 4; i += (long long)gridDim.x * blockDim.x) {
            unsigned int w = m[i];
            if ((w & 0xFFu) == 0 || (w & 0xFF00u) == 0 ||
                (w & 0xFF0000u) == 0 || (w & 0xFF000000u) == 0) { any_zero = true; break; }
        }
    }
    if (any_zero) g_mask_allones = 0;
}

// ============================ attention via mma.sync ========================
// Block: 256 threads (8 warps), 128 query rows, chunks of 64 keys.
// QK^T: single tf32 term. PV: 3-term tf32 split (split at fragment load).
#define AT_SPAD 68
#define AT_K 0                       // Ktf [64][68] tf32 (uint32)
#define AT_V (64 * AT_SPAD)          // Vs  [64][68] fp32
#define AT_P (2 * 64 * AT_SPAD)      // Ps  [128][68] fp32 (Q staging, then P)
#define AT_FLOATS (AT_P + 128 * AT_SPAD)
#define AT_BYTES  (AT_FLOATS * 4)    // 69632

__global__ void __launch_bounds__(256)
attn_mma_kernel(const float* __restrict__ qkv,
                const void* __restrict__ mask,
                float* __restrict__ att) {
    extern __shared__ float sh[];
    uint32_t* Ktf = reinterpret_cast<uint32_t*>(sh + AT_K);
    float* Vs = sh + AT_V;
    float* Ps = sh + AT_P;

    const int tid = threadIdx.x;
    const int wid = tid >> 5;
    const int lane = tid & 31;
    const int g  = lane >> 2;   // 0..7
    const int tq = lane & 3;    // 0..3
    const int wq = wid * 16;    // warp's query-row offset within tile
    const int q0 = blockIdx.x * 128;
    const int h  = blockIdx.y;
    const int b  = blockIdx.z;

    const int mask_allones = g_mask_allones;
    const int mask_esize   = g_mask_esize;
    const size_t qkv_base = (size_t)b * SEQ * QKVN;
    const int hoff = h * DIM;
    const size_t mask_base = (size_t)b * SEQ * SEQ;

    // ---- stage Q tile [128][64] into Ps region ----
#pragma unroll
    for (int p = 0; p < 8; p++) {
        int idx = p * 256 + tid;
        int r = idx >> 4, c = (idx & 15) * 4;
        float4 v = *reinterpret_cast<const float4*>(
            &qkv[qkv_base + (size_t)(q0 + r) * QKVN + hoff + c]);
        *reinterpret_cast<float4*>(&Ps[r * AT_SPAD + c]) = v;
    }
    __syncthreads();

    // ---- Q fragments (single tf32) ----
    uint32_t qf[8][4];
#pragma unroll
    for (int kb = 0; kb < 8; kb++) {
        const int r0 = (wq + g) * AT_SPAD + kb * 8 + tq;
        const int r1 = (wq + g + 8) * AT_SPAD + kb * 8 + tq;
        qf[kb][0] = to_tf32(Ps[r0]);
        qf[kb][1] = to_tf32(Ps[r1]);
        qf[kb][2] = to_tf32(Ps[r0 + 4]);
        qf[kb][3] = to_tf32(Ps[r1 + 4]);
    }

    float o[8][4];
#pragma unroll
    for (int nt = 0; nt < 8; nt++)
#pragma unroll
        for (int r = 0; r < 4; r++) o[nt][r] = 0.0f;
    float m0r = -1e30f, m1r = -1e30f, l0r = 0.0f, l1r = 0.0f;

    for (int kt = 0; kt < SEQ / 64; kt++) {
        const int k0 = kt * 64;
        __syncthreads();
        // ---- load K (convert tf32) and V (fp32) ----
#pragma unroll
        for (int p = 0; p < 4; p++) {
            int idx = p * 256 + tid;
            int key = idx >> 4, c = (idx & 15) * 4;
            size_t row = qkv_base + (size_t)(k0 + key) * QKVN + hoff;
            float4 kv = *reinterpret_cast<const float4*>(&qkv[row + 768 + c]);
            *reinterpret_cast<uint4*>(&Ktf[key * AT_SPAD + c]) =
                make_uint4(to_tf32(kv.x), to_tf32(kv.y), to_tf32(kv.z), to_tf32(kv.w));
            float4 vv = *reinterpret_cast<const float4*>(&qkv[row + 1536 + c]);
            *reinterpret_cast<float4*>(&Vs[key * AT_SPAD + c]) = vv;
        }
        __syncthreads();

        // ---- S = Q K^T (single tf32 term) ----
        float s[8][4];
#pragma unroll
        for (int nt = 0; nt < 8; nt++)
#pragma unroll
            for (int r = 0; r < 4; r++) s[nt][r] = 0.0f;

#pragma unroll
        for (int kb = 0; kb < 8; kb++) {
#pragma unroll
            for (int nt = 0; nt < 8; nt++) {
                uint32_t b0 = Ktf[(nt * 8 + g) * AT_SPAD + kb * 8 + tq];
                uint32_t b1 = Ktf[(nt * 8 + g) * AT_SPAD + kb * 8 + tq + 4];
                mma_tf32(s[nt], qf[kb][0], qf[kb][1], qf[kb][2], qf[kb][3], b0, b1);
            }
        }

        // ---- scale + mask ----
        if (mask_allones) {
#pragma unroll
            for (int nt = 0; nt < 8; nt++)
#pragma unroll
                for (int r = 0; r < 4; r++) s[nt][r] *= 0.125f;
        } else {
            const int qg0 = q0 + wq + g, qg1 = qg0 + 8;
#pragma unroll
            for (int nt = 0; nt < 8; nt++) {
                int kcol = k0 + nt * 8 + 2 * tq;
                bool mk[4];
                if (mask_esize == 4) {
                    const unsigned int* mm = (const unsigned int*)mask;
                    mk[0] = mm[mask_base + (size_t)qg0 * SEQ + kcol] != 0;
                    mk[1] = mm[mask_base + (size_t)qg0 * SEQ + kcol + 1] != 0;
                    mk[2] = mm[mask_base + (size_t)qg1 * SEQ + kcol] != 0;
                    mk[3] = mm[mask_base + (size_t)qg1 * SEQ + kcol + 1] != 0;
                } else {
                    const unsigned char* mm = (const unsigned char*)mask;
                    mk[0] = mm[mask_base + (size_t)qg0 * SEQ + kcol] != 0;
                    mk[1] = mm[mask_base + (size_t)qg0 * SEQ + kcol + 1] != 0;
                    mk[2] = mm[mask_base + (size_t)qg1 * SEQ + kcol] != 0;
                    mk[3] = mm[mask_base + (size_t)qg1 * SEQ + kcol + 1] != 0;
                }
#pragma unroll
                for (int r = 0; r < 4; r++)
                    s[nt][r] = mk[r] ? s[nt][r] * 0.125f : -1e9f;
            }
        }

        // ---- online softmax (rows g and g+8; reduce over tq group) ----
        float mt0 = -1e30f, mt1 = -1e30f;
#pragma unroll
        for (int nt = 0; nt < 8; nt++) {
            mt0 = fmaxf(mt0, fmaxf(s[nt][0], s[nt][1]));
            mt1 = fmaxf(mt1, fmaxf(s[nt][2], s[nt][3]));
        }
        mt0 = fmaxf(mt0, __shfl_xor_sync(0xffffffff, mt0, 1));
        mt0 = fmaxf(mt0, __shfl_xor_sync(0xffffffff, mt0, 2));
        mt1 = fmaxf(mt1, __shfl_xor_sync(0xffffffff, mt1, 1));
        mt1 = fmaxf(mt1, __shfl_xor_sync(0xffffffff, mt1, 2));

        float mn0 = fmaxf(m0r, mt0), mn1 = fmaxf(m1r, mt1);
        float a0 = __expf(m0r - mn0), a1 = __expf(m1r - mn1);
        m0r = mn0; m1r = mn1;

        float lt0 = 0.0f, lt1 = 0.0f;
#pragma unroll
        for (int nt = 0; nt < 8; nt++) {
            s[nt][0] = __expf(s[nt][0] - mn0);
            s[nt][1] = __expf(s[nt][1] - mn0);
            s[nt][2] = __expf(s[nt][2] - mn1);
            s[nt][3] = __expf(s[nt][3] - mn1);
            lt0 += s[nt][0] + s[nt][1];
            lt1 += s[nt][2] + s[nt][3];
        }
        lt0 += __shfl_xor_sync(0xffffffff, lt0, 1);
        lt0 += __shfl_xor_sync(0xffffffff, lt0, 2);
        lt1 += __shfl_xor_sync(0xffffffff, lt1, 1);
        lt1 += __shfl_xor_sync(0xffffffff, lt1, 2);
        l0r = l0r * a0 + lt0;
        l1r = l1r * a1 + lt1;

#pragma unroll
        for (int nt = 0; nt < 8; nt++) {
            o[nt][0] *= a0; o[nt][1] *= a0;
            o[nt][2] *= a1; o[nt][3] *= a1;
        }

        // ---- store P (fp32) to smem (own rows only) ----
#pragma unroll
        for (int nt = 0; nt < 8; nt++) {
            *reinterpret_cast<float2*>(&Ps[(wq + g) * AT_SPAD + nt * 8 + 2 * tq]) =
                make_float2(s[nt][0], s[nt][1]);
            *reinterpret_cast<float2*>(&Ps[(wq + g + 8) * AT_SPAD + nt * 8 + 2 * tq]) =
                make_float2(s[nt][2], s[nt][3]);
        }
        __syncwarp();

        // ---- O += P @ V (3-term tf32 split at fragment load) ----
#pragma unroll
        for (int kb = 0; kb < 8; kb++) {
            const int pr0 = (wq + g) * AT_SPAD + kb * 8 + tq;
            const int pr1 = (wq + g + 8) * AT_SPAD + kb * 8 + tq;
            uint32_t ph[4], pl[4];
            split_tf32(Ps[pr0], ph[0], pl[0]);
            split_tf32(Ps[pr1], ph[1], pl[1]);
            split_tf32(Ps[pr0 + 4], ph[2], pl[2]);
            split_tf32(Ps[pr1 + 4], ph[3], pl[3]);
#pragma unroll
            for (int nt = 0; nt < 8; nt++) {
                uint32_t vh0, vl0, vh1, vl1;
                split_tf32(Vs[(kb * 8 + tq) * AT_SPAD + nt * 8 + g], vh0, vl0);
                split_tf32(Vs[(kb * 8 + tq + 4) * AT_SPAD + nt * 8 + g], vh1, vl1);
                mma_tf32(o[nt], ph[0], ph[1], ph[2], ph[3], vh0, vh1);
                mma_tf32(o[nt], ph[0], ph[1], ph[2], ph[3], vl0, vl1);
                mma_tf32(o[nt], pl[0], pl[1], pl[2], pl[3], vh0, vh1);
            }
        }
    }

    // ---- write output ----
    const float inv0 = 1.0f / l0r, inv1 = 1.0f / l1r;
    const size_t row0 = (size_t)b * SEQ + q0 + wq + g;
    const size_t row1 = row0 + 8;
#pragma unroll
    for (int nt = 0; nt < 8; nt++) {
        const int col = hoff + nt * 8 + 2 * tq;
        *reinterpret_cast<float2*>(&g_att[row0 * (HEADS * DIM) + col]) =
            make_float2(o[nt][0] * inv0, o[nt][1] * inv0);
        *reinterpret_cast<float2*>(&g_att[row1 * (HEADS * DIM) + col]) =
            make_float2(o[nt][2] * inv1, o[nt][3] * inv1);
    }
}

// ============================================================================
extern "C" void kernel_launch(void* const* d_in, const int* in_sizes, int n_in,
                              void* d_out, int out_size) {
    const float* x      = (const float*)d_in[0];
    const void*  mask   = d_in[1];
    const float* W_pre  = (const float*)d_in[2];
    const float* b_pre  = (const float*)d_in[3];
    const float* W_proj = (const float*)d_in[4];
    const float* b_proj = (const float*)d_in[5];
    float* out = (float*)d_out;

    float* qkv;
    float* att;
    cudaGetSymbolAddress((void**)&qkv, g_qkv);
    cudaGetSymbolAddress((void**)&att, g_att);

    mask_detect_kernel<<<1, 1>>>((const unsigned int*)mask);
    mask_scan_kernel<<<256, 256>>>(mask);

    cudaFuncSetAttribute(gemm_tf32_kernel,
                         cudaFuncAttributeMaxDynamicSharedMemorySize, GSM_BYTES);
    cudaFuncSetAttribute(attn_mma_kernel,
                         cudaFuncAttributeMaxDynamicSharedMemorySize, AT_BYTES);

    // 1) QKV GEMM
    {
        dim3 grid(QKVN / 64, ROWS / 128);
        gemm_tf32_kernel<<<grid, 256, GSM_BYTES>>>(x, W_pre, b_pre, qkv,
                                                   ROWS, QKVN, EMB);
    }
    // 2) Attention (tensor-core)
    {
        dim3 grid(SEQ / 128, HEADS, BATCH);
        attn_mma_kernel<<<grid, 256, AT_BYTES>>>(qkv, mask, att);
    }
    // 3) Projection GEMM
    {
        dim3 grid(EMB / 64, ROWS / 128);
        gemm_tf32_kernel<<<grid, 256, GSM_BYTES>>>(att, W_proj, b_proj, out,
                                                   ROWS, EMB, EMB);
    }
}

// round 7
// speedup vs baseline: 1.5422x; 1.0812x over previous
#include <cuda_runtime.h>
#include <math.h>
#include <stdint.h>

#define HEADS 12
#define DIM   64
#define BATCH 2
#define SEQ   2048
#define EMB   768
#define QKVN  (3 * HEADS * DIM)   // 2304
#define ROWS  (BATCH * SEQ)       // 4096
#define MASKN (BATCH * SEQ * SEQ) // 8388608

// ----- device scratch -----
__device__ float g_qkv[ROWS * QKVN];
__device__ float g_xhi[ROWS * EMB];
__device__ float g_xlo[ROWS * EMB];
__device__ float g_wpre_hi[EMB * QKVN];
__device__ float g_wpre_lo[EMB * QKVN];
__device__ float g_wproj_hi[EMB * EMB];
__device__ float g_wproj_lo[EMB * EMB];
__device__ float g_atthi[ROWS * EMB];
__device__ float g_attlo[ROWS * EMB];
__device__ int   g_mask_esize;
__device__ int   g_mask_allones;

// ============================ helpers =======================================
__device__ __forceinline__ uint32_t to_tf32(float x) {
    uint32_t r;
    asm("cvt.rna.tf32.f32 %0, %1;" : "=r"(r) : "f"(x));
    return r;
}
__device__ __forceinline__ void split_tf32(float x, uint32_t& hi, uint32_t& lo) {
    asm("cvt.rna.tf32.f32 %0, %1;" : "=r"(hi) : "f"(x));
    float r = x - __uint_as_float(hi);
    asm("cvt.rna.tf32.f32 %0, %1;" : "=r"(lo) : "f"(r));
}
__device__ __forceinline__ void mma_tf32(float c[4],
                                         uint32_t a0, uint32_t a1, uint32_t a2, uint32_t a3,
                                         uint32_t b0, uint32_t b1) {
    asm volatile(
        "mma.sync.aligned.m16n8k8.row.col.f32.tf32.tf32.f32 "
        "{%0,%1,%2,%3}, {%4,%5,%6,%7}, {%8,%9}, {%0,%1,%2,%3};"
        : "+f"(c[0]), "+f"(c[1]), "+f"(c[2]), "+f"(c[3])
        : "r"(a0), "r"(a1), "r"(a2), "r"(a3), "r"(b0), "r"(b1));
}
#define CP16(dst, src) \
    asm volatile("cp.async.ca.shared.global [%0], [%1], 16;" :: "r"(dst), "l"(src) : "memory")
#define CP_COMMIT() asm volatile("cp.async.commit_group;" ::: "memory")
#define CP_WAIT1() asm volatile("cp.async.wait_group 1;" ::: "memory")
#define CP_WAIT0() asm volatile("cp.async.wait_group 0;" ::: "memory")

// ============================ split prepass =================================
__global__ void split_kernel(const float4* __restrict__ in,
                             uint4* __restrict__ hi, uint4* __restrict__ lo, int n4) {
    for (int i = blockIdx.x * blockDim.x + threadIdx.x; i < n4;
         i += gridDim.x * blockDim.x) {
        float4 v = in[i];
        uint4 h, l;
        split_tf32(v.x, h.x, l.x);
        split_tf32(v.y, h.y, l.y);
        split_tf32(v.z, h.z, l.z);
        split_tf32(v.w, h.w, l.w);
        hi[i] = h;
        lo[i] = l;
    }
}

// ============================ GEMM (pre-split, cp.async pipelined) ==========
// C[M,N] = A @ B + bias with A=Ahi+Alo, B=Bhi+Blo (3-term tf32).
// CTA 128x64, BK=32, 256 threads, double-buffered smem.
// Byte offsets (per stage s in {0,1}):
//   sAhi: s*18432            (128x36 f32)
//   sAlo: 36864 + s*18432
//   sBhi: 73728 + s*9216     (32x72 f32, [k][n])
//   sBlo: 92160 + s*9216
#define G2_BYTES 110592

__global__ void __launch_bounds__(256)
gemm_split_kernel(const float* __restrict__ Ahi, const float* __restrict__ Alo,
                  const float* __restrict__ Bhi, const float* __restrict__ Blo,
                  const float* __restrict__ bias, float* __restrict__ C,
                  int M, int N, int K) {
    extern __shared__ char smraw[];
    float* fsm = reinterpret_cast<float*>(smraw);
    const uint32_t sb = (uint32_t)__cvta_generic_to_shared(smraw);

    const int tid = threadIdx.x;
    const int wid = tid >> 5;
    const int lane = tid & 31;
    const int g  = lane >> 2;
    const int tq = lane & 3;
    const int wm = wid >> 1;
    const int wn = wid & 1;
    const int m0 = blockIdx.y * 128;
    const int n0 = blockIdx.x * 64;
    const int nkt = K / 32;

    float acc[2][4][4];
#pragma unroll
    for (int i = 0; i < 2; i++)
#pragma unroll
        for (int j = 0; j < 4; j++)
#pragma unroll
            for (int r = 0; r < 4; r++) acc[i][j][r] = 0.0f;

    auto issue_tile = [&](int s, int kt) {
        // A tiles: 128x32 hi + lo, 1024 chunks each over 4 iterations
#pragma unroll
        for (int p = 0; p < 4; p++) {
            int idx = p * 256 + tid;
            int r = idx >> 3, ch = idx & 7;
            const float* srcH = Ahi + (size_t)(m0 + r) * K + kt * 32 + ch * 4;
            const float* srcL = Alo + (size_t)(m0 + r) * K + kt * 32 + ch * 4;
            uint32_t dH = sb + s * 18432 + (r * 36 + ch * 4) * 4;
            uint32_t dL = sb + 36864 + s * 18432 + (r * 36 + ch * 4) * 4;
            CP16(dH, srcH);
            CP16(dL, srcL);
        }
        // B tiles: 32x64 hi + lo = 512 float4 chunks each -> 1024 total, 4 iters
#pragma unroll
        for (int p = 0; p < 4; p++) {
            int idx = p * 256 + tid;
            int mat = idx >> 9;          // 0 = hi, 1 = lo
            int within = idx & 511;
            int r = within >> 4;         // 0..31
            int ch = within & 15;        // 0..15 -> columns ch*4..ch*4+3
            const float* src = (mat == 0 ? Bhi : Blo) +
                               (size_t)(kt * 32 + r) * N + n0 + ch * 4;
            uint32_t dst = sb + (mat == 0 ? 73728u : 92160u) + s * 9216 +
                           (r * 72 + ch * 4) * 4;
            CP16(dst, src);
        }
        CP_COMMIT();
    };

    issue_tile(0, 0);

    for (int kt = 0; kt < nkt; kt++) {
        const int s = kt & 1;
        if (kt + 1 < nkt) {
            issue_tile(1 - s, kt + 1);
            CP_WAIT1();
        } else {
            CP_WAIT0();
        }
        __syncthreads();

        const float* sAhi = fsm + s * 4608;
        const float* sAlo = fsm + 9216 + s * 4608;
        const float* sBhi = fsm + 18432 + s * 2304;
        const float* sBlo = fsm + 23040 + s * 2304;

#pragma unroll
        for (int ks = 0; ks < 4; ks++) {
            const int kb = ks * 8;
            uint32_t ahi[2][4], alo[2][4];
#pragma unroll
            for (int i = 0; i < 2; i++) {
                const int rbase = (wm * 32 + i * 16 + g) * 36 + kb + tq;
                ahi[i][0] = __float_as_uint(sAhi[rbase]);
                ahi[i][1] = __float_as_uint(sAhi[rbase + 8 * 36]);
                ahi[i][2] = __float_as_uint(sAhi[rbase + 4]);
                ahi[i][3] = __float_as_uint(sAhi[rbase + 8 * 36 + 4]);
                alo[i][0] = __float_as_uint(sAlo[rbase]);
                alo[i][1] = __float_as_uint(sAlo[rbase + 8 * 36]);
                alo[i][2] = __float_as_uint(sAlo[rbase + 4]);
                alo[i][3] = __float_as_uint(sAlo[rbase + 8 * 36 + 4]);
            }
            uint32_t bhi[4][2], blo[4][2];
#pragma unroll
            for (int j = 0; j < 4; j++) {
                const int col = wn * 32 + j * 8 + g;
                bhi[j][0] = __float_as_uint(sBhi[(kb + tq) * 72 + col]);
                bhi[j][1] = __float_as_uint(sBhi[(kb + tq + 4) * 72 + col]);
                blo[j][0] = __float_as_uint(sBlo[(kb + tq) * 72 + col]);
                blo[j][1] = __float_as_uint(sBlo[(kb + tq + 4) * 72 + col]);
            }
#pragma unroll
            for (int i = 0; i < 2; i++)
#pragma unroll
                for (int j = 0; j < 4; j++) {
                    mma_tf32(acc[i][j], ahi[i][0], ahi[i][1], ahi[i][2], ahi[i][3],
                             blo[j][0], blo[j][1]);
                    mma_tf32(acc[i][j], alo[i][0], alo[i][1], alo[i][2], alo[i][3],
                             bhi[j][0], bhi[j][1]);
                    mma_tf32(acc[i][j], ahi[i][0], ahi[i][1], ahi[i][2], ahi[i][3],
                             bhi[j][0], bhi[j][1]);
                }
        }
        __syncthreads();
    }

#pragma unroll
    for (int i = 0; i < 2; i++) {
        const int row = m0 + wm * 32 + i * 16 + g;
#pragma unroll
        for (int j = 0; j < 4; j++) {
            const int col = n0 + wn * 32 + j * 8 + 2 * tq;
            const float b0 = bias[col], b1 = bias[col + 1];
            float2 o1 = make_float2(acc[i][j][0] + b0, acc[i][j][1] + b1);
            float2 o2 = make_float2(acc[i][j][2] + b0, acc[i][j][3] + b1);
            *reinterpret_cast<float2*>(&C[(size_t)row * N + col]) = o1;
            *reinterpret_cast<float2*>(&C[(size_t)(row + 8) * N + col]) = o2;
        }
    }
}

// ============================ mask handling =================================
__global__ void mask_detect_kernel(const unsigned int* __restrict__ mask) {
    unsigned int w0 = mask[0];
    int esize;
    if (w0 == 0x01010101u) esize = 1;
    else if (w0 == 1u || w0 == 0x3f800000u) esize = 4;
    else if ((w0 & 0xFFu) != 0u || (w0 >> 8) == 0u) esize = 1;
    else esize = 4;
    g_mask_esize = esize;
    g_mask_allones = 1;
}

__global__ void mask_scan_kernel(const void* __restrict__ mask) {
    const int esize = g_mask_esize;
    bool any_zero = false;
    if (esize == 4) {
        const unsigned int* m = (const unsigned int*)mask;
        for (long long i = (long long)blockIdx.x * blockDim.x + threadIdx.x;
             i < MASKN; i += (long long)gridDim.x * blockDim.x)
            if (m[i] == 0u) { any_zero = true; break; }
    } else {
        const unsigned int* m = (const unsigned int*)mask;
        for (long long i = (long long)blockIdx.x * blockDim.x + threadIdx.x;
             i < MASKN / 4; i += (long long)gridDim.x * blockDim.x) {
            unsigned int w = m[i];
            if ((w & 0xFFu) == 0 || (w & 0xFF00u) == 0 ||
                (w & 0xFF0000u) == 0 || (w & 0xFF000000u) == 0) { any_zero = true; break; }
        }
    }
    if (any_zero) g_mask_allones = 0;
}

// ============================ attention via mma.sync ========================
// 256 threads (8 warps), 128 query rows, chunks of 64 keys.
// QK^T single tf32 (scale folded into Q). PV 3-term with PRE-SPLIT V and P.
// smem (float idx): Ktf [64][68] @0 ; Vhi [64][72] @4352 ; Vlo @8960 ;
//                   Phi [128][68] @13568 ; Plo @22272 ; total 30976 fl
#define AT_K    0
#define AT_VHI  4352
#define AT_VLO  8960
#define AT_PHI  13568
#define AT_PLO  22272
#define AT_BYTES (30976 * 4)

__global__ void __launch_bounds__(256)
attn_mma_kernel(const float* __restrict__ qkv,
                const void* __restrict__ mask,
                float* __restrict__ atthi, float* __restrict__ attlo) {
    extern __shared__ float sh[];
    uint32_t* Ktf = reinterpret_cast<uint32_t*>(sh + AT_K);
    uint32_t* Vhi = reinterpret_cast<uint32_t*>(sh + AT_VHI);
    uint32_t* Vlo = reinterpret_cast<uint32_t*>(sh + AT_VLO);
    uint32_t* Phi = reinterpret_cast<uint32_t*>(sh + AT_PHI);
    uint32_t* Plo = reinterpret_cast<uint32_t*>(sh + AT_PLO);
    float* Qstage = sh + AT_PHI;   // reuse Phi region for Q staging

    const int tid = threadIdx.x;
    const int wid = tid >> 5;
    const int lane = tid & 31;
    const int g  = lane >> 2;
    const int tq = lane & 3;
    const int wq = wid * 16;
    const int q0 = blockIdx.x * 128;
    const int h  = blockIdx.y;
    const int b  = blockIdx.z;

    const int mask_allones = g_mask_allones;
    const int mask_esize   = g_mask_esize;
    const size_t qkv_base = (size_t)b * SEQ * QKVN;
    const int hoff = h * DIM;
    const size_t mask_base = (size_t)b * SEQ * SEQ;

    // ---- stage Q tile [128][64] ----
#pragma unroll
    for (int p = 0; p < 8; p++) {
        int idx = p * 256 + tid;
        int r = idx >> 4, c = (idx & 15) * 4;
        float4 v = *reinterpret_cast<const float4*>(
            &qkv[qkv_base + (size_t)(q0 + r) * QKVN + hoff + c]);
        *reinterpret_cast<float4*>(&Qstage[r * 68 + c]) = v;
    }
    __syncthreads();

    // ---- Q fragments (single tf32, scale 1/8 folded in — exact pow2) ----
    uint32_t qf[8][4];
#pragma unroll
    for (int kb = 0; kb < 8; kb++) {
        const int r0 = (wq + g) * 68 + kb * 8 + tq;
        const int r1 = (wq + g + 8) * 68 + kb * 8 + tq;
        qf[kb][0] = to_tf32(0.125f * Qstage[r0]);
        qf[kb][1] = to_tf32(0.125f * Qstage[r1]);
        qf[kb][2] = to_tf32(0.125f * Qstage[r0 + 4]);
        qf[kb][3] = to_tf32(0.125f * Qstage[r1 + 4]);
    }
    __syncthreads();

    float o[8][4];
#pragma unroll
    for (int nt = 0; nt < 8; nt++)
#pragma unroll
        for (int r = 0; r < 4; r++) o[nt][r] = 0.0f;
    float m0r = -1e30f, m1r = -1e30f, l0r = 0.0f, l1r = 0.0f;

    for (int kt = 0; kt < SEQ / 64; kt++) {
        const int k0 = kt * 64;
        __syncthreads();
        // ---- load K (tf32) and V (pre-split hi/lo) ----
#pragma unroll
        for (int p = 0; p < 4; p++) {
            int idx = p * 256 + tid;
            int key = idx >> 4, c = (idx & 15) * 4;
            size_t row = qkv_base + (size_t)(k0 + key) * QKVN + hoff;
            float4 kv = *reinterpret_cast<const float4*>(&qkv[row + 768 + c]);
            *reinterpret_cast<uint4*>(&Ktf[key * 68 + c]) =
                make_uint4(to_tf32(kv.x), to_tf32(kv.y), to_tf32(kv.z), to_tf32(kv.w));
            float4 vv = *reinterpret_cast<const float4*>(&qkv[row + 1536 + c]);
            uint4 vh, vl;
            split_tf32(vv.x, vh.x, vl.x); split_tf32(vv.y, vh.y, vl.y);
            split_tf32(vv.z, vh.z, vl.z); split_tf32(vv.w, vh.w, vl.w);
            *reinterpret_cast<uint4*>(&Vhi[key * 72 + c]) = vh;
            *reinterpret_cast<uint4*>(&Vlo[key * 72 + c]) = vl;
        }
        __syncthreads();

        // ---- S = (Q/8) K^T ----
        float s[8][4];
#pragma unroll
        for (int nt = 0; nt < 8; nt++)
#pragma unroll
            for (int r = 0; r < 4; r++) s[nt][r] = 0.0f;
#pragma unroll
        for (int kb = 0; kb < 8; kb++) {
#pragma unroll
            for (int nt = 0; nt < 8; nt++) {
                uint32_t b0 = Ktf[(nt * 8 + g) * 68 + kb * 8 + tq];
                uint32_t b1 = Ktf[(nt * 8 + g) * 68 + kb * 8 + tq + 4];
                mma_tf32(s[nt], qf[kb][0], qf[kb][1], qf[kb][2], qf[kb][3], b0, b1);
            }
        }

        // ---- mask (scores already scaled) ----
        if (!mask_allones) {
            const int qg0 = q0 + wq + g, qg1 = qg0 + 8;
#pragma unroll
            for (int nt = 0; nt < 8; nt++) {
                int kcol = k0 + nt * 8 + 2 * tq;
                bool mk[4];
                if (mask_esize == 4) {
                    const unsigned int* mm = (const unsigned int*)mask;
                    mk[0] = mm[mask_base + (size_t)qg0 * SEQ + kcol] != 0;
                    mk[1] = mm[mask_base + (size_t)qg0 * SEQ + kcol + 1] != 0;
                    mk[2] = mm[mask_base + (size_t)qg1 * SEQ + kcol] != 0;
                    mk[3] = mm[mask_base + (size_t)qg1 * SEQ + kcol + 1] != 0;
                } else {
                    const unsigned char* mm = (const unsigned char*)mask;
                    mk[0] = mm[mask_base + (size_t)qg0 * SEQ + kcol] != 0;
                    mk[1] = mm[mask_base + (size_t)qg0 * SEQ + kcol + 1] != 0;
                    mk[2] = mm[mask_base + (size_t)qg1 * SEQ + kcol] != 0;
                    mk[3] = mm[mask_base + (size_t)qg1 * SEQ + kcol + 1] != 0;
                }
#pragma unroll
                for (int r = 0; r < 4; r++)
                    if (!mk[r]) s[nt][r] = -1e9f;
            }
        }

        // ---- online softmax ----
        float mt0 = -1e30f, mt1 = -1e30f;
#pragma unroll
        for (int nt = 0; nt < 8; nt++) {
            mt0 = fmaxf(mt0, fmaxf(s[nt][0], s[nt][1]));
            mt1 = fmaxf(mt1, fmaxf(s[nt][2], s[nt][3]));
        }
        mt0 = fmaxf(mt0, __shfl_xor_sync(0xffffffff, mt0, 1));
        mt0 = fmaxf(mt0, __shfl_xor_sync(0xffffffff, mt0, 2));
        mt1 = fmaxf(mt1, __shfl_xor_sync(0xffffffff, mt1, 1));
        mt1 = fmaxf(mt1, __shfl_xor_sync(0xffffffff, mt1, 2));

        float mn0 = fmaxf(m0r, mt0), mn1 = fmaxf(m1r, mt1);
        float a0 = __expf(m0r - mn0), a1 = __expf(m1r - mn1);
        m0r = mn0; m1r = mn1;

        float lt0 = 0.0f, lt1 = 0.0f;
#pragma unroll
        for (int nt = 0; nt < 8; nt++) {
            s[nt][0] = __expf(s[nt][0] - mn0);
            s[nt][1] = __expf(s[nt][1] - mn0);
            s[nt][2] = __expf(s[nt][2] - mn1);
            s[nt][3] = __expf(s[nt][3] - mn1);
            lt0 += s[nt][0] + s[nt][1];
            lt1 += s[nt][2] + s[nt][3];
        }
        lt0 += __shfl_xor_sync(0xffffffff, lt0, 1);
        lt0 += __shfl_xor_sync(0xffffffff, lt0, 2);
        lt1 += __shfl_xor_sync(0xffffffff, lt1, 1);
        lt1 += __shfl_xor_sync(0xffffffff, lt1, 2);
        l0r = l0r * a0 + lt0;
        l1r = l1r * a1 + lt1;

#pragma unroll
        for (int nt = 0; nt < 8; nt++) {
            o[nt][0] *= a0; o[nt][1] *= a0;
            o[nt][2] *= a1; o[nt][3] *= a1;
        }

        // ---- split P and store hi/lo to smem (own rows; warp-local) ----
#pragma unroll
        for (int nt = 0; nt < 8; nt++) {
            uint32_t h0, l0, h1, l1, h2, l2, h3, l3;
            split_tf32(s[nt][0], h0, l0);
            split_tf32(s[nt][1], h1, l1);
            split_tf32(s[nt][2], h2, l2);
            split_tf32(s[nt][3], h3, l3);
            const int p0 = (wq + g) * 68 + nt * 8 + 2 * tq;
            const int p1 = (wq + g + 8) * 68 + nt * 8 + 2 * tq;
            *reinterpret_cast<uint2*>(&Phi[p0]) = make_uint2(h0, h1);
            *reinterpret_cast<uint2*>(&Phi[p1]) = make_uint2(h2, h3);
            *reinterpret_cast<uint2*>(&Plo[p0]) = make_uint2(l0, l1);
            *reinterpret_cast<uint2*>(&Plo[p1]) = make_uint2(l2, l3);
        }
        __syncwarp();

        // ---- O += P @ V (3-term, all operands pre-split) ----
#pragma unroll
        for (int kb = 0; kb < 8; kb++) {
            const int pr0 = (wq + g) * 68 + kb * 8 + tq;
            const int pr1 = (wq + g + 8) * 68 + kb * 8 + tq;
            uint32_t ph[4], pl[4];
            ph[0] = Phi[pr0]; ph[1] = Phi[pr1];
            ph[2] = Phi[pr0 + 4]; ph[3] = Phi[pr1 + 4];
            pl[0] = Plo[pr0]; pl[1] = Plo[pr1];
            pl[2] = Plo[pr0 + 4]; pl[3] = Plo[pr1 + 4];
            const int vr0 = (kb * 8 + tq) * 72;
            const int vr1 = (kb * 8 + tq + 4) * 72;
#pragma unroll
            for (int nt = 0; nt < 8; nt++) {
                const int d = nt * 8 + g;
                uint32_t vh0 = Vhi[vr0 + d], vh1 = Vhi[vr1 + d];
                uint32_t vl0 = Vlo[vr0 + d], vl1 = Vlo[vr1 + d];
                mma_tf32(o[nt], ph[0], ph[1], ph[2], ph[3], vh0, vh1);
                mma_tf32(o[nt], ph[0], ph[1], ph[2], ph[3], vl0, vl1);
                mma_tf32(o[nt], pl[0], pl[1], pl[2], pl[3], vh0, vh1);
            }
        }
    }

    // ---- write output pre-split (consumed by proj GEMM) ----
    const float inv0 = 1.0f / l0r, inv1 = 1.0f / l1r;
    const size_t row0 = (size_t)b * SEQ + q0 + wq + g;
    const size_t row1 = row0 + 8;
    uint32_t* aHi = reinterpret_cast<uint32_t*>(atthi);
    uint32_t* aLo = reinterpret_cast<uint32_t*>(attlo);
#pragma unroll
    for (int nt = 0; nt < 8; nt++) {
        const int col = hoff + nt * 8 + 2 * tq;
        uint32_t h0, l0, h1, l1, h2, l2, h3, l3;
        split_tf32(o[nt][0] * inv0, h0, l0);
        split_tf32(o[nt][1] * inv0, h1, l1);
        split_tf32(o[nt][2] * inv1, h2, l2);
        split_tf32(o[nt][3] * inv1, h3, l3);
        *reinterpret_cast<uint2*>(&aHi[row0 * EMB + col]) = make_uint2(h0, h1);
        *reinterpret_cast<uint2*>(&aLo[row0 * EMB + col]) = make_uint2(l0, l1);
        *reinterpret_cast<uint2*>(&aHi[row1 * EMB + col]) = make_uint2(h2, h3);
        *reinterpret_cast<uint2*>(&aLo[row1 * EMB + col]) = make_uint2(l2, l3);
    }
}

// ============================================================================
extern "C" void kernel_launch(void* const* d_in, const int* in_sizes, int n_in,
                              void* d_out, int out_size) {
    const float* x      = (const float*)d_in[0];
    const void*  mask   = d_in[1];
    const float* W_pre  = (const float*)d_in[2];
    const float* b_pre  = (const float*)d_in[3];
    const float* W_proj = (const float*)d_in[4];
    const float* b_proj = (const float*)d_in[5];
    float* out = (float*)d_out;

    float *qkv, *xhi, *xlo, *wph, *wpl, *wjh, *wjl, *ahi, *alo;
    cudaGetSymbolAddress((void**)&qkv, g_qkv);
    cudaGetSymbolAddress((void**)&xhi, g_xhi);
    cudaGetSymbolAddress((void**)&xlo, g_xlo);
    cudaGetSymbolAddress((void**)&wph, g_wpre_hi);
    cudaGetSymbolAddress((void**)&wpl, g_wpre_lo);
    cudaGetSymbolAddress((void**)&wjh, g_wproj_hi);
    cudaGetSymbolAddress((void**)&wjl, g_wproj_lo);
    cudaGetSymbolAddress((void**)&ahi, g_atthi);
    cudaGetSymbolAddress((void**)&alo, g_attlo);

    mask_detect_kernel<<<1, 1>>>((const unsigned int*)mask);
    mask_scan_kernel<<<256, 256>>>(mask);

    // input splits
    split_kernel<<<1024, 256>>>((const float4*)x, (uint4*)xhi, (uint4*)xlo,
                                ROWS * EMB / 4);
    split_kernel<<<1024, 256>>>((const float4*)W_pre, (uint4*)wph, (uint4*)wpl,
                                EMB * QKVN / 4);
    split_kernel<<<512, 256>>>((const float4*)W_proj, (uint4*)wjh, (uint4*)wjl,
                               EMB * EMB / 4);

    cudaFuncSetAttribute(gemm_split_kernel,
                         cudaFuncAttributeMaxDynamicSharedMemorySize, G2_BYTES);
    cudaFuncSetAttribute(attn_mma_kernel,
                         cudaFuncAttributeMaxDynamicSharedMemorySize, AT_BYTES);

    // 1) QKV GEMM
    {
        dim3 grid(QKVN / 64, ROWS / 128);
        gemm_split_kernel<<<grid, 256, G2_BYTES>>>(xhi, xlo, wph, wpl,
                                                   b_pre, qkv, ROWS, QKVN, EMB);
    }
    // 2) Attention (writes att pre-split)
    {
        dim3 grid(SEQ / 128, HEADS, BATCH);
        attn_mma_kernel<<<grid, 256, AT_BYTES>>>(qkv, mask, ahi, alo);
    }
    // 3) Projection GEMM
    {
        dim3 grid(EMB / 64, ROWS / 128);
        gemm_split_kernel<<<grid, 256, G2_BYTES>>>(ahi, alo, wjh, wjl,
                                                   b_proj, out, ROWS, EMB, EMB);
    }
}

// round 8
// speedup vs baseline: 1.6799x; 1.0893x over previous
#include <cuda_runtime.h>
#include <math.h>
#include <stdint.h>

#define HEADS 12
#define DIM   64
#define BATCH 2
#define SEQ   2048
#define EMB   768
#define QKVN  (3 * HEADS * DIM)   // 2304
#define ROWS  (BATCH * SEQ)       // 4096
#define MASKN (BATCH * SEQ * SEQ) // 8388608

// ----- device scratch -----
__device__ uint32_t g_qtf[ROWS * EMB];   // Q pre-scaled (1/8), tf32
__device__ uint32_t g_ktf[ROWS * EMB];   // K tf32
__device__ uint32_t g_vhi[ROWS * EMB];   // V split hi
__device__ uint32_t g_vlo[ROWS * EMB];   // V split lo
__device__ float g_xhi[ROWS * EMB];
__device__ float g_xlo[ROWS * EMB];
__device__ float g_wpre_hi[EMB * QKVN];
__device__ float g_wpre_lo[EMB * QKVN];
__device__ float g_wproj_hi[EMB * EMB];
__device__ float g_wproj_lo[EMB * EMB];
__device__ float g_atthi[ROWS * EMB];
__device__ float g_attlo[ROWS * EMB];
__device__ int   g_mask_esize;
__device__ int   g_mask_allones;

// ============================ helpers =======================================
__device__ __forceinline__ uint32_t to_tf32(float x) {
    uint32_t r;
    asm("cvt.rna.tf32.f32 %0, %1;" : "=r"(r) : "f"(x));
    return r;
}
__device__ __forceinline__ void split_tf32(float x, uint32_t& hi, uint32_t& lo) {
    asm("cvt.rna.tf32.f32 %0, %1;" : "=r"(hi) : "f"(x));
    float r = x - __uint_as_float(hi);
    asm("cvt.rna.tf32.f32 %0, %1;" : "=r"(lo) : "f"(r));
}
__device__ __forceinline__ void mma_tf32(float c[4],
                                         uint32_t a0, uint32_t a1, uint32_t a2, uint32_t a3,
                                         uint32_t b0, uint32_t b1) {
    asm volatile(
        "mma.sync.aligned.m16n8k8.row.col.f32.tf32.tf32.f32 "
        "{%0,%1,%2,%3}, {%4,%5,%6,%7}, {%8,%9}, {%0,%1,%2,%3};"
        : "+f"(c[0]), "+f"(c[1]), "+f"(c[2]), "+f"(c[3])
        : "r"(a0), "r"(a1), "r"(a2), "r"(a3), "r"(b0), "r"(b1));
}
#define CP16(dst, src) \
    asm volatile("cp.async.ca.shared.global [%0], [%1], 16;" :: "r"(dst), "l"(src) : "memory")
#define CP_COMMIT() asm volatile("cp.async.commit_group;" ::: "memory")
#define CP_WAIT1() asm volatile("cp.async.wait_group 1;" ::: "memory")
#define CP_WAIT0() asm volatile("cp.async.wait_group 0;" ::: "memory")

// ============================ split prepass =================================
__global__ void split_kernel(const float4* __restrict__ in,
                             uint4* __restrict__ hi, uint4* __restrict__ lo, int n4) {
    for (int i = blockIdx.x * blockDim.x + threadIdx.x; i < n4;
         i += gridDim.x * blockDim.x) {
        float4 v = in[i];
        uint4 h, l;
        split_tf32(v.x, h.x, l.x);
        split_tf32(v.y, h.y, l.y);
        split_tf32(v.z, h.z, l.z);
        split_tf32(v.w, h.w, l.w);
        hi[i] = h;
        lo[i] = l;
    }
}

// ============================ GEMM (pre-split, cp.async pipelined) ==========
// MODE 0: C = acc + bias (fp32). MODE 1: QKV epilogue -> qtf/ktf/vhi/vlo.
#define G2_BYTES 110592

template <int MODE>
__global__ void __launch_bounds__(256)
gemm_split_kernel(const float* __restrict__ Ahi, const float* __restrict__ Alo,
                  const float* __restrict__ Bhi, const float* __restrict__ Blo,
                  const float* __restrict__ bias, float* __restrict__ C,
                  uint32_t* __restrict__ qtf, uint32_t* __restrict__ ktf,
                  uint32_t* __restrict__ vhi, uint32_t* __restrict__ vlo,
                  int M, int N, int K) {
    extern __shared__ char smraw[];
    float* fsm = reinterpret_cast<float*>(smraw);
    const uint32_t sb = (uint32_t)__cvta_generic_to_shared(smraw);

    const int tid = threadIdx.x;
    const int wid = tid >> 5;
    const int lane = tid & 31;
    const int g  = lane >> 2;
    const int tq = lane & 3;
    const int wm = wid >> 1;
    const int wn = wid & 1;
    const int m0 = blockIdx.y * 128;
    const int n0 = blockIdx.x * 64;
    const int nkt = K / 32;

    float acc[2][4][4];
#pragma unroll
    for (int i = 0; i < 2; i++)
#pragma unroll
        for (int j = 0; j < 4; j++)
#pragma unroll
            for (int r = 0; r < 4; r++) acc[i][j][r] = 0.0f;

    auto issue_tile = [&](int s, int kt) {
#pragma unroll
        for (int p = 0; p < 4; p++) {
            int idx = p * 256 + tid;
            int r = idx >> 3, ch = idx & 7;
            const float* srcH = Ahi + (size_t)(m0 + r) * K + kt * 32 + ch * 4;
            const float* srcL = Alo + (size_t)(m0 + r) * K + kt * 32 + ch * 4;
            uint32_t dH = sb + s * 18432 + (r * 36 + ch * 4) * 4;
            uint32_t dL = sb + 36864 + s * 18432 + (r * 36 + ch * 4) * 4;
            CP16(dH, srcH);
            CP16(dL, srcL);
        }
#pragma unroll
        for (int p = 0; p < 4; p++) {
            int idx = p * 256 + tid;
            int mat = idx >> 9;
            int within = idx & 511;
            int r = within >> 4;
            int ch = within & 15;
            const float* src = (mat == 0 ? Bhi : Blo) +
                               (size_t)(kt * 32 + r) * N + n0 + ch * 4;
            uint32_t dst = sb + (mat == 0 ? 73728u : 92160u) + s * 9216 +
                           (r * 72 + ch * 4) * 4;
            CP16(dst, src);
        }
        CP_COMMIT();
    };

    issue_tile(0, 0);

    for (int kt = 0; kt < nkt; kt++) {
        const int s = kt & 1;
        if (kt + 1 < nkt) {
            issue_tile(1 - s, kt + 1);
            CP_WAIT1();
        } else {
            CP_WAIT0();
        }
        __syncthreads();

        const float* sAhi = fsm + s * 4608;
        const float* sAlo = fsm + 9216 + s * 4608;
        const float* sBhi = fsm + 18432 + s * 2304;
        const float* sBlo = fsm + 23040 + s * 2304;

#pragma unroll
        for (int ks = 0; ks < 4; ks++) {
            const int kb = ks * 8;
            uint32_t ahi[2][4], alo[2][4];
#pragma unroll
            for (int i = 0; i < 2; i++) {
                const int rbase = (wm * 32 + i * 16 + g) * 36 + kb + tq;
                ahi[i][0] = __float_as_uint(sAhi[rbase]);
                ahi[i][1] = __float_as_uint(sAhi[rbase + 8 * 36]);
                ahi[i][2] = __float_as_uint(sAhi[rbase + 4]);
                ahi[i][3] = __float_as_uint(sAhi[rbase + 8 * 36 + 4]);
                alo[i][0] = __float_as_uint(sAlo[rbase]);
                alo[i][1] = __float_as_uint(sAlo[rbase + 8 * 36]);
                alo[i][2] = __float_as_uint(sAlo[rbase + 4]);
                alo[i][3] = __float_as_uint(sAlo[rbase + 8 * 36 + 4]);
            }
            uint32_t bhi[4][2], blo[4][2];
#pragma unroll
            for (int j = 0; j < 4; j++) {
                const int col = wn * 32 + j * 8 + g;
                bhi[j][0] = __float_as_uint(sBhi[(kb + tq) * 72 + col]);
                bhi[j][1] = __float_as_uint(sBhi[(kb + tq + 4) * 72 + col]);
                blo[j][0] = __float_as_uint(sBlo[(kb + tq) * 72 + col]);
                blo[j][1] = __float_as_uint(sBlo[(kb + tq + 4) * 72 + col]);
            }
#pragma unroll
            for (int i = 0; i < 2; i++)
#pragma unroll
                for (int j = 0; j < 4; j++) {
                    mma_tf32(acc[i][j], ahi[i][0], ahi[i][1], ahi[i][2], ahi[i][3],
                             blo[j][0], blo[j][1]);
                    mma_tf32(acc[i][j], alo[i][0], alo[i][1], alo[i][2], alo[i][3],
                             bhi[j][0], bhi[j][1]);
                    mma_tf32(acc[i][j], ahi[i][0], ahi[i][1], ahi[i][2], ahi[i][3],
                             bhi[j][0], bhi[j][1]);
                }
        }
        __syncthreads();
    }

    // ---- epilogue ----
    const int region = n0 / EMB;           // block-uniform (MODE 1)
#pragma unroll
    for (int i = 0; i < 2; i++) {
        const int row = m0 + wm * 32 + i * 16 + g;
#pragma unroll
        for (int j = 0; j < 4; j++) {
            const int col = n0 + wn * 32 + j * 8 + 2 * tq;
            const float b0 = bias[col], b1 = bias[col + 1];
            float v00 = acc[i][j][0] + b0, v01 = acc[i][j][1] + b1;
            float v10 = acc[i][j][2] + b0, v11 = acc[i][j][3] + b1;
            if (MODE == 0) {
                *reinterpret_cast<float2*>(&C[(size_t)row * N + col]) =
                    make_float2(v00, v01);
                *reinterpret_cast<float2*>(&C[(size_t)(row + 8) * N + col]) =
                    make_float2(v10, v11);
            } else {
                const int cemb = col - region * EMB;
                const size_t a0 = (size_t)row * EMB + cemb;
                const size_t a1 = (size_t)(row + 8) * EMB + cemb;
                if (region == 0) {
                    *reinterpret_cast<uint2*>(&qtf[a0]) =
                        make_uint2(to_tf32(0.125f * v00), to_tf32(0.125f * v01));
                    *reinterpret_cast<uint2*>(&qtf[a1]) =
                        make_uint2(to_tf32(0.125f * v10), to_tf32(0.125f * v11));
                } else if (region == 1) {
                    *reinterpret_cast<uint2*>(&ktf[a0]) =
                        make_uint2(to_tf32(v00), to_tf32(v01));
                    *reinterpret_cast<uint2*>(&ktf[a1]) =
                        make_uint2(to_tf32(v10), to_tf32(v11));
                } else {
                    uint32_t h0, l0, h1, l1;
                    split_tf32(v00, h0, l0);
                    split_tf32(v01, h1, l1);
                    *reinterpret_cast<uint2*>(&vhi[a0]) = make_uint2(h0, h1);
                    *reinterpret_cast<uint2*>(&vlo[a0]) = make_uint2(l0, l1);
                    split_tf32(v10, h0, l0);
                    split_tf32(v11, h1, l1);
                    *reinterpret_cast<uint2*>(&vhi[a1]) = make_uint2(h0, h1);
                    *reinterpret_cast<uint2*>(&vlo[a1]) = make_uint2(l0, l1);
                }
            }
        }
    }
}

// ============================ mask handling =================================
__global__ void mask_detect_kernel(const unsigned int* __restrict__ mask) {
    unsigned int w0 = mask[0];
    int esize;
    if (w0 == 0x01010101u) esize = 1;
    else if (w0 == 1u || w0 == 0x3f800000u) esize = 4;
    else if ((w0 & 0xFFu) != 0u || (w0 >> 8) == 0u) esize = 1;
    else esize = 4;
    g_mask_esize = esize;
    g_mask_allones = 1;
}

__global__ void mask_scan_kernel(const void* __restrict__ mask) {
    const int esize = g_mask_esize;
    bool any_zero = false;
    if (esize == 4) {
        const unsigned int* m = (const unsigned int*)mask;
        for (long long i = (long long)blockIdx.x * blockDim.x + threadIdx.x;
             i < MASKN; i += (long long)gridDim.x * blockDim.x)
            if (m[i] == 0u) { any_zero = true; break; }
    } else {
        const unsigned int* m = (const unsigned int*)mask;
        for (long long i = (long long)blockIdx.x * blockDim.x + threadIdx.x;
             i < MASKN / 4; i += (long long)gridDim.x * blockDim.x) {
            unsigned int w = m[i];
            if ((w & 0xFFu) == 0 || (w & 0xFF00u) == 0 ||
                (w & 0xFF0000u) == 0 || (w & 0xFF000000u) == 0) { any_zero = true; break; }
        }
    }
    if (any_zero) g_mask_allones = 0;
}

// ============================ attention via mma.sync ========================
// 256 threads (8 warps), 128 query rows, chunks of 64 keys, double-buffered
// cp.async K/V (operands pre-converted/pre-split by QKV GEMM epilogue).
// smem floats: stage s (s=0,1): Ktf@s*13568 [64][68]; Vhi@+4352 [64][72];
//              Vlo@+8960 [64][72]. Phi@27136 [128][68]; Plo@35840 [128][68].
#define AT2_PHI 27136
#define AT2_PLO 35840
#define AT2_BYTES (44544 * 4)   // 178176

__global__ void __launch_bounds__(256)
attn_mma_kernel(const uint32_t* __restrict__ qtf, const uint32_t* __restrict__ ktf,
                const uint32_t* __restrict__ vhi, const uint32_t* __restrict__ vlo,
                const void* __restrict__ mask,
                float* __restrict__ atthi, float* __restrict__ attlo) {
    extern __shared__ float sh[];
    const uint32_t sb = (uint32_t)__cvta_generic_to_shared(sh);
    uint32_t* Phi = reinterpret_cast<uint32_t*>(sh + AT2_PHI);
    uint32_t* Plo = reinterpret_cast<uint32_t*>(sh + AT2_PLO);
    uint32_t* Qstage = Phi;   // Q staged in Phi region before loop

    const int tid = threadIdx.x;
    const int wid = tid >> 5;
    const int lane = tid & 31;
    const int g  = lane >> 2;
    const int tq = lane & 3;
    const int wq = wid * 16;
    const int q0 = blockIdx.x * 128;
    const int h  = blockIdx.y;
    const int b  = blockIdx.z;

    const int mask_allones = g_mask_allones;
    const int mask_esize   = g_mask_esize;
    const size_t rbase = (size_t)b * SEQ;       // row base
    const int hoff = h * DIM;
    const size_t mask_base = (size_t)b * SEQ * SEQ;

    auto issue_kv = [&](int s, int kt) {
        const int k0 = kt * 64;
#pragma unroll
        for (int p = 0; p < 4; p++) {          // K: 64 rows x 16 chunks
            int idx = p * 256 + tid;
            int key = idx >> 4, c = idx & 15;
            const uint32_t* src = ktf + (rbase + k0 + key) * EMB + hoff + c * 4;
            uint32_t dst = sb + (s * 13568 + key * 68 + c * 4) * 4;
            CP16(dst, src);
        }
#pragma unroll
        for (int p = 0; p < 8; p++) {          // Vhi+Vlo: 2 x 1024 chunks
            int idx = p * 256 + tid;
            int mat = idx >> 10;
            int within = idx & 1023;
            int key = within >> 4, c = within & 15;
            const uint32_t* src = (mat == 0 ? vhi : vlo) +
                                  (rbase + k0 + key) * EMB + hoff + c * 4;
            uint32_t dst = sb + (s * 13568 + 4352 + mat * 4608 + key * 72 + c * 4) * 4;
            CP16(dst, src);
        }
        CP_COMMIT();
    };

    // ---- stage Q (cp.async) + first K/V ----
#pragma unroll
    for (int p = 0; p < 8; p++) {
        int idx = p * 256 + tid;
        int r = idx >> 4, c = idx & 15;
        const uint32_t* src = qtf + (rbase + q0 + r) * EMB + hoff + c * 4;
        uint32_t dst = sb + (AT2_PHI + r * 68 + c * 4) * 4;
        CP16(dst, src);
    }
    CP_COMMIT();
    issue_kv(0, 0);
    CP_WAIT1();          // Q group done; kv(0) may still be in flight
    __syncthreads();

    // ---- Q fragments (already scaled+tf32) ----
    uint32_t qf[8][4];
#pragma unroll
    for (int kb = 0; kb < 8; kb++) {
        const int r0 = (wq + g) * 68 + kb * 8 + tq;
        const int r1 = (wq + g + 8) * 68 + kb * 8 + tq;
        qf[kb][0] = Qstage[r0];
        qf[kb][1] = Qstage[r1];
        qf[kb][2] = Qstage[r0 + 4];
        qf[kb][3] = Qstage[r1 + 4];
    }
    __syncthreads();

    float o[8][4];
#pragma unroll
    for (int nt = 0; nt < 8; nt++)
#pragma unroll
        for (int r = 0; r < 4; r++) o[nt][r] = 0.0f;
    float m0r = -1e30f, m1r = -1e30f, l0r = 0.0f, l1r = 0.0f;

    const int nkt = SEQ / 64;
    for (int kt = 0; kt < nkt; kt++) {
        const int s = kt & 1;
        const int k0 = kt * 64;
        if (kt + 1 < nkt) {
            issue_kv(1 - s, kt + 1);
            CP_WAIT1();
        } else {
            CP_WAIT0();
        }
        __syncthreads();

        const uint32_t* Ktf_s = reinterpret_cast<const uint32_t*>(sh + s * 13568);
        const uint32_t* Vhi_s = reinterpret_cast<const uint32_t*>(sh + s * 13568 + 4352);
        const uint32_t* Vlo_s = reinterpret_cast<const uint32_t*>(sh + s * 13568 + 8960);

        // ---- S = (Q/8) K^T ----
        float s4[8][4];
#pragma unroll
        for (int nt = 0; nt < 8; nt++)
#pragma unroll
            for (int r = 0; r < 4; r++) s4[nt][r] = 0.0f;
#pragma unroll
        for (int kb = 0; kb < 8; kb++) {
#pragma unroll
            for (int nt = 0; nt < 8; nt++) {
                uint32_t b0 = Ktf_s[(nt * 8 + g) * 68 + kb * 8 + tq];
                uint32_t b1 = Ktf_s[(nt * 8 + g) * 68 + kb * 8 + tq + 4];
                mma_tf32(s4[nt], qf[kb][0], qf[kb][1], qf[kb][2], qf[kb][3], b0, b1);
            }
        }

        // ---- mask ----
        if (!mask_allones) {
            const int qg0 = q0 + wq + g, qg1 = qg0 + 8;
#pragma unroll
            for (int nt = 0; nt < 8; nt++) {
                int kcol = k0 + nt * 8 + 2 * tq;
                bool mk[4];
                if (mask_esize == 4) {
                    const unsigned int* mm = (const unsigned int*)mask;
                    mk[0] = mm[mask_base + (size_t)qg0 * SEQ + kcol] != 0;
                    mk[1] = mm[mask_base + (size_t)qg0 * SEQ + kcol + 1] != 0;
                    mk[2] = mm[mask_base + (size_t)qg1 * SEQ + kcol] != 0;
                    mk[3] = mm[mask_base + (size_t)qg1 * SEQ + kcol + 1] != 0;
                } else {
                    const unsigned char* mm = (const unsigned char*)mask;
                    mk[0] = mm[mask_base + (size_t)qg0 * SEQ + kcol] != 0;
                    mk[1] = mm[mask_base + (size_t)qg0 * SEQ + kcol + 1] != 0;
                    mk[2] = mm[mask_base + (size_t)qg1 * SEQ + kcol] != 0;
                    mk[3] = mm[mask_base + (size_t)qg1 * SEQ + kcol + 1] != 0;
                }
#pragma unroll
                for (int r = 0; r < 4; r++)
                    if (!mk[r]) s4[nt][r] = -1e9f;
            }
        }

        // ---- online softmax ----
        float mt0 = -1e30f, mt1 = -1e30f;
#pragma unroll
        for (int nt = 0; nt < 8; nt++) {
            mt0 = fmaxf(mt0, fmaxf(s4[nt][0], s4[nt][1]));
            mt1 = fmaxf(mt1, fmaxf(s4[nt][2], s4[nt][3]));
        }
        mt0 = fmaxf(mt0, __shfl_xor_sync(0xffffffff, mt0, 1));
        mt0 = fmaxf(mt0, __shfl_xor_sync(0xffffffff, mt0, 2));
        mt1 = fmaxf(mt1, __shfl_xor_sync(0xffffffff, mt1, 1));
        mt1 = fmaxf(mt1, __shfl_xor_sync(0xffffffff, mt1, 2));

        float mn0 = fmaxf(m0r, mt0), mn1 = fmaxf(m1r, mt1);
        float a0 = __expf(m0r - mn0), a1 = __expf(m1r - mn1);
        m0r = mn0; m1r = mn1;

        float lt0 = 0.0f, lt1 = 0.0f;
#pragma unroll
        for (int nt = 0; nt < 8; nt++) {
            s4[nt][0] = __expf(s4[nt][0] - mn0);
            s4[nt][1] = __expf(s4[nt][1] - mn0);
            s4[nt][2] = __expf(s4[nt][2] - mn1);
            s4[nt][3] = __expf(s4[nt][3] - mn1);
            lt0 += s4[nt][0] + s4[nt][1];
            lt1 += s4[nt][2] + s4[nt][3];
        }
        lt0 += __shfl_xor_sync(0xffffffff, lt0, 1);
        lt0 += __shfl_xor_sync(0xffffffff, lt0, 2);
        lt1 += __shfl_xor_sync(0xffffffff, lt1, 1);
        lt1 += __shfl_xor_sync(0xffffffff, lt1, 2);
        l0r = l0r * a0 + lt0;
        l1r = l1r * a1 + lt1;

#pragma unroll
        for (int nt = 0; nt < 8; nt++) {
            o[nt][0] *= a0; o[nt][1] *= a0;
            o[nt][2] *= a1; o[nt][3] *= a1;
        }

        // ---- split P, store hi/lo to smem (warp-local rows) ----
#pragma unroll
        for (int nt = 0; nt < 8; nt++) {
            uint32_t h0, l0, h1, l1, h2, l2, h3, l3;
            split_tf32(s4[nt][0], h0, l0);
            split_tf32(s4[nt][1], h1, l1);
            split_tf32(s4[nt][2], h2, l2);
            split_tf32(s4[nt][3], h3, l3);
            const int p0 = (wq + g) * 68 + nt * 8 + 2 * tq;
            const int p1 = (wq + g + 8) * 68 + nt * 8 + 2 * tq;
            *reinterpret_cast<uint2*>(&Phi[p0]) = make_uint2(h0, h1);
            *reinterpret_cast<uint2*>(&Phi[p1]) = make_uint2(h2, h3);
            *reinterpret_cast<uint2*>(&Plo[p0]) = make_uint2(l0, l1);
            *reinterpret_cast<uint2*>(&Plo[p1]) = make_uint2(l2, l3);
        }
        __syncwarp();

        // ---- O += P @ V (3-term, pre-split) ----
#pragma unroll
        for (int kb = 0; kb < 8; kb++) {
            const int pr0 = (wq + g) * 68 + kb * 8 + tq;
            const int pr1 = (wq + g + 8) * 68 + kb * 8 + tq;
            uint32_t ph[4], pl[4];
            ph[0] = Phi[pr0]; ph[1] = Phi[pr1];
            ph[2] = Phi[pr0 + 4]; ph[3] = Phi[pr1 + 4];
            pl[0] = Plo[pr0]; pl[1] = Plo[pr1];
            pl[2] = Plo[pr0 + 4]; pl[3] = Plo[pr1 + 4];
            const int vr0 = (kb * 8 + tq) * 72;
            const int vr1 = (kb * 8 + tq + 4) * 72;
#pragma unroll
            for (int nt = 0; nt < 8; nt++) {
                const int d = nt * 8 + g;
                uint32_t vh0 = Vhi_s[vr0 + d], vh1 = Vhi_s[vr1 + d];
                uint32_t vl0 = Vlo_s[vr0 + d], vl1 = Vlo_s[vr1 + d];
                mma_tf32(o[nt], ph[0], ph[1], ph[2], ph[3], vh0, vh1);
                mma_tf32(o[nt], ph[0], ph[1], ph[2], ph[3], vl0, vl1);
                mma_tf32(o[nt], pl[0], pl[1], pl[2], pl[3], vh0, vh1);
            }
        }
        __syncthreads();   // protect buffer 1-s before next issue
    }

    // ---- write output pre-split (consumed by proj GEMM) ----
    const float inv0 = 1.0f / l0r, inv1 = 1.0f / l1r;
    const size_t row0 = rbase + q0 + wq + g;
    const size_t row1 = row0 + 8;
    uint32_t* aHi = reinterpret_cast<uint32_t*>(atthi);
    uint32_t* aLo = reinterpret_cast<uint32_t*>(attlo);
#pragma unroll
    for (int nt = 0; nt < 8; nt++) {
        const int col = hoff + nt * 8 + 2 * tq;
        uint32_t h0, l0, h1, l1, h2, l2, h3, l3;
        split_tf32(o[nt][0] * inv0, h0, l0);
        split_tf32(o[nt][1] * inv0, h1, l1);
        split_tf32(o[nt][2] * inv1, h2, l2);
        split_tf32(o[nt][3] * inv1, h3, l3);
        *reinterpret_cast<uint2*>(&aHi[row0 * EMB + col]) = make_uint2(h0, h1);
        *reinterpret_cast<uint2*>(&aLo[row0 * EMB + col]) = make_uint2(l0, l1);
        *reinterpret_cast<uint2*>(&aHi[row1 * EMB + col]) = make_uint2(h2, h3);
        *reinterpret_cast<uint2*>(&aLo[row1 * EMB + col]) = make_uint2(l2, l3);
    }
}

// ============================================================================
extern "C" void kernel_launch(void* const* d_in, const int* in_sizes, int n_in,
                              void* d_out, int out_size) {
    const float* x      = (const float*)d_in[0];
    const void*  mask   = d_in[1];
    const float* W_pre  = (const float*)d_in[2];
    const float* b_pre  = (const float*)d_in[3];
    const float* W_proj = (const float*)d_in[4];
    const float* b_proj = (const float*)d_in[5];
    float* out = (float*)d_out;

    uint32_t *qtf, *ktf, *vhi, *vlo;
    float *xhi, *xlo, *wph, *wpl, *wjh, *wjl, *ahi, *alo;
    cudaGetSymbolAddress((void**)&qtf, g_qtf);
    cudaGetSymbolAddress((void**)&ktf, g_ktf);
    cudaGetSymbolAddress((void**)&vhi, g_vhi);
    cudaGetSymbolAddress((void**)&vlo, g_vlo);
    cudaGetSymbolAddress((void**)&xhi, g_xhi);
    cudaGetSymbolAddress((void**)&xlo, g_xlo);
    cudaGetSymbolAddress((void**)&wph, g_wpre_hi);
    cudaGetSymbolAddress((void**)&wpl, g_wpre_lo);
    cudaGetSymbolAddress((void**)&wjh, g_wproj_hi);
    cudaGetSymbolAddress((void**)&wjl, g_wproj_lo);
    cudaGetSymbolAddress((void**)&ahi, g_atthi);
    cudaGetSymbolAddress((void**)&alo, g_attlo);

    mask_detect_kernel<<<1, 1>>>((const unsigned int*)mask);
    mask_scan_kernel<<<256, 256>>>(mask);

    split_kernel<<<1024, 256>>>((const float4*)x, (uint4*)xhi, (uint4*)xlo,
                                ROWS * EMB / 4);
    split_kernel<<<1024, 256>>>((const float4*)W_pre, (uint4*)wph, (uint4*)wpl,
                                EMB * QKVN / 4);
    split_kernel<<<512, 256>>>((const float4*)W_proj, (uint4*)wjh, (uint4*)wjl,
                               EMB * EMB / 4);

    cudaFuncSetAttribute(gemm_split_kernel<0>,
                         cudaFuncAttributeMaxDynamicSharedMemorySize, G2_BYTES);
    cudaFuncSetAttribute(gemm_split_kernel<1>,
                         cudaFuncAttributeMaxDynamicSharedMemorySize, G2_BYTES);
    cudaFuncSetAttribute(attn_mma_kernel,
                         cudaFuncAttributeMaxDynamicSharedMemorySize, AT2_BYTES);

    // 1) QKV GEMM -> attention-ready operands
    {
        dim3 grid(QKVN / 64, ROWS / 128);
        gemm_split_kernel<1><<<grid, 256, G2_BYTES>>>(
            xhi, xlo, wph, wpl, b_pre, nullptr, qtf, ktf, vhi, vlo,
            ROWS, QKVN, EMB);
    }
    // 2) Attention (pipelined, conversion-free mainloop)
    {
        dim3 grid(SEQ / 128, HEADS, BATCH);
        attn_mma_kernel<<<grid, 256, AT2_BYTES>>>(qtf, ktf, vhi, vlo, mask,
                                                  ahi, alo);
    }
    // 3) Projection GEMM
    {
        dim3 grid(EMB / 64, ROWS / 128);
        gemm_split_kernel<0><<<grid, 256, G2_BYTES>>>(
            ahi, alo, wjh, wjl, b_proj, out, nullptr, nullptr, nullptr, nullptr,
            ROWS, EMB, EMB);
    }
}

// round 9
// speedup vs baseline: 1.8571x; 1.1055x over previous
#include <cuda_runtime.h>
#include <math.h>
#include <stdint.h>

#define HEADS 12
#define DIM   64
#define BATCH 2
#define SEQ   2048
#define EMB   768
#define QKVN  (3 * HEADS * DIM)   // 2304
#define ROWS  (BATCH * SEQ)       // 4096
#define MASKN (BATCH * SEQ * SEQ) // 8388608

// ----- device scratch -----
__device__ uint32_t g_qtf[ROWS * EMB];   // Q pre-scaled (1/8), tf32
__device__ uint32_t g_ktf[ROWS * EMB];   // K tf32
__device__ uint32_t g_vhi[ROWS * EMB];   // V split hi
__device__ uint32_t g_vlo[ROWS * EMB];   // V split lo
__device__ float g_xhi[ROWS * EMB];
__device__ float g_xlo[ROWS * EMB];
__device__ float g_wpre_hi[EMB * QKVN];
__device__ float g_wpre_lo[EMB * QKVN];
__device__ float g_wproj_hi[EMB * EMB];
__device__ float g_wproj_lo[EMB * EMB];
__device__ float g_atthi[ROWS * EMB];
__device__ float g_attlo[ROWS * EMB];
__device__ int   g_mask_esize;
__device__ int   g_mask_allones;

// ============================ helpers =======================================
__device__ __forceinline__ uint32_t to_tf32(float x) {
    uint32_t r;
    asm("cvt.rna.tf32.f32 %0, %1;" : "=r"(r) : "f"(x));
    return r;
}
__device__ __forceinline__ void split_tf32(float x, uint32_t& hi, uint32_t& lo) {
    asm("cvt.rna.tf32.f32 %0, %1;" : "=r"(hi) : "f"(x));
    float r = x - __uint_as_float(hi);
    asm("cvt.rna.tf32.f32 %0, %1;" : "=r"(lo) : "f"(r));
}
__device__ __forceinline__ void mma_tf32(float c[4],
                                         uint32_t a0, uint32_t a1, uint32_t a2, uint32_t a3,
                                         uint32_t b0, uint32_t b1) {
    asm volatile(
        "mma.sync.aligned.m16n8k8.row.col.f32.tf32.tf32.f32 "
        "{%0,%1,%2,%3}, {%4,%5,%6,%7}, {%8,%9}, {%0,%1,%2,%3};"
        : "+f"(c[0]), "+f"(c[1]), "+f"(c[2]), "+f"(c[3])
        : "r"(a0), "r"(a1), "r"(a2), "r"(a3), "r"(b0), "r"(b1));
}
#define CP16(dst, src) \
    asm volatile("cp.async.ca.shared.global [%0], [%1], 16;" :: "r"(dst), "l"(src) : "memory")
#define CP_COMMIT() asm volatile("cp.async.commit_group;" ::: "memory")
#define CP_WAIT1() asm volatile("cp.async.wait_group 1;" ::: "memory")
#define CP_WAIT0() asm volatile("cp.async.wait_group 0;" ::: "memory")

// ============================ split prepass =================================
__global__ void split_kernel(const float4* __restrict__ in,
                             uint4* __restrict__ hi, uint4* __restrict__ lo, int n4) {
    for (int i = blockIdx.x * blockDim.x + threadIdx.x; i < n4;
         i += gridDim.x * blockDim.x) {
        float4 v = in[i];
        uint4 h, l;
        split_tf32(v.x, h.x, l.x);
        split_tf32(v.y, h.y, l.y);
        split_tf32(v.z, h.z, l.z);
        split_tf32(v.w, h.w, l.w);
        hi[i] = h;
        lo[i] = l;
    }
}

// ============================ GEMM (pre-split, cp.async pipelined) ==========
// MODE 0: C = acc + bias (fp32). MODE 1: QKV epilogue -> qtf/ktf/vhi/vlo.
#define G2_BYTES 110592

template <int MODE>
__global__ void __launch_bounds__(256, 2)
gemm_split_kernel(const float* __restrict__ Ahi, const float* __restrict__ Alo,
                  const float* __restrict__ Bhi, const float* __restrict__ Blo,
                  const float* __restrict__ bias, float* __restrict__ C,
                  uint32_t* __restrict__ qtf, uint32_t* __restrict__ ktf,
                  uint32_t* __restrict__ vhi, uint32_t* __restrict__ vlo,
                  int M, int N, int K) {
    extern __shared__ char smraw[];
    float* fsm = reinterpret_cast<float*>(smraw);
    const uint32_t sb = (uint32_t)__cvta_generic_to_shared(smraw);

    const int tid = threadIdx.x;
    const int wid = tid >> 5;
    const int lane = tid & 31;
    const int g  = lane >> 2;
    const int tq = lane & 3;
    const int wm = wid >> 1;
    const int wn = wid & 1;
    const int m0 = blockIdx.y * 128;
    const int n0 = blockIdx.x * 64;
    const int nkt = K / 32;

    float acc[2][4][4];
#pragma unroll
    for (int i = 0; i < 2; i++)
#pragma unroll
        for (int j = 0; j < 4; j++)
#pragma unroll
            for (int r = 0; r < 4; r++) acc[i][j][r] = 0.0f;

    auto issue_tile = [&](int s, int kt) {
#pragma unroll
        for (int p = 0; p < 4; p++) {
            int idx = p * 256 + tid;
            int r = idx >> 3, ch = idx & 7;
            const float* srcH = Ahi + (size_t)(m0 + r) * K + kt * 32 + ch * 4;
            const float* srcL = Alo + (size_t)(m0 + r) * K + kt * 32 + ch * 4;
            uint32_t dH = sb + s * 18432 + (r * 36 + ch * 4) * 4;
            uint32_t dL = sb + 36864 + s * 18432 + (r * 36 + ch * 4) * 4;
            CP16(dH, srcH);
            CP16(dL, srcL);
        }
#pragma unroll
        for (int p = 0; p < 4; p++) {
            int idx = p * 256 + tid;
            int mat = idx >> 9;
            int within = idx & 511;
            int r = within >> 4;
            int ch = within & 15;
            const float* src = (mat == 0 ? Bhi : Blo) +
                               (size_t)(kt * 32 + r) * N + n0 + ch * 4;
            uint32_t dst = sb + (mat == 0 ? 73728u : 92160u) + s * 9216 +
                           (r * 72 + ch * 4) * 4;
            CP16(dst, src);
        }
        CP_COMMIT();
    };

    issue_tile(0, 0);

    for (int kt = 0; kt < nkt; kt++) {
        const int s = kt & 1;
        if (kt + 1 < nkt) {
            issue_tile(1 - s, kt + 1);
            CP_WAIT1();
        } else {
            CP_WAIT0();
        }
        __syncthreads();

        const float* sAhi = fsm + s * 4608;
        const float* sAlo = fsm + 9216 + s * 4608;
        const float* sBhi = fsm + 18432 + s * 2304;
        const float* sBlo = fsm + 23040 + s * 2304;

#pragma unroll
        for (int ks = 0; ks < 4; ks++) {
            const int kb = ks * 8;
            uint32_t ahi[2][4], alo[2][4];
#pragma unroll
            for (int i = 0; i < 2; i++) {
                const int rbase = (wm * 32 + i * 16 + g) * 36 + kb + tq;
                ahi[i][0] = __float_as_uint(sAhi[rbase]);
                ahi[i][1] = __float_as_uint(sAhi[rbase + 8 * 36]);
                ahi[i][2] = __float_as_uint(sAhi[rbase + 4]);
                ahi[i][3] = __float_as_uint(sAhi[rbase + 8 * 36 + 4]);
                alo[i][0] = __float_as_uint(sAlo[rbase]);
                alo[i][1] = __float_as_uint(sAlo[rbase + 8 * 36]);
                alo[i][2] = __float_as_uint(sAlo[rbase + 4]);
                alo[i][3] = __float_as_uint(sAlo[rbase + 8 * 36 + 4]);
            }
            uint32_t bhi[4][2], blo[4][2];
#pragma unroll
            for (int j = 0; j < 4; j++) {
                const int col = wn * 32 + j * 8 + g;
                bhi[j][0] = __float_as_uint(sBhi[(kb + tq) * 72 + col]);
                bhi[j][1] = __float_as_uint(sBhi[(kb + tq + 4) * 72 + col]);
                blo[j][0] = __float_as_uint(sBlo[(kb + tq) * 72 + col]);
                blo[j][1] = __float_as_uint(sBlo[(kb + tq + 4) * 72 + col]);
            }
#pragma unroll
            for (int i = 0; i < 2; i++)
#pragma unroll
                for (int j = 0; j < 4; j++) {
                    mma_tf32(acc[i][j], ahi[i][0], ahi[i][1], ahi[i][2], ahi[i][3],
                             blo[j][0], blo[j][1]);
                    mma_tf32(acc[i][j], alo[i][0], alo[i][1], alo[i][2], alo[i][3],
                             bhi[j][0], bhi[j][1]);
                    mma_tf32(acc[i][j], ahi[i][0], ahi[i][1], ahi[i][2], ahi[i][3],
                             bhi[j][0], bhi[j][1]);
                }
        }
        __syncthreads();
    }

    // ---- epilogue ----
    const int region = n0 / EMB;           // block-uniform (MODE 1)
#pragma unroll
    for (int i = 0; i < 2; i++) {
        const int row = m0 + wm * 32 + i * 16 + g;
#pragma unroll
        for (int j = 0; j < 4; j++) {
            const int col = n0 + wn * 32 + j * 8 + 2 * tq;
            const float b0 = bias[col], b1 = bias[col + 1];
            float v00 = acc[i][j][0] + b0, v01 = acc[i][j][1] + b1;
            float v10 = acc[i][j][2] + b0, v11 = acc[i][j][3] + b1;
            if (MODE == 0) {
                *reinterpret_cast<float2*>(&C[(size_t)row * N + col]) =
                    make_float2(v00, v01);
                *reinterpret_cast<float2*>(&C[(size_t)(row + 8) * N + col]) =
                    make_float2(v10, v11);
            } else {
                const int cemb = col - region * EMB;
                const size_t a0 = (size_t)row * EMB + cemb;
                const size_t a1 = (size_t)(row + 8) * EMB + cemb;
                if (region == 0) {
                    *reinterpret_cast<uint2*>(&qtf[a0]) =
                        make_uint2(to_tf32(0.125f * v00), to_tf32(0.125f * v01));
                    *reinterpret_cast<uint2*>(&qtf[a1]) =
                        make_uint2(to_tf32(0.125f * v10), to_tf32(0.125f * v11));
                } else if (region == 1) {
                    *reinterpret_cast<uint2*>(&ktf[a0]) =
                        make_uint2(to_tf32(v00), to_tf32(v01));
                    *reinterpret_cast<uint2*>(&ktf[a1]) =
                        make_uint2(to_tf32(v10), to_tf32(v11));
                } else {
                    uint32_t h0, l0, h1, l1;
                    split_tf32(v00, h0, l0);
                    split_tf32(v01, h1, l1);
                    *reinterpret_cast<uint2*>(&vhi[a0]) = make_uint2(h0, h1);
                    *reinterpret_cast<uint2*>(&vlo[a0]) = make_uint2(l0, l1);
                    split_tf32(v10, h0, l0);
                    split_tf32(v11, h1, l1);
                    *reinterpret_cast<uint2*>(&vhi[a1]) = make_uint2(h0, h1);
                    *reinterpret_cast<uint2*>(&vlo[a1]) = make_uint2(l0, l1);
                }
            }
        }
    }
}

// ============================ mask handling =================================
__global__ void mask_detect_kernel(const unsigned int* __restrict__ mask) {
    unsigned int w0 = mask[0];
    int esize;
    if (w0 == 0x01010101u) esize = 1;
    else if (w0 == 1u || w0 == 0x3f800000u) esize = 4;
    else if ((w0 & 0xFFu) != 0u || (w0 >> 8) == 0u) esize = 1;
    else esize = 4;
    g_mask_esize = esize;
    g_mask_allones = 1;
}

__global__ void mask_scan_kernel(const void* __restrict__ mask) {
    const int esize = g_mask_esize;
    bool any_zero = false;
    if (esize == 4) {
        const unsigned int* m = (const unsigned int*)mask;
        for (long long i = (long long)blockIdx.x * blockDim.x + threadIdx.x;
             i < MASKN; i += (long long)gridDim.x * blockDim.x)
            if (m[i] == 0u) { any_zero = true; break; }
    } else {
        const unsigned int* m = (const unsigned int*)mask;
        for (long long i = (long long)blockIdx.x * blockDim.x + threadIdx.x;
             i < MASKN / 4; i += (long long)gridDim.x * blockDim.x) {
            unsigned int w = m[i];
            if ((w & 0xFFu) == 0 || (w & 0xFF00u) == 0 ||
                (w & 0xFF0000u) == 0 || (w & 0xFF000000u) == 0) { any_zero = true; break; }
        }
    }
    if (any_zero) g_mask_allones = 0;
}

// ============================ attention via mma.sync ========================
// 256 threads (8 warps), 128 query rows, chunks of 64 keys, double-buffered
// cp.async K/V. QK single tf32 (scale folded). PV 2-term: Phi*(Vhi+Vlo).
// smem floats: stage s: Ktf@s*13568 [64][68]; Vhi@+4352 [64][72];
//              Vlo@+8960 [64][72]. Phi@27136 [128][68]. Total 35840 fl.
#define AT2_PHI 27136
#define AT2_BYTES (35840 * 4)   // 143360

__global__ void __launch_bounds__(256)
attn_mma_kernel(const uint32_t* __restrict__ qtf, const uint32_t* __restrict__ ktf,
                const uint32_t* __restrict__ vhi, const uint32_t* __restrict__ vlo,
                const void* __restrict__ mask,
                float* __restrict__ atthi, float* __restrict__ attlo) {
    extern __shared__ float sh[];
    const uint32_t sb = (uint32_t)__cvta_generic_to_shared(sh);
    uint32_t* Phi = reinterpret_cast<uint32_t*>(sh + AT2_PHI);
    uint32_t* Qstage = Phi;   // Q staged in Phi region before loop

    const int tid = threadIdx.x;
    const int wid = tid >> 5;
    const int lane = tid & 31;
    const int g  = lane >> 2;
    const int tq = lane & 3;
    const int wq = wid * 16;
    const int q0 = blockIdx.x * 128;
    const int h  = blockIdx.y;
    const int b  = blockIdx.z;

    const int mask_allones = g_mask_allones;
    const int mask_esize   = g_mask_esize;
    const size_t rbase = (size_t)b * SEQ;
    const int hoff = h * DIM;
    const size_t mask_base = (size_t)b * SEQ * SEQ;

    auto issue_kv = [&](int s, int kt) {
        const int k0 = kt * 64;
#pragma unroll
        for (int p = 0; p < 4; p++) {          // K: 64 rows x 16 chunks
            int idx = p * 256 + tid;
            int key = idx >> 4, c = idx & 15;
            const uint32_t* src = ktf + (rbase + k0 + key) * EMB + hoff + c * 4;
            uint32_t dst = sb + (s * 13568 + key * 68 + c * 4) * 4;
            CP16(dst, src);
        }
#pragma unroll
        for (int p = 0; p < 8; p++) {          // Vhi+Vlo: 2 x 1024 chunks
            int idx = p * 256 + tid;
            int mat = idx >> 10;
            int within = idx & 1023;
            int key = within >> 4, c = within & 15;
            const uint32_t* src = (mat == 0 ? vhi : vlo) +
                                  (rbase + k0 + key) * EMB + hoff + c * 4;
            uint32_t dst = sb + (s * 13568 + 4352 + mat * 4608 + key * 72 + c * 4) * 4;
            CP16(dst, src);
        }
        CP_COMMIT();
    };

    // ---- stage Q (cp.async) + first K/V ----
#pragma unroll
    for (int p = 0; p < 8; p++) {
        int idx = p * 256 + tid;
        int r = idx >> 4, c = idx & 15;
        const uint32_t* src = qtf + (rbase + q0 + r) * EMB + hoff + c * 4;
        uint32_t dst = sb + (AT2_PHI + r * 68 + c * 4) * 4;
        CP16(dst, src);
    }
    CP_COMMIT();
    issue_kv(0, 0);
    CP_WAIT1();          // Q group done
    __syncthreads();

    uint32_t qf[8][4];
#pragma unroll
    for (int kb = 0; kb < 8; kb++) {
        const int r0 = (wq + g) * 68 + kb * 8 + tq;
        const int r1 = (wq + g + 8) * 68 + kb * 8 + tq;
        qf[kb][0] = Qstage[r0];
        qf[kb][1] = Qstage[r1];
        qf[kb][2] = Qstage[r0 + 4];
        qf[kb][3] = Qstage[r1 + 4];
    }
    __syncthreads();

    float o[8][4];
#pragma unroll
    for (int nt = 0; nt < 8; nt++)
#pragma unroll
        for (int r = 0; r < 4; r++) o[nt][r] = 0.0f;
    float m0r = -1e30f, m1r = -1e30f, l0r = 0.0f, l1r = 0.0f;

    const int nkt = SEQ / 64;
    for (int kt = 0; kt < nkt; kt++) {
        const int s = kt & 1;
        const int k0 = kt * 64;
        if (kt + 1 < nkt) {
            issue_kv(1 - s, kt + 1);
            CP_WAIT1();
        } else {
            CP_WAIT0();
        }
        __syncthreads();

        const uint32_t* Ktf_s = reinterpret_cast<const uint32_t*>(sh + s * 13568);
        const uint32_t* Vhi_s = reinterpret_cast<const uint32_t*>(sh + s * 13568 + 4352);
        const uint32_t* Vlo_s = reinterpret_cast<const uint32_t*>(sh + s * 13568 + 8960);

        // ---- S = (Q/8) K^T ----
        float s4[8][4];
#pragma unroll
        for (int nt = 0; nt < 8; nt++)
#pragma unroll
            for (int r = 0; r < 4; r++) s4[nt][r] = 0.0f;
#pragma unroll
        for (int kb = 0; kb < 8; kb++) {
#pragma unroll
            for (int nt = 0; nt < 8; nt++) {
                uint32_t b0 = Ktf_s[(nt * 8 + g) * 68 + kb * 8 + tq];
                uint32_t b1 = Ktf_s[(nt * 8 + g) * 68 + kb * 8 + tq + 4];
                mma_tf32(s4[nt], qf[kb][0], qf[kb][1], qf[kb][2], qf[kb][3], b0, b1);
            }
        }

        // ---- mask ----
        if (!mask_allones) {
            const int qg0 = q0 + wq + g, qg1 = qg0 + 8;
#pragma unroll
            for (int nt = 0; nt < 8; nt++) {
                int kcol = k0 + nt * 8 + 2 * tq;
                bool mk[4];
                if (mask_esize == 4) {
                    const unsigned int* mm = (const unsigned int*)mask;
                    mk[0] = mm[mask_base + (size_t)qg0 * SEQ + kcol] != 0;
                    mk[1] = mm[mask_base + (size_t)qg0 * SEQ + kcol + 1] != 0;
                    mk[2] = mm[mask_base + (size_t)qg1 * SEQ + kcol] != 0;
                    mk[3] = mm[mask_base + (size_t)qg1 * SEQ + kcol + 1] != 0;
                } else {
                    const unsigned char* mm = (const unsigned char*)mask;
                    mk[0] = mm[mask_base + (size_t)qg0 * SEQ + kcol] != 0;
                    mk[1] = mm[mask_base + (size_t)qg0 * SEQ + kcol + 1] != 0;
                    mk[2] = mm[mask_base + (size_t)qg1 * SEQ + kcol] != 0;
                    mk[3] = mm[mask_base + (size_t)qg1 * SEQ + kcol + 1] != 0;
                }
#pragma unroll
                for (int r = 0; r < 4; r++)
                    if (!mk[r]) s4[nt][r] = -1e9f;
            }
        }

        // ---- online softmax ----
        float mt0 = -1e30f, mt1 = -1e30f;
#pragma unroll
        for (int nt = 0; nt < 8; nt++) {
            mt0 = fmaxf(mt0, fmaxf(s4[nt][0], s4[nt][1]));
            mt1 = fmaxf(mt1, fmaxf(s4[nt][2], s4[nt][3]));
        }
        mt0 = fmaxf(mt0, __shfl_xor_sync(0xffffffff, mt0, 1));
        mt0 = fmaxf(mt0, __shfl_xor_sync(0xffffffff, mt0, 2));
        mt1 = fmaxf(mt1, __shfl_xor_sync(0xffffffff, mt1, 1));
        mt1 = fmaxf(mt1, __shfl_xor_sync(0xffffffff, mt1, 2));

        float mn0 = fmaxf(m0r, mt0), mn1 = fmaxf(m1r, mt1);
        float a0 = __expf(m0r - mn0), a1 = __expf(m1r - mn1);
        m0r = mn0; m1r = mn1;

        float lt0 = 0.0f, lt1 = 0.0f;
#pragma unroll
        for (int nt = 0; nt < 8; nt++) {
            s4[nt][0] = __expf(s4[nt][0] - mn0);
            s4[nt][1] = __expf(s4[nt][1] - mn0);
            s4[nt][2] = __expf(s4[nt][2] - mn1);
            s4[nt][3] = __expf(s4[nt][3] - mn1);
            lt0 += s4[nt][0] + s4[nt][1];
            lt1 += s4[nt][2] + s4[nt][3];
        }
        lt0 += __shfl_xor_sync(0xffffffff, lt0, 1);
        lt0 += __shfl_xor_sync(0xffffffff, lt0, 2);
        lt1 += __shfl_xor_sync(0xffffffff, lt1, 1);
        lt1 += __shfl_xor_sync(0xffffffff, lt1, 2);
        l0r = l0r * a0 + lt0;
        l1r = l1r * a1 + lt1;

#pragma unroll
        for (int nt = 0; nt < 8; nt++) {
            o[nt][0] *= a0; o[nt][1] *= a0;
            o[nt][2] *= a1; o[nt][3] *= a1;
        }

        // ---- P -> tf32 hi only, store to smem (warp-local rows) ----
#pragma unroll
        for (int nt = 0; nt < 8; nt++) {
            const int p0 = (wq + g) * 68 + nt * 8 + 2 * tq;
            const int p1 = (wq + g + 8) * 68 + nt * 8 + 2 * tq;
            *reinterpret_cast<uint2*>(&Phi[p0]) =
                make_uint2(to_tf32(s4[nt][0]), to_tf32(s4[nt][1]));
            *reinterpret_cast<uint2*>(&Phi[p1]) =
                make_uint2(to_tf32(s4[nt][2]), to_tf32(s4[nt][3]));
        }
        __syncwarp();

        // ---- O += Phi @ (Vhi + Vlo)  (2-term) ----
#pragma unroll
        for (int kb = 0; kb < 8; kb++) {
            const int pr0 = (wq + g) * 68 + kb * 8 + tq;
            const int pr1 = (wq + g + 8) * 68 + kb * 8 + tq;
            uint32_t ph[4];
            ph[0] = Phi[pr0]; ph[1] = Phi[pr1];
            ph[2] = Phi[pr0 + 4]; ph[3] = Phi[pr1 + 4];
            const int vr0 = (kb * 8 + tq) * 72;
            const int vr1 = (kb * 8 + tq + 4) * 72;
#pragma unroll
            for (int nt = 0; nt < 8; nt++) {
                const int d = nt * 8 + g;
                uint32_t vh0 = Vhi_s[vr0 + d], vh1 = Vhi_s[vr1 + d];
                uint32_t vl0 = Vlo_s[vr0 + d], vl1 = Vlo_s[vr1 + d];
                mma_tf32(o[nt], ph[0], ph[1], ph[2], ph[3], vh0, vh1);
                mma_tf32(o[nt], ph[0], ph[1], ph[2], ph[3], vl0, vl1);
            }
        }
        __syncthreads();   // protect buffer 1-s before next issue
    }

    // ---- write output pre-split (consumed by proj GEMM) ----
    const float inv0 = 1.0f / l0r, inv1 = 1.0f / l1r;
    const size_t row0 = rbase + q0 + wq + g;
    const size_t row1 = row0 + 8;
    uint32_t* aHi = reinterpret_cast<uint32_t*>(atthi);
    uint32_t* aLo = reinterpret_cast<uint32_t*>(attlo);
#pragma unroll
    for (int nt = 0; nt < 8; nt++) {
        const int col = hoff + nt * 8 + 2 * tq;
        uint32_t h0, l0, h1, l1, h2, l2, h3, l3;
        split_tf32(o[nt][0] * inv0, h0, l0);
        split_tf32(o[nt][1] * inv0, h1, l1);
        split_tf32(o[nt][2] * inv1, h2, l2);
        split_tf32(o[nt][3] * inv1, h3, l3);
        *reinterpret_cast<uint2*>(&aHi[row0 * EMB + col]) = make_uint2(h0, h1);
        *reinterpret_cast<uint2*>(&aLo[row0 * EMB + col]) = make_uint2(l0, l1);
        *reinterpret_cast<uint2*>(&aHi[row1 * EMB + col]) = make_uint2(h2, h3);
        *reinterpret_cast<uint2*>(&aLo[row1 * EMB + col]) = make_uint2(l2, l3);
    }
}

// ============================================================================
extern "C" void kernel_launch(void* const* d_in, const int* in_sizes, int n_in,
                              void* d_out, int out_size) {
    const float* x      = (const float*)d_in[0];
    const void*  mask   = d_in[1];
    const float* W_pre  = (const float*)d_in[2];
    const float* b_pre  = (const float*)d_in[3];
    const float* W_proj = (const float*)d_in[4];
    const float* b_proj = (const float*)d_in[5];
    float* out = (float*)d_out;

    uint32_t *qtf, *ktf, *vhi, *vlo;
    float *xhi, *xlo, *wph, *wpl, *wjh, *wjl, *ahi, *alo;
    cudaGetSymbolAddress((void**)&qtf, g_qtf);
    cudaGetSymbolAddress((void**)&ktf, g_ktf);
    cudaGetSymbolAddress((void**)&vhi, g_vhi);
    cudaGetSymbolAddress((void**)&vlo, g_vlo);
    cudaGetSymbolAddress((void**)&xhi, g_xhi);
    cudaGetSymbolAddress((void**)&xlo, g_xlo);
    cudaGetSymbolAddress((void**)&wph, g_wpre_hi);
    cudaGetSymbolAddress((void**)&wpl, g_wpre_lo);
    cudaGetSymbolAddress((void**)&wjh, g_wproj_hi);
    cudaGetSymbolAddress((void**)&wjl, g_wproj_lo);
    cudaGetSymbolAddress((void**)&ahi, g_atthi);
    cudaGetSymbolAddress((void**)&alo, g_attlo);

    mask_detect_kernel<<<1, 1>>>((const unsigned int*)mask);
    mask_scan_kernel<<<256, 256>>>(mask);

    split_kernel<<<1024, 256>>>((const float4*)x, (uint4*)xhi, (uint4*)xlo,
                                ROWS * EMB / 4);
    split_kernel<<<1024, 256>>>((const float4*)W_pre, (uint4*)wph, (uint4*)wpl,
                                EMB * QKVN / 4);
    split_kernel<<<512, 256>>>((const float4*)W_proj, (uint4*)wjh, (uint4*)wjl,
                               EMB * EMB / 4);

    cudaFuncSetAttribute(gemm_split_kernel<0>,
                         cudaFuncAttributeMaxDynamicSharedMemorySize, G2_BYTES);
    cudaFuncSetAttribute(gemm_split_kernel<1>,
                         cudaFuncAttributeMaxDynamicSharedMemorySize, G2_BYTES);
    cudaFuncSetAttribute(attn_mma_kernel,
                         cudaFuncAttributeMaxDynamicSharedMemorySize, AT2_BYTES);

    // 1) QKV GEMM -> attention-ready operands
    {
        dim3 grid(QKVN / 64, ROWS / 128);
        gemm_split_kernel<1><<<grid, 256, G2_BYTES>>>(
            xhi, xlo, wph, wpl, b_pre, nullptr, qtf, ktf, vhi, vlo,
            ROWS, QKVN, EMB);
    }
    // 2) Attention (pipelined, conversion-free mainloop, 2-term PV)
    {
        dim3 grid(SEQ / 128, HEADS, BATCH);
        attn_mma_kernel<<<grid, 256, AT2_BYTES>>>(qtf, ktf, vhi, vlo, mask,
                                                  ahi, alo);
    }
    // 3) Projection GEMM
    {
        dim3 grid(EMB / 64, ROWS / 128);
        gemm_split_kernel<0><<<grid, 256, G2_BYTES>>>(
            ahi, alo, wjh, wjl, b_proj, out, nullptr, nullptr, nullptr, nullptr,
            ROWS, EMB, EMB);
    }
}

// round 10
// speedup vs baseline: 2.1814x; 1.1746x over previous
#include <cuda_runtime.h>
#include <math.h>
#include <stdint.h>

#define HEADS 12
#define DIM   64
#define BATCH 2
#define SEQ   2048
#define EMB   768
#define QKVN  (3 * HEADS * DIM)   // 2304
#define ROWS  (BATCH * SEQ)       // 4096
#define MASKN (BATCH * SEQ * SEQ) // 8388608

// ----- device scratch -----
__device__ uint32_t g_qtf[ROWS * EMB];   // Q pre-scaled (1/8), tf32
__device__ uint32_t g_ktf[ROWS * EMB];   // K tf32
__device__ uint32_t g_vhi[ROWS * EMB];   // V split hi
__device__ uint32_t g_vlo[ROWS * EMB];   // V split lo
__device__ uint32_t g_xtf[ROWS * EMB];   // x as single tf32
__device__ uint32_t g_atttf[ROWS * EMB]; // attention out, single tf32
__device__ float g_wpre_hi[EMB * QKVN];
__device__ float g_wpre_lo[EMB * QKVN];
__device__ float g_wproj_hi[EMB * EMB];
__device__ float g_wproj_lo[EMB * EMB];
__device__ int   g_mask_esize;
__device__ int   g_mask_allones;

// ============================ helpers =======================================
__device__ __forceinline__ uint32_t to_tf32(float x) {
    uint32_t r;
    asm("cvt.rna.tf32.f32 %0, %1;" : "=r"(r) : "f"(x));
    return r;
}
__device__ __forceinline__ void split_tf32(float x, uint32_t& hi, uint32_t& lo) {
    asm("cvt.rna.tf32.f32 %0, %1;" : "=r"(hi) : "f"(x));
    float r = x - __uint_as_float(hi);
    asm("cvt.rna.tf32.f32 %0, %1;" : "=r"(lo) : "f"(r));
}
__device__ __forceinline__ void mma_tf32(float c[4],
                                         uint32_t a0, uint32_t a1, uint32_t a2, uint32_t a3,
                                         uint32_t b0, uint32_t b1) {
    asm volatile(
        "mma.sync.aligned.m16n8k8.row.col.f32.tf32.tf32.f32 "
        "{%0,%1,%2,%3}, {%4,%5,%6,%7}, {%8,%9}, {%0,%1,%2,%3};"
        : "+f"(c[0]), "+f"(c[1]), "+f"(c[2]), "+f"(c[3])
        : "r"(a0), "r"(a1), "r"(a2), "r"(a3), "r"(b0), "r"(b1));
}
#define CP16(dst, src) \
    asm volatile("cp.async.ca.shared.global [%0], [%1], 16;" :: "r"(dst), "l"(src) : "memory")
#define CP_COMMIT() asm volatile("cp.async.commit_group;" ::: "memory")
#define CP_WAIT1() asm volatile("cp.async.wait_group 1;" ::: "memory")
#define CP_WAIT0() asm volatile("cp.async.wait_group 0;" ::: "memory")

// ============================ prepass kernels ===============================
__global__ void split_kernel(const float4* __restrict__ in,
                             uint4* __restrict__ hi, uint4* __restrict__ lo, int n4) {
    for (int i = blockIdx.x * blockDim.x + threadIdx.x; i < n4;
         i += gridDim.x * blockDim.x) {
        float4 v = in[i];
        uint4 h, l;
        split_tf32(v.x, h.x, l.x);
        split_tf32(v.y, h.y, l.y);
        split_tf32(v.z, h.z, l.z);
        split_tf32(v.w, h.w, l.w);
        hi[i] = h;
        lo[i] = l;
    }
}
__global__ void cvt_kernel(const float4* __restrict__ in,
                           uint4* __restrict__ out, int n4) {
    for (int i = blockIdx.x * blockDim.x + threadIdx.x; i < n4;
         i += gridDim.x * blockDim.x) {
        float4 v = in[i];
        out[i] = make_uint4(to_tf32(v.x), to_tf32(v.y), to_tf32(v.z), to_tf32(v.w));
    }
}

// ============================ GEMM (A single tf32, B hi+lo) =================
// C = A*(Bhi+Blo) + bias (2-term). MODE 0: fp32 out. MODE 1: QKV epilogue.
// smem bytes/stage: sA 18432 (128x36 u32), sBhi 9216, sBlo 9216 ([32][72]).
// Layout: sA @ s*18432 ; sBhi @ 36864+s*9216 ; sBlo @ 55296+s*9216.
#define G3_BYTES 73728

template <int MODE>
__global__ void __launch_bounds__(256, 2)
gemm_split_kernel(const uint32_t* __restrict__ Atf,
                  const float* __restrict__ Bhi, const float* __restrict__ Blo,
                  const float* __restrict__ bias, float* __restrict__ C,
                  uint32_t* __restrict__ qtf, uint32_t* __restrict__ ktf,
                  uint32_t* __restrict__ vhi, uint32_t* __restrict__ vlo,
                  int M, int N, int K) {
    extern __shared__ char smraw[];
    float* fsm = reinterpret_cast<float*>(smraw);
    const uint32_t sb = (uint32_t)__cvta_generic_to_shared(smraw);

    const int tid = threadIdx.x;
    const int wid = tid >> 5;
    const int lane = tid & 31;
    const int g  = lane >> 2;
    const int tq = lane & 3;
    const int wm = wid >> 1;
    const int wn = wid & 1;
    const int m0 = blockIdx.y * 128;
    const int n0 = blockIdx.x * 64;
    const int nkt = K / 32;

    float acc[2][4][4];
#pragma unroll
    for (int i = 0; i < 2; i++)
#pragma unroll
        for (int j = 0; j < 4; j++)
#pragma unroll
            for (int r = 0; r < 4; r++) acc[i][j][r] = 0.0f;

    auto issue_tile = [&](int s, int kt) {
#pragma unroll
        for (int p = 0; p < 4; p++) {          // A: 128x32 u32 = 1024 chunks
            int idx = p * 256 + tid;
            int r = idx >> 3, ch = idx & 7;
            const uint32_t* src = Atf + (size_t)(m0 + r) * K + kt * 32 + ch * 4;
            uint32_t dst = sb + s * 18432 + (r * 36 + ch * 4) * 4;
            CP16(dst, src);
        }
#pragma unroll
        for (int p = 0; p < 4; p++) {          // Bhi+Blo: 2 x 512 chunks
            int idx = p * 256 + tid;
            int mat = idx >> 9;
            int within = idx & 511;
            int r = within >> 4;
            int ch = within & 15;
            const float* src = (mat == 0 ? Bhi : Blo) +
                               (size_t)(kt * 32 + r) * N + n0 + ch * 4;
            uint32_t dst = sb + (mat == 0 ? 36864u : 55296u) + s * 9216 +
                           (r * 72 + ch * 4) * 4;
            CP16(dst, src);
        }
        CP_COMMIT();
    };

    issue_tile(0, 0);

    for (int kt = 0; kt < nkt; kt++) {
        const int s = kt & 1;
        if (kt + 1 < nkt) {
            issue_tile(1 - s, kt + 1);
            CP_WAIT1();
        } else {
            CP_WAIT0();
        }
        __syncthreads();

        const float* sA   = fsm + s * 4608;
        const float* sBhi = fsm + 9216 + s * 2304;
        const float* sBlo = fsm + 13824 + s * 2304;

#pragma unroll
        for (int ks = 0; ks < 4; ks++) {
            const int kb = ks * 8;
            uint32_t af[2][4];
#pragma unroll
            for (int i = 0; i < 2; i++) {
                const int rbase = (wm * 32 + i * 16 + g) * 36 + kb + tq;
                af[i][0] = __float_as_uint(sA[rbase]);
                af[i][1] = __float_as_uint(sA[rbase + 8 * 36]);
                af[i][2] = __float_as_uint(sA[rbase + 4]);
                af[i][3] = __float_as_uint(sA[rbase + 8 * 36 + 4]);
            }
            uint32_t bhi[4][2], blo[4][2];
#pragma unroll
            for (int j = 0; j < 4; j++) {
                const int col = wn * 32 + j * 8 + g;
                bhi[j][0] = __float_as_uint(sBhi[(kb + tq) * 72 + col]);
                bhi[j][1] = __float_as_uint(sBhi[(kb + tq + 4) * 72 + col]);
                blo[j][0] = __float_as_uint(sBlo[(kb + tq) * 72 + col]);
                blo[j][1] = __float_as_uint(sBlo[(kb + tq + 4) * 72 + col]);
            }
#pragma unroll
            for (int i = 0; i < 2; i++)
#pragma unroll
                for (int j = 0; j < 4; j++) {
                    mma_tf32(acc[i][j], af[i][0], af[i][1], af[i][2], af[i][3],
                             blo[j][0], blo[j][1]);
                    mma_tf32(acc[i][j], af[i][0], af[i][1], af[i][2], af[i][3],
                             bhi[j][0], bhi[j][1]);
                }
        }
        __syncthreads();
    }

    // ---- epilogue ----
    const int region = n0 / EMB;           // block-uniform (MODE 1)
#pragma unroll
    for (int i = 0; i < 2; i++) {
        const int row = m0 + wm * 32 + i * 16 + g;
#pragma unroll
        for (int j = 0; j < 4; j++) {
            const int col = n0 + wn * 32 + j * 8 + 2 * tq;
            const float b0 = bias[col], b1 = bias[col + 1];
            float v00 = acc[i][j][0] + b0, v01 = acc[i][j][1] + b1;
            float v10 = acc[i][j][2] + b0, v11 = acc[i][j][3] + b1;
            if (MODE == 0) {
                *reinterpret_cast<float2*>(&C[(size_t)row * N + col]) =
                    make_float2(v00, v01);
                *reinterpret_cast<float2*>(&C[(size_t)(row + 8) * N + col]) =
                    make_float2(v10, v11);
            } else {
                const int cemb = col - region * EMB;
                const size_t a0 = (size_t)row * EMB + cemb;
                const size_t a1 = (size_t)(row + 8) * EMB + cemb;
                if (region == 0) {
                    *reinterpret_cast<uint2*>(&qtf[a0]) =
                        make_uint2(to_tf32(0.125f * v00), to_tf32(0.125f * v01));
                    *reinterpret_cast<uint2*>(&qtf[a1]) =
                        make_uint2(to_tf32(0.125f * v10), to_tf32(0.125f * v11));
                } else if (region == 1) {
                    *reinterpret_cast<uint2*>(&ktf[a0]) =
                        make_uint2(to_tf32(v00), to_tf32(v01));
                    *reinterpret_cast<uint2*>(&ktf[a1]) =
                        make_uint2(to_tf32(v10), to_tf32(v11));
                } else {
                    uint32_t h0, l0, h1, l1;
                    split_tf32(v00, h0, l0);
                    split_tf32(v01, h1, l1);
                    *reinterpret_cast<uint2*>(&vhi[a0]) = make_uint2(h0, h1);
                    *reinterpret_cast<uint2*>(&vlo[a0]) = make_uint2(l0, l1);
                    split_tf32(v10, h0, l0);
                    split_tf32(v11, h1, l1);
                    *reinterpret_cast<uint2*>(&vhi[a1]) = make_uint2(h0, h1);
                    *reinterpret_cast<uint2*>(&vlo[a1]) = make_uint2(l0, l1);
                }
            }
        }
    }
}

// ============================ mask handling =================================
__global__ void mask_detect_kernel(const unsigned int* __restrict__ mask) {
    unsigned int w0 = mask[0];
    int esize;
    if (w0 == 0x01010101u) esize = 1;
    else if (w0 == 1u || w0 == 0x3f800000u) esize = 4;
    else if ((w0 & 0xFFu) != 0u || (w0 >> 8) == 0u) esize = 1;
    else esize = 4;
    g_mask_esize = esize;
    g_mask_allones = 1;
}

__global__ void mask_scan_kernel(const void* __restrict__ mask) {
    const int esize = g_mask_esize;
    bool any_zero = false;
    if (esize == 4) {
        const unsigned int* m = (const unsigned int*)mask;
        for (long long i = (long long)blockIdx.x * blockDim.x + threadIdx.x;
             i < MASKN; i += (long long)gridDim.x * blockDim.x)
            if (m[i] == 0u) { any_zero = true; break; }
    } else {
        const unsigned int* m = (const unsigned int*)mask;
        for (long long i = (long long)blockIdx.x * blockDim.x + threadIdx.x;
             i < MASKN / 4; i += (long long)gridDim.x * blockDim.x) {
            unsigned int w = m[i];
            if ((w & 0xFFu) == 0 || (w & 0xFF00u) == 0 ||
                (w & 0xFF0000u) == 0 || (w & 0xFF000000u) == 0) { any_zero = true; break; }
        }
    }
    if (any_zero) g_mask_allones = 0;
}

// ============================ attention via mma.sync ========================
// 256 threads (8 warps), 128 query rows, chunks of 64 keys, double-buffered
// cp.async K/V. QK single tf32 (scale folded). PV 2-term: Phi*(Vhi+Vlo).
// Output: single tf32 (att_lo dropped).
#define AT2_PHI 27136
#define AT2_BYTES (35840 * 4)   // 143360

__global__ void __launch_bounds__(256)
attn_mma_kernel(const uint32_t* __restrict__ qtf, const uint32_t* __restrict__ ktf,
                const uint32_t* __restrict__ vhi, const uint32_t* __restrict__ vlo,
                const void* __restrict__ mask,
                uint32_t* __restrict__ atttf) {
    extern __shared__ float sh[];
    const uint32_t sb = (uint32_t)__cvta_generic_to_shared(sh);
    uint32_t* Phi = reinterpret_cast<uint32_t*>(sh + AT2_PHI);
    uint32_t* Qstage = Phi;

    const int tid = threadIdx.x;
    const int wid = tid >> 5;
    const int lane = tid & 31;
    const int g  = lane >> 2;
    const int tq = lane & 3;
    const int wq = wid * 16;
    const int q0 = blockIdx.x * 128;
    const int h  = blockIdx.y;
    const int b  = blockIdx.z;

    const int mask_allones = g_mask_allones;
    const int mask_esize   = g_mask_esize;
    const size_t rbase = (size_t)b * SEQ;
    const int hoff = h * DIM;
    const size_t mask_base = (size_t)b * SEQ * SEQ;

    auto issue_kv = [&](int s, int kt) {
        const int k0 = kt * 64;
#pragma unroll
        for (int p = 0; p < 4; p++) {
            int idx = p * 256 + tid;
            int key = idx >> 4, c = idx & 15;
            const uint32_t* src = ktf + (rbase + k0 + key) * EMB + hoff + c * 4;
            uint32_t dst = sb + (s * 13568 + key * 68 + c * 4) * 4;
            CP16(dst, src);
        }
#pragma unroll
        for (int p = 0; p < 8; p++) {
            int idx = p * 256 + tid;
            int mat = idx >> 10;
            int within = idx & 1023;
            int key = within >> 4, c = within & 15;
            const uint32_t* src = (mat == 0 ? vhi : vlo) +
                                  (rbase + k0 + key) * EMB + hoff + c * 4;
            uint32_t dst = sb + (s * 13568 + 4352 + mat * 4608 + key * 72 + c * 4) * 4;
            CP16(dst, src);
        }
        CP_COMMIT();
    };

    // ---- stage Q + first K/V ----
#pragma unroll
    for (int p = 0; p < 8; p++) {
        int idx = p * 256 + tid;
        int r = idx >> 4, c = idx & 15;
        const uint32_t* src = qtf + (rbase + q0 + r) * EMB + hoff + c * 4;
        uint32_t dst = sb + (AT2_PHI + r * 68 + c * 4) * 4;
        CP16(dst, src);
    }
    CP_COMMIT();
    issue_kv(0, 0);
    CP_WAIT1();
    __syncthreads();

    uint32_t qf[8][4];
#pragma unroll
    for (int kb = 0; kb < 8; kb++) {
        const int r0 = (wq + g) * 68 + kb * 8 + tq;
        const int r1 = (wq + g + 8) * 68 + kb * 8 + tq;
        qf[kb][0] = Qstage[r0];
        qf[kb][1] = Qstage[r1];
        qf[kb][2] = Qstage[r0 + 4];
        qf[kb][3] = Qstage[r1 + 4];
    }
    __syncthreads();

    float o[8][4];
#pragma unroll
    for (int nt = 0; nt < 8; nt++)
#pragma unroll
        for (int r = 0; r < 4; r++) o[nt][r] = 0.0f;
    float m0r = -1e30f, m1r = -1e30f, l0r = 0.0f, l1r = 0.0f;

    const int nkt = SEQ / 64;
    for (int kt = 0; kt < nkt; kt++) {
        const int s = kt & 1;
        const int k0 = kt * 64;
        if (kt + 1 < nkt) {
            issue_kv(1 - s, kt + 1);
            CP_WAIT1();
        } else {
            CP_WAIT0();
        }
        __syncthreads();

        const uint32_t* Ktf_s = reinterpret_cast<const uint32_t*>(sh + s * 13568);
        const uint32_t* Vhi_s = reinterpret_cast<const uint32_t*>(sh + s * 13568 + 4352);
        const uint32_t* Vlo_s = reinterpret_cast<const uint32_t*>(sh + s * 13568 + 8960);

        float s4[8][4];
#pragma unroll
        for (int nt = 0; nt < 8; nt++)
#pragma unroll
            for (int r = 0; r < 4; r++) s4[nt][r] = 0.0f;
#pragma unroll
        for (int kb = 0; kb < 8; kb++) {
#pragma unroll
            for (int nt = 0; nt < 8; nt++) {
                uint32_t b0 = Ktf_s[(nt * 8 + g) * 68 + kb * 8 + tq];
                uint32_t b1 = Ktf_s[(nt * 8 + g) * 68 + kb * 8 + tq + 4];
                mma_tf32(s4[nt], qf[kb][0], qf[kb][1], qf[kb][2], qf[kb][3], b0, b1);
            }
        }

        if (!mask_allones) {
            const int qg0 = q0 + wq + g, qg1 = qg0 + 8;
#pragma unroll
            for (int nt = 0; nt < 8; nt++) {
                int kcol = k0 + nt * 8 + 2 * tq;
                bool mk[4];
                if (mask_esize == 4) {
                    const unsigned int* mm = (const unsigned int*)mask;
                    mk[0] = mm[mask_base + (size_t)qg0 * SEQ + kcol] != 0;
                    mk[1] = mm[mask_base + (size_t)qg0 * SEQ + kcol + 1] != 0;
                    mk[2] = mm[mask_base + (size_t)qg1 * SEQ + kcol] != 0;
                    mk[3] = mm[mask_base + (size_t)qg1 * SEQ + kcol + 1] != 0;
                } else {
                    const unsigned char* mm = (const unsigned char*)mask;
                    mk[0] = mm[mask_base + (size_t)qg0 * SEQ + kcol] != 0;
                    mk[1] = mm[mask_base + (size_t)qg0 * SEQ + kcol + 1] != 0;
                    mk[2] = mm[mask_base + (size_t)qg1 * SEQ + kcol] != 0;
                    mk[3] = mm[mask_base + (size_t)qg1 * SEQ + kcol + 1] != 0;
                }
#pragma unroll
                for (int r = 0; r < 4; r++)
                    if (!mk[r]) s4[nt][r] = -1e9f;
            }
        }

        float mt0 = -1e30f, mt1 = -1e30f;
#pragma unroll
        for (int nt = 0; nt < 8; nt++) {
            mt0 = fmaxf(mt0, fmaxf(s4[nt][0], s4[nt][1]));
            mt1 = fmaxf(mt1, fmaxf(s4[nt][2], s4[nt][3]));
        }
        mt0 = fmaxf(mt0, __shfl_xor_sync(0xffffffff, mt0, 1));
        mt0 = fmaxf(mt0, __shfl_xor_sync(0xffffffff, mt0, 2));
        mt1 = fmaxf(mt1, __shfl_xor_sync(0xffffffff, mt1, 1));
        mt1 = fmaxf(mt1, __shfl_xor_sync(0xffffffff, mt1, 2));

        float mn0 = fmaxf(m0r, mt0), mn1 = fmaxf(m1r, mt1);
        float a0 = __expf(m0r - mn0), a1 = __expf(m1r - mn1);
        m0r = mn0; m1r = mn1;

        float lt0 = 0.0f, lt1 = 0.0f;
#pragma unroll
        for (int nt = 0; nt < 8; nt++) {
            s4[nt][0] = __expf(s4[nt][0] - mn0);
            s4[nt][1] = __expf(s4[nt][1] - mn0);
            s4[nt][2] = __expf(s4[nt][2] - mn1);
            s4[nt][3] = __expf(s4[nt][3] - mn1);
            lt0 += s4[nt][0] + s4[nt][1];
            lt1 += s4[nt][2] + s4[nt][3];
        }
        lt0 += __shfl_xor_sync(0xffffffff, lt0, 1);
        lt0 += __shfl_xor_sync(0xffffffff, lt0, 2);
        lt1 += __shfl_xor_sync(0xffffffff, lt1, 1);
        lt1 += __shfl_xor_sync(0xffffffff, lt1, 2);
        l0r = l0r * a0 + lt0;
        l1r = l1r * a1 + lt1;

#pragma unroll
        for (int nt = 0; nt < 8; nt++) {
            o[nt][0] *= a0; o[nt][1] *= a0;
            o[nt][2] *= a1; o[nt][3] *= a1;
        }

#pragma unroll
        for (int nt = 0; nt < 8; nt++) {
            const int p0 = (wq + g) * 68 + nt * 8 + 2 * tq;
            const int p1 = (wq + g + 8) * 68 + nt * 8 + 2 * tq;
            *reinterpret_cast<uint2*>(&Phi[p0]) =
                make_uint2(to_tf32(s4[nt][0]), to_tf32(s4[nt][1]));
            *reinterpret_cast<uint2*>(&Phi[p1]) =
                make_uint2(to_tf32(s4[nt][2]), to_tf32(s4[nt][3]));
        }
        __syncwarp();

#pragma unroll
        for (int kb = 0; kb < 8; kb++) {
            const int pr0 = (wq + g) * 68 + kb * 8 + tq;
            const int pr1 = (wq + g + 8) * 68 + kb * 8 + tq;
            uint32_t ph[4];
            ph[0] = Phi[pr0]; ph[1] = Phi[pr1];
            ph[2] = Phi[pr0 + 4]; ph[3] = Phi[pr1 + 4];
            const int vr0 = (kb * 8 + tq) * 72;
            const int vr1 = (kb * 8 + tq + 4) * 72;
#pragma unroll
            for (int nt = 0; nt < 8; nt++) {
                const int d = nt * 8 + g;
                uint32_t vh0 = Vhi_s[vr0 + d], vh1 = Vhi_s[vr1 + d];
                uint32_t vl0 = Vlo_s[vr0 + d], vl1 = Vlo_s[vr1 + d];
                mma_tf32(o[nt], ph[0], ph[1], ph[2], ph[3], vh0, vh1);
                mma_tf32(o[nt], ph[0], ph[1], ph[2], ph[3], vl0, vl1);
            }
        }
        __syncthreads();
    }

    // ---- write output as single tf32 ----
    const float inv0 = 1.0f / l0r, inv1 = 1.0f / l1r;
    const size_t row0 = rbase + q0 + wq + g;
    const size_t row1 = row0 + 8;
#pragma unroll
    for (int nt = 0; nt < 8; nt++) {
        const int col = hoff + nt * 8 + 2 * tq;
        *reinterpret_cast<uint2*>(&atttf[row0 * EMB + col]) =
            make_uint2(to_tf32(o[nt][0] * inv0), to_tf32(o[nt][1] * inv0));
        *reinterpret_cast<uint2*>(&atttf[row1 * EMB + col]) =
            make_uint2(to_tf32(o[nt][2] * inv1), to_tf32(o[nt][3] * inv1));
    }
}

// ============================================================================
extern "C" void kernel_launch(void* const* d_in, const int* in_sizes, int n_in,
                              void* d_out, int out_size) {
    const float* x      = (const float*)d_in[0];
    const void*  mask   = d_in[1];
    const float* W_pre  = (const float*)d_in[2];
    const float* b_pre  = (const float*)d_in[3];
    const float* W_proj = (const float*)d_in[4];
    const float* b_proj = (const float*)d_in[5];
    float* out = (float*)d_out;

    uint32_t *qtf, *ktf, *vhi, *vlo, *xtf, *atttf;
    float *wph, *wpl, *wjh, *wjl;
    cudaGetSymbolAddress((void**)&qtf, g_qtf);
    cudaGetSymbolAddress((void**)&ktf, g_ktf);
    cudaGetSymbolAddress((void**)&vhi, g_vhi);
    cudaGetSymbolAddress((void**)&vlo, g_vlo);
    cudaGetSymbolAddress((void**)&xtf, g_xtf);
    cudaGetSymbolAddress((void**)&atttf, g_atttf);
    cudaGetSymbolAddress((void**)&wph, g_wpre_hi);
    cudaGetSymbolAddress((void**)&wpl, g_wpre_lo);
    cudaGetSymbolAddress((void**)&wjh, g_wproj_hi);
    cudaGetSymbolAddress((void**)&wjl, g_wproj_lo);

    mask_detect_kernel<<<1, 1>>>((const unsigned int*)mask);
    mask_scan_kernel<<<256, 256>>>(mask);

    cvt_kernel<<<512, 256>>>((const float4*)x, (uint4*)xtf, ROWS * EMB / 4);
    split_kernel<<<1024, 256>>>((const float4*)W_pre, (uint4*)wph, (uint4*)wpl,
                                EMB * QKVN / 4);
    split_kernel<<<512, 256>>>((const float4*)W_proj, (uint4*)wjh, (uint4*)wjl,
                               EMB * EMB / 4);

    cudaFuncSetAttribute(gemm_split_kernel<0>,
                         cudaFuncAttributeMaxDynamicSharedMemorySize, G3_BYTES);
    cudaFuncSetAttribute(gemm_split_kernel<1>,
                         cudaFuncAttributeMaxDynamicSharedMemorySize, G3_BYTES);
    cudaFuncSetAttribute(attn_mma_kernel,
                         cudaFuncAttributeMaxDynamicSharedMemorySize, AT2_BYTES);

    // 1) QKV GEMM -> attention-ready operands
    {
        dim3 grid(QKVN / 64, ROWS / 128);
        gemm_split_kernel<1><<<grid, 256, G3_BYTES>>>(
            xtf, wph, wpl, b_pre, nullptr, qtf, ktf, vhi, vlo,
            ROWS, QKVN, EMB);
    }
    // 2) Attention
    {
        dim3 grid(SEQ / 128, HEADS, BATCH);
        attn_mma_kernel<<<grid, 256, AT2_BYTES>>>(qtf, ktf, vhi, vlo, mask, atttf);
    }
    // 3) Projection GEMM
    {
        dim3 grid(EMB / 64, ROWS / 128);
        gemm_split_kernel<0><<<grid, 256, G3_BYTES>>>(
            atttf, wjh, wjl, b_proj, out, nullptr, nullptr, nullptr, nullptr,
            ROWS, EMB, EMB);
    }
}

// round 11
// speedup vs baseline: 3.0391x; 1.3932x over previous
#include <cuda_runtime.h>
#include <math.h>
#include <stdint.h>

#define HEADS 12
#define DIM   64
#define BATCH 2
#define SEQ   2048
#define EMB   768
#define QKVN  (3 * HEADS * DIM)   // 2304
#define ROWS  (BATCH * SEQ)       // 4096
#define MASKN (BATCH * SEQ * SEQ) // 8388608

// ----- device scratch (all tf32-as-uint32) -----
__device__ uint32_t g_qtf[ROWS * EMB];     // Q pre-scaled (1/8)
__device__ uint32_t g_ktf[ROWS * EMB];     // K
__device__ uint32_t g_vtf[ROWS * EMB];     // V
__device__ uint32_t g_xtf[ROWS * EMB];     // x
__device__ uint32_t g_atttf[ROWS * EMB];   // attention out
__device__ uint32_t g_wpretf[EMB * QKVN];  // W_pre
__device__ uint32_t g_wprojtf[EMB * EMB];  // W_proj
__device__ int   g_mask_esize;
__device__ int   g_mask_allones;

// ============================ helpers =======================================
__device__ __forceinline__ uint32_t to_tf32(float x) {
    uint32_t r;
    asm("cvt.rna.tf32.f32 %0, %1;" : "=r"(r) : "f"(x));
    return r;
}
__device__ __forceinline__ void mma_tf32(float c[4],
                                         uint32_t a0, uint32_t a1, uint32_t a2, uint32_t a3,
                                         uint32_t b0, uint32_t b1) {
    asm volatile(
        "mma.sync.aligned.m16n8k8.row.col.f32.tf32.tf32.f32 "
        "{%0,%1,%2,%3}, {%4,%5,%6,%7}, {%8,%9}, {%0,%1,%2,%3};"
        : "+f"(c[0]), "+f"(c[1]), "+f"(c[2]), "+f"(c[3])
        : "r"(a0), "r"(a1), "r"(a2), "r"(a3), "r"(b0), "r"(b1));
}
#define CP16(dst, src) \
    asm volatile("cp.async.ca.shared.global [%0], [%1], 16;" :: "r"(dst), "l"(src) : "memory")
#define CP_COMMIT() asm volatile("cp.async.commit_group;" ::: "memory")
#define CP_WAIT1() asm volatile("cp.async.wait_group 1;" ::: "memory")
#define CP_WAIT0() asm volatile("cp.async.wait_group 0;" ::: "memory")

// ============================ prepass: fp32 -> tf32 =========================
__global__ void cvt_kernel(const float4* __restrict__ in,
                           uint4* __restrict__ out, int n4) {
    for (int i = blockIdx.x * blockDim.x + threadIdx.x; i < n4;
         i += gridDim.x * blockDim.x) {
        float4 v = in[i];
        out[i] = make_uint4(to_tf32(v.x), to_tf32(v.y), to_tf32(v.z), to_tf32(v.w));
    }
}

// ============================ GEMM (single tf32 both operands) ==============
// C = A*B + bias. MODE 0: fp32 out. MODE 1: QKV epilogue -> qtf/ktf/vtf.
// smem bytes: sA stage s @ s*18432 ([128][36] u32); sB @ 36864 + s*9216
// ([32][72] u32). Total 55296.
#define G4_BYTES 55296

template <int MODE>
__global__ void __launch_bounds__(256)
gemm_tf_kernel(const uint32_t* __restrict__ Atf, const uint32_t* __restrict__ Btf,
               const float* __restrict__ bias, float* __restrict__ C,
               uint32_t* __restrict__ qtf, uint32_t* __restrict__ ktf,
               uint32_t* __restrict__ vtf,
               int M, int N, int K) {
    extern __shared__ char smraw[];
    uint32_t* usm = reinterpret_cast<uint32_t*>(smraw);
    const uint32_t sb = (uint32_t)__cvta_generic_to_shared(smraw);

    const int tid = threadIdx.x;
    const int wid = tid >> 5;
    const int lane = tid & 31;
    const int g  = lane >> 2;
    const int tq = lane & 3;
    const int wm = wid >> 1;
    const int wn = wid & 1;
    const int m0 = blockIdx.y * 128;
    const int n0 = blockIdx.x * 64;
    const int nkt = K / 32;

    float acc[2][4][4];
#pragma unroll
    for (int i = 0; i < 2; i++)
#pragma unroll
        for (int j = 0; j < 4; j++)
#pragma unroll
            for (int r = 0; r < 4; r++) acc[i][j][r] = 0.0f;

    auto issue_tile = [&](int s, int kt) {
#pragma unroll
        for (int p = 0; p < 4; p++) {          // A: 128x32 = 1024 chunks
            int idx = p * 256 + tid;
            int r = idx >> 3, ch = idx & 7;
            const uint32_t* src = Atf + (size_t)(m0 + r) * K + kt * 32 + ch * 4;
            uint32_t dst = sb + s * 18432 + (r * 36 + ch * 4) * 4;
            CP16(dst, src);
        }
#pragma unroll
        for (int p = 0; p < 2; p++) {          // B: 32x64 = 512 chunks
            int idx = p * 256 + tid;
            int r = idx >> 4, ch = idx & 15;
            const uint32_t* src = Btf + (size_t)(kt * 32 + r) * N + n0 + ch * 4;
            uint32_t dst = sb + 36864 + s * 9216 + (r * 72 + ch * 4) * 4;
            CP16(dst, src);
        }
        CP_COMMIT();
    };

    issue_tile(0, 0);

    for (int kt = 0; kt < nkt; kt++) {
        const int s = kt & 1;
        if (kt + 1 < nkt) {
            issue_tile(1 - s, kt + 1);
            CP_WAIT1();
        } else {
            CP_WAIT0();
        }
        __syncthreads();

        const uint32_t* sA = usm + s * 4608;
        const uint32_t* sB = usm + 9216 + s * 2304;

#pragma unroll
        for (int ks = 0; ks < 4; ks++) {
            const int kb = ks * 8;
            uint32_t af[2][4];
#pragma unroll
            for (int i = 0; i < 2; i++) {
                const int rbase = (wm * 32 + i * 16 + g) * 36 + kb + tq;
                af[i][0] = sA[rbase];
                af[i][1] = sA[rbase + 8 * 36];
                af[i][2] = sA[rbase + 4];
                af[i][3] = sA[rbase + 8 * 36 + 4];
            }
            uint32_t bf[4][2];
#pragma unroll
            for (int j = 0; j < 4; j++) {
                const int col = wn * 32 + j * 8 + g;
                bf[j][0] = sB[(kb + tq) * 72 + col];
                bf[j][1] = sB[(kb + tq + 4) * 72 + col];
            }
#pragma unroll
            for (int i = 0; i < 2; i++)
#pragma unroll
                for (int j = 0; j < 4; j++)
                    mma_tf32(acc[i][j], af[i][0], af[i][1], af[i][2], af[i][3],
                             bf[j][0], bf[j][1]);
        }
        __syncthreads();
    }

    // ---- epilogue ----
    const int region = n0 / EMB;           // block-uniform (MODE 1)
#pragma unroll
    for (int i = 0; i < 2; i++) {
        const int row = m0 + wm * 32 + i * 16 + g;
#pragma unroll
        for (int j = 0; j < 4; j++) {
            const int col = n0 + wn * 32 + j * 8 + 2 * tq;
            const float b0 = bias[col], b1 = bias[col + 1];
            float v00 = acc[i][j][0] + b0, v01 = acc[i][j][1] + b1;
            float v10 = acc[i][j][2] + b0, v11 = acc[i][j][3] + b1;
            if (MODE == 0) {
                *reinterpret_cast<float2*>(&C[(size_t)row * N + col]) =
                    make_float2(v00, v01);
                *reinterpret_cast<float2*>(&C[(size_t)(row + 8) * N + col]) =
                    make_float2(v10, v11);
            } else {
                const int cemb = col - region * EMB;
                const size_t a0 = (size_t)row * EMB + cemb;
                const size_t a1 = (size_t)(row + 8) * EMB + cemb;
                uint32_t* dst = (region == 0) ? qtf : (region == 1) ? ktf : vtf;
                const float sc = (region == 0) ? 0.125f : 1.0f;
                *reinterpret_cast<uint2*>(&dst[a0]) =
                    make_uint2(to_tf32(sc * v00), to_tf32(sc * v01));
                *reinterpret_cast<uint2*>(&dst[a1]) =
                    make_uint2(to_tf32(sc * v10), to_tf32(sc * v11));
            }
        }
    }
}

// ============================ mask handling =================================
__global__ void mask_detect_kernel(const unsigned int* __restrict__ mask) {
    unsigned int w0 = mask[0];
    int esize;
    if (w0 == 0x01010101u) esize = 1;
    else if (w0 == 1u || w0 == 0x3f800000u) esize = 4;
    else if ((w0 & 0xFFu) != 0u || (w0 >> 8) == 0u) esize = 1;
    else esize = 4;
    g_mask_esize = esize;
    g_mask_allones = 1;
}

__global__ void mask_scan_kernel(const void* __restrict__ mask) {
    const int esize = g_mask_esize;
    bool any_zero = false;
    if (esize == 4) {
        const unsigned int* m = (const unsigned int*)mask;
        for (long long i = (long long)blockIdx.x * blockDim.x + threadIdx.x;
             i < MASKN; i += (long long)gridDim.x * blockDim.x)
            if (m[i] == 0u) { any_zero = true; break; }
    } else {
        const unsigned int* m = (const unsigned int*)mask;
        for (long long i = (long long)blockIdx.x * blockDim.x + threadIdx.x;
             i < MASKN / 4; i += (long long)gridDim.x * blockDim.x) {
            unsigned int w = m[i];
            if ((w & 0xFFu) == 0 || (w & 0xFF00u) == 0 ||
                (w & 0xFF0000u) == 0 || (w & 0xFF000000u) == 0) { any_zero = true; break; }
        }
    }
    if (any_zero) g_mask_allones = 0;
}

// ============================ attention via mma.sync ========================
// 256 threads (8 warps), 128 query rows, chunks of 64 keys, double-buffered
// cp.async K/V. All operands single tf32. QK scale folded into Q.
// smem floats: stage s: K @ s*8960 [64][68]; V @ s*8960+4352 [64][72].
// Phi @ 17920 [128][68]. Total 26624 fl = 106496 B.
#define AT3_PHI 17920
#define AT3_BYTES (26624 * 4)

__global__ void __launch_bounds__(256)
attn_mma_kernel(const uint32_t* __restrict__ qtf, const uint32_t* __restrict__ ktf,
                const uint32_t* __restrict__ vtf,
                const void* __restrict__ mask,
                uint32_t* __restrict__ atttf) {
    extern __shared__ float sh[];
    const uint32_t sb = (uint32_t)__cvta_generic_to_shared(sh);
    uint32_t* Phi = reinterpret_cast<uint32_t*>(sh + AT3_PHI);
    uint32_t* Qstage = Phi;

    const int tid = threadIdx.x;
    const int wid = tid >> 5;
    const int lane = tid & 31;
    const int g  = lane >> 2;
    const int tq = lane & 3;
    const int wq = wid * 16;
    const int q0 = blockIdx.x * 128;
    const int h  = blockIdx.y;
    const int b  = blockIdx.z;

    const int mask_allones = g_mask_allones;
    const int mask_esize   = g_mask_esize;
    const size_t rbase = (size_t)b * SEQ;
    const int hoff = h * DIM;
    const size_t mask_base = (size_t)b * SEQ * SEQ;

    auto issue_kv = [&](int s, int kt) {
        const int k0 = kt * 64;
#pragma unroll
        for (int p = 0; p < 4; p++) {          // K: 1024 chunks
            int idx = p * 256 + tid;
            int key = idx >> 4, c = idx & 15;
            const uint32_t* src = ktf + (rbase + k0 + key) * EMB + hoff + c * 4;
            uint32_t dst = sb + (s * 8960 + key * 68 + c * 4) * 4;
            CP16(dst, src);
        }
#pragma unroll
        for (int p = 0; p < 4; p++) {          // V: 1024 chunks
            int idx = p * 256 + tid;
            int key = idx >> 4, c = idx & 15;
            const uint32_t* src = vtf + (rbase + k0 + key) * EMB + hoff + c * 4;
            uint32_t dst = sb + (s * 8960 + 4352 + key * 72 + c * 4) * 4;
            CP16(dst, src);
        }
        CP_COMMIT();
    };

    // ---- stage Q + first K/V ----
#pragma unroll
    for (int p = 0; p < 8; p++) {
        int idx = p * 256 + tid;
        int r = idx >> 4, c = idx & 15;
        const uint32_t* src = qtf + (rbase + q0 + r) * EMB + hoff + c * 4;
        uint32_t dst = sb + (AT3_PHI + r * 68 + c * 4) * 4;
        CP16(dst, src);
    }
    CP_COMMIT();
    issue_kv(0, 0);
    CP_WAIT1();
    __syncthreads();

    uint32_t qf[8][4];
#pragma unroll
    for (int kb = 0; kb < 8; kb++) {
        const int r0 = (wq + g) * 68 + kb * 8 + tq;
        const int r1 = (wq + g + 8) * 68 + kb * 8 + tq;
        qf[kb][0] = Qstage[r0];
        qf[kb][1] = Qstage[r1];
        qf[kb][2] = Qstage[r0 + 4];
        qf[kb][3] = Qstage[r1 + 4];
    }
    __syncthreads();

    float o[8][4];
#pragma unroll
    for (int nt = 0; nt < 8; nt++)
#pragma unroll
        for (int r = 0; r < 4; r++) o[nt][r] = 0.0f;
    float m0r = -1e30f, m1r = -1e30f, l0r = 0.0f, l1r = 0.0f;

    const int nkt = SEQ / 64;
    for (int kt = 0; kt < nkt; kt++) {
        const int s = kt & 1;
        const int k0 = kt * 64;
        if (kt + 1 < nkt) {
            issue_kv(1 - s, kt + 1);
            CP_WAIT1();
        } else {
            CP_WAIT0();
        }
        __syncthreads();

        const uint32_t* Ktf_s = reinterpret_cast<const uint32_t*>(sh + s * 8960);
        const uint32_t* Vtf_s = reinterpret_cast<const uint32_t*>(sh + s * 8960 + 4352);

        // ---- S = (Q/8) K^T ----
        float s4[8][4];
#pragma unroll
        for (int nt = 0; nt < 8; nt++)
#pragma unroll
            for (int r = 0; r < 4; r++) s4[nt][r] = 0.0f;
#pragma unroll
        for (int kb = 0; kb < 8; kb++) {
#pragma unroll
            for (int nt = 0; nt < 8; nt++) {
                uint32_t b0 = Ktf_s[(nt * 8 + g) * 68 + kb * 8 + tq];
                uint32_t b1 = Ktf_s[(nt * 8 + g) * 68 + kb * 8 + tq + 4];
                mma_tf32(s4[nt], qf[kb][0], qf[kb][1], qf[kb][2], qf[kb][3], b0, b1);
            }
        }

        // ---- mask ----
        if (!mask_allones) {
            const int qg0 = q0 + wq + g, qg1 = qg0 + 8;
#pragma unroll
            for (int nt = 0; nt < 8; nt++) {
                int kcol = k0 + nt * 8 + 2 * tq;
                bool mk[4];
                if (mask_esize == 4) {
                    const unsigned int* mm = (const unsigned int*)mask;
                    mk[0] = mm[mask_base + (size_t)qg0 * SEQ + kcol] != 0;
                    mk[1] = mm[mask_base + (size_t)qg0 * SEQ + kcol + 1] != 0;
                    mk[2] = mm[mask_base + (size_t)qg1 * SEQ + kcol] != 0;
                    mk[3] = mm[mask_base + (size_t)qg1 * SEQ + kcol + 1] != 0;
                } else {
                    const unsigned char* mm = (const unsigned char*)mask;
                    mk[0] = mm[mask_base + (size_t)qg0 * SEQ + kcol] != 0;
                    mk[1] = mm[mask_base + (size_t)qg0 * SEQ + kcol + 1] != 0;
                    mk[2] = mm[mask_base + (size_t)qg1 * SEQ + kcol] != 0;
                    mk[3] = mm[mask_base + (size_t)qg1 * SEQ + kcol + 1] != 0;
                }
#pragma unroll
                for (int r = 0; r < 4; r++)
                    if (!mk[r]) s4[nt][r] = -1e9f;
            }
        }

        // ---- online softmax ----
        float mt0 = -1e30f, mt1 = -1e30f;
#pragma unroll
        for (int nt = 0; nt < 8; nt++) {
            mt0 = fmaxf(mt0, fmaxf(s4[nt][0], s4[nt][1]));
            mt1 = fmaxf(mt1, fmaxf(s4[nt][2], s4[nt][3]));
        }
        mt0 = fmaxf(mt0, __shfl_xor_sync(0xffffffff, mt0, 1));
        mt0 = fmaxf(mt0, __shfl_xor_sync(0xffffffff, mt0, 2));
        mt1 = fmaxf(mt1, __shfl_xor_sync(0xffffffff, mt1, 1));
        mt1 = fmaxf(mt1, __shfl_xor_sync(0xffffffff, mt1, 2));

        float mn0 = fmaxf(m0r, mt0), mn1 = fmaxf(m1r, mt1);
        float a0 = __expf(m0r - mn0), a1 = __expf(m1r - mn1);
        m0r = mn0; m1r = mn1;

        float lt0 = 0.0f, lt1 = 0.0f;
#pragma unroll
        for (int nt = 0; nt < 8; nt++) {
            s4[nt][0] = __expf(s4[nt][0] - mn0);
            s4[nt][1] = __expf(s4[nt][1] - mn0);
            s4[nt][2] = __expf(s4[nt][2] - mn1);
            s4[nt][3] = __expf(s4[nt][3] - mn1);
            lt0 += s4[nt][0] + s4[nt][1];
            lt1 += s4[nt][2] + s4[nt][3];
        }
        lt0 += __shfl_xor_sync(0xffffffff, lt0, 1);
        lt0 += __shfl_xor_sync(0xffffffff, lt0, 2);
        lt1 += __shfl_xor_sync(0xffffffff, lt1, 1);
        lt1 += __shfl_xor_sync(0xffffffff, lt1, 2);
        l0r = l0r * a0 + lt0;
        l1r = l1r * a1 + lt1;

#pragma unroll
        for (int nt = 0; nt < 8; nt++) {
            o[nt][0] *= a0; o[nt][1] *= a0;
            o[nt][2] *= a1; o[nt][3] *= a1;
        }

        // ---- P -> tf32, store (warp-local rows) ----
#pragma unroll
        for (int nt = 0; nt < 8; nt++) {
            const int p0 = (wq + g) * 68 + nt * 8 + 2 * tq;
            const int p1 = (wq + g + 8) * 68 + nt * 8 + 2 * tq;
            *reinterpret_cast<uint2*>(&Phi[p0]) =
                make_uint2(to_tf32(s4[nt][0]), to_tf32(s4[nt][1]));
            *reinterpret_cast<uint2*>(&Phi[p1]) =
                make_uint2(to_tf32(s4[nt][2]), to_tf32(s4[nt][3]));
        }
        __syncwarp();

        // ---- O += P @ V (single term) ----
#pragma unroll
        for (int kb = 0; kb < 8; kb++) {
            const int pr0 = (wq + g) * 68 + kb * 8 + tq;
            const int pr1 = (wq + g + 8) * 68 + kb * 8 + tq;
            uint32_t ph[4];
            ph[0] = Phi[pr0]; ph[1] = Phi[pr1];
            ph[2] = Phi[pr0 + 4]; ph[3] = Phi[pr1 + 4];
            const int vr0 = (kb * 8 + tq) * 72;
            const int vr1 = (kb * 8 + tq + 4) * 72;
#pragma unroll
            for (int nt = 0; nt < 8; nt++) {
                const int d = nt * 8 + g;
                mma_tf32(o[nt], ph[0], ph[1], ph[2], ph[3],
                         Vtf_s[vr0 + d], Vtf_s[vr1 + d]);
            }
        }
        __syncthreads();
    }

    // ---- write output as single tf32 ----
    const float inv0 = 1.0f / l0r, inv1 = 1.0f / l1r;
    const size_t row0 = rbase + q0 + wq + g;
    const size_t row1 = row0 + 8;
#pragma unroll
    for (int nt = 0; nt < 8; nt++) {
        const int col = hoff + nt * 8 + 2 * tq;
        *reinterpret_cast<uint2*>(&atttf[row0 * EMB + col]) =
            make_uint2(to_tf32(o[nt][0] * inv0), to_tf32(o[nt][1] * inv0));
        *reinterpret_cast<uint2*>(&atttf[row1 * EMB + col]) =
            make_uint2(to_tf32(o[nt][2] * inv1), to_tf32(o[nt][3] * inv1));
    }
}

// ============================================================================
extern "C" void kernel_launch(void* const* d_in, const int* in_sizes, int n_in,
                              void* d_out, int out_size) {
    const float* x      = (const float*)d_in[0];
    const void*  mask   = d_in[1];
    const float* W_pre  = (const float*)d_in[2];
    const float* b_pre  = (const float*)d_in[3];
    const float* W_proj = (const float*)d_in[4];
    const float* b_proj = (const float*)d_in[5];
    float* out = (float*)d_out;

    uint32_t *qtf, *ktf, *vtf, *xtf, *atttf, *wpretf, *wprojtf;
    cudaGetSymbolAddress((void**)&qtf, g_qtf);
    cudaGetSymbolAddress((void**)&ktf, g_ktf);
    cudaGetSymbolAddress((void**)&vtf, g_vtf);
    cudaGetSymbolAddress((void**)&xtf, g_xtf);
    cudaGetSymbolAddress((void**)&atttf, g_atttf);
    cudaGetSymbolAddress((void**)&wpretf, g_wpretf);
    cudaGetSymbolAddress((void**)&wprojtf, g_wprojtf);

    mask_detect_kernel<<<1, 1>>>((const unsigned int*)mask);
    mask_scan_kernel<<<256, 256>>>(mask);

    cvt_kernel<<<512, 256>>>((const float4*)x, (uint4*)xtf, ROWS * EMB / 4);
    cvt_kernel<<<1024, 256>>>((const float4*)W_pre, (uint4*)wpretf,
                              EMB * QKVN / 4);
    cvt_kernel<<<512, 256>>>((const float4*)W_proj, (uint4*)wprojtf,
                             EMB * EMB / 4);

    cudaFuncSetAttribute(gemm_tf_kernel<0>,
                         cudaFuncAttributeMaxDynamicSharedMemorySize, G4_BYTES);
    cudaFuncSetAttribute(gemm_tf_kernel<1>,
                         cudaFuncAttributeMaxDynamicSharedMemorySize, G4_BYTES);
    cudaFuncSetAttribute(attn_mma_kernel,
                         cudaFuncAttributeMaxDynamicSharedMemorySize, AT3_BYTES);

    // 1) QKV GEMM -> attention-ready operands
    {
        dim3 grid(QKVN / 64, ROWS / 128);
        gemm_tf_kernel<1><<<grid, 256, G4_BYTES>>>(
            xtf, wpretf, b_pre, nullptr, qtf, ktf, vtf, ROWS, QKVN, EMB);
    }
    // 2) Attention
    {
        dim3 grid(SEQ / 128, HEADS, BATCH);
        attn_mma_kernel<<<grid, 256, AT3_BYTES>>>(qtf, ktf, vtf, mask, atttf);
    }
    // 3) Projection GEMM
    {
        dim3 grid(EMB / 64, ROWS / 128);
        gemm_tf_kernel<0><<<grid, 256, G4_BYTES>>>(
            atttf, wprojtf, b_proj, out, nullptr, nullptr, nullptr,
            ROWS, EMB, EMB);
    }
}

// round 12
// speedup vs baseline: 3.6866x; 1.2131x over previous
#include <cuda_runtime.h>
#include <math.h>
#include <stdint.h>

#define HEADS 12
#define DIM   64
#define BATCH 2
#define SEQ   2048
#define EMB   768
#define QKVN  (3 * HEADS * DIM)   // 2304
#define ROWS  (BATCH * SEQ)       // 4096
#define MASKN (BATCH * SEQ * SEQ) // 8388608

// ----- device scratch (all tf32-as-uint32) -----
__device__ uint32_t g_qtf[ROWS * EMB];     // Q pre-scaled (1/8)
__device__ uint32_t g_ktf[ROWS * EMB];     // K
__device__ uint32_t g_vtf[ROWS * EMB];     // V
__device__ uint32_t g_xtf[ROWS * EMB];     // x
__device__ uint32_t g_atttf[ROWS * EMB];   // attention out
__device__ uint32_t g_wpretf[EMB * QKVN];  // W_pre
__device__ uint32_t g_wprojtf[EMB * EMB];  // W_proj
__device__ int   g_mask_esize;
__device__ int   g_mask_allones;

// ============================ helpers =======================================
__device__ __forceinline__ uint32_t to_tf32(float x) {
    uint32_t r;
    asm("cvt.rna.tf32.f32 %0, %1;" : "=r"(r) : "f"(x));
    return r;
}
__device__ __forceinline__ void mma_tf32(float c[4],
                                         uint32_t a0, uint32_t a1, uint32_t a2, uint32_t a3,
                                         uint32_t b0, uint32_t b1) {
    asm volatile(
        "mma.sync.aligned.m16n8k8.row.col.f32.tf32.tf32.f32 "
        "{%0,%1,%2,%3}, {%4,%5,%6,%7}, {%8,%9}, {%0,%1,%2,%3};"
        : "+f"(c[0]), "+f"(c[1]), "+f"(c[2]), "+f"(c[3])
        : "r"(a0), "r"(a1), "r"(a2), "r"(a3), "r"(b0), "r"(b1));
}
#define CP16(dst, src) \
    asm volatile("cp.async.ca.shared.global [%0], [%1], 16;" :: "r"(dst), "l"(src) : "memory")
#define CP_COMMIT() asm volatile("cp.async.commit_group;" ::: "memory")
#define CP_WAIT1() asm volatile("cp.async.wait_group 1;" ::: "memory")
#define CP_WAIT0() asm volatile("cp.async.wait_group 0;" ::: "memory")

// ============================ prepass: fp32 -> tf32 =========================
__global__ void cvt_kernel(const float4* __restrict__ in,
                           uint4* __restrict__ out, int n4) {
    for (int i = blockIdx.x * blockDim.x + threadIdx.x; i < n4;
         i += gridDim.x * blockDim.x) {
        float4 v = in[i];
        out[i] = make_uint4(to_tf32(v.x), to_tf32(v.y), to_tf32(v.z), to_tf32(v.w));
    }
}

// ============================ GEMM (single tf32 both operands) ==============
#define G4_BYTES 55296

template <int MODE>
__global__ void __launch_bounds__(256, 2)
gemm_tf_kernel(const uint32_t* __restrict__ Atf, const uint32_t* __restrict__ Btf,
               const float* __restrict__ bias, float* __restrict__ C,
               uint32_t* __restrict__ qtf, uint32_t* __restrict__ ktf,
               uint32_t* __restrict__ vtf,
               int M, int N, int K) {
    extern __shared__ char smraw[];
    uint32_t* usm = reinterpret_cast<uint32_t*>(smraw);
    const uint32_t sb = (uint32_t)__cvta_generic_to_shared(smraw);

    const int tid = threadIdx.x;
    const int wid = tid >> 5;
    const int lane = tid & 31;
    const int g  = lane >> 2;
    const int tq = lane & 3;
    const int wm = wid >> 1;
    const int wn = wid & 1;
    const int m0 = blockIdx.y * 128;
    const int n0 = blockIdx.x * 64;
    const int nkt = K / 32;

    float acc[2][4][4];
#pragma unroll
    for (int i = 0; i < 2; i++)
#pragma unroll
        for (int j = 0; j < 4; j++)
#pragma unroll
            for (int r = 0; r < 4; r++) acc[i][j][r] = 0.0f;

    auto issue_tile = [&](int s, int kt) {
#pragma unroll
        for (int p = 0; p < 4; p++) {          // A: 128x32
            int idx = p * 256 + tid;
            int r = idx >> 3, ch = idx & 7;
            const uint32_t* src = Atf + (size_t)(m0 + r) * K + kt * 32 + ch * 4;
            uint32_t dst = sb + s * 18432 + (r * 36 + ch * 4) * 4;
            CP16(dst, src);
        }
#pragma unroll
        for (int p = 0; p < 2; p++) {          // B: 32x64
            int idx = p * 256 + tid;
            int r = idx >> 4, ch = idx & 15;
            const uint32_t* src = Btf + (size_t)(kt * 32 + r) * N + n0 + ch * 4;
            uint32_t dst = sb + 36864 + s * 9216 + (r * 72 + ch * 4) * 4;
            CP16(dst, src);
        }
        CP_COMMIT();
    };

    issue_tile(0, 0);

    for (int kt = 0; kt < nkt; kt++) {
        const int s = kt & 1;
        if (kt + 1 < nkt) {
            issue_tile(1 - s, kt + 1);
            CP_WAIT1();
        } else {
            CP_WAIT0();
        }
        __syncthreads();

        const uint32_t* sA = usm + s * 4608;
        const uint32_t* sB = usm + 9216 + s * 2304;

#pragma unroll
        for (int ks = 0; ks < 4; ks++) {
            const int kb = ks * 8;
            uint32_t af[2][4];
#pragma unroll
            for (int i = 0; i < 2; i++) {
                const int rbase = (wm * 32 + i * 16 + g) * 36 + kb + tq;
                af[i][0] = sA[rbase];
                af[i][1] = sA[rbase + 8 * 36];
                af[i][2] = sA[rbase + 4];
                af[i][3] = sA[rbase + 8 * 36 + 4];
            }
            uint32_t bf[4][2];
#pragma unroll
            for (int j = 0; j < 4; j++) {
                const int col = wn * 32 + j * 8 + g;
                bf[j][0] = sB[(kb + tq) * 72 + col];
                bf[j][1] = sB[(kb + tq + 4) * 72 + col];
            }
#pragma unroll
            for (int i = 0; i < 2; i++)
#pragma unroll
                for (int j = 0; j < 4; j++)
                    mma_tf32(acc[i][j], af[i][0], af[i][1], af[i][2], af[i][3],
                             bf[j][0], bf[j][1]);
        }
        __syncthreads();
    }

    // ---- epilogue ----
    const int region = n0 / EMB;
#pragma unroll
    for (int i = 0; i < 2; i++) {
        const int row = m0 + wm * 32 + i * 16 + g;
#pragma unroll
        for (int j = 0; j < 4; j++) {
            const int col = n0 + wn * 32 + j * 8 + 2 * tq;
            const float b0 = bias[col], b1 = bias[col + 1];
            float v00 = acc[i][j][0] + b0, v01 = acc[i][j][1] + b1;
            float v10 = acc[i][j][2] + b0, v11 = acc[i][j][3] + b1;
            if (MODE == 0) {
                *reinterpret_cast<float2*>(&C[(size_t)row * N + col]) =
                    make_float2(v00, v01);
                *reinterpret_cast<float2*>(&C[(size_t)(row + 8) * N + col]) =
                    make_float2(v10, v11);
            } else {
                const int cemb = col - region * EMB;
                const size_t a0 = (size_t)row * EMB + cemb;
                const size_t a1 = (size_t)(row + 8) * EMB + cemb;
                uint32_t* dst = (region == 0) ? qtf : (region == 1) ? ktf : vtf;
                const float sc = (region == 0) ? 0.125f : 1.0f;
                *reinterpret_cast<uint2*>(&dst[a0]) =
                    make_uint2(to_tf32(sc * v00), to_tf32(sc * v01));
                *reinterpret_cast<uint2*>(&dst[a1]) =
                    make_uint2(to_tf32(sc * v10), to_tf32(sc * v11));
            }
        }
    }
}

// ============================ mask handling =================================
__global__ void mask_detect_kernel(const unsigned int* __restrict__ mask) {
    unsigned int w0 = mask[0];
    int esize;
    if (w0 == 0x01010101u) esize = 1;
    else if (w0 == 1u || w0 == 0x3f800000u) esize = 4;
    else if ((w0 & 0xFFu) != 0u || (w0 >> 8) == 0u) esize = 1;
    else esize = 4;
    g_mask_esize = esize;
    g_mask_allones = 1;
}

__device__ __forceinline__ unsigned int haszero_byte(unsigned int v) {
    return (v - 0x01010101u) & ~v & 0x80808080u;
}

__global__ void mask_scan_kernel(const uint4* __restrict__ mask) {
    const int esize = g_mask_esize;
    unsigned int any = 0;
    if (esize == 4) {
        const int n = MASKN / 4;   // uint4 count
        for (int i = blockIdx.x * blockDim.x + threadIdx.x; i < n;
             i += gridDim.x * blockDim.x) {
            uint4 w = mask[i];
            any |= (w.x == 0u) | (w.y == 0u) | (w.z == 0u) | (w.w == 0u);
        }
    } else {
        const int n = MASKN / 16;  // uint4 count, 16 bytes each
        for (int i = blockIdx.x * blockDim.x + threadIdx.x; i < n;
             i += gridDim.x * blockDim.x) {
            uint4 w = mask[i];
            any |= haszero_byte(w.x) | haszero_byte(w.y) |
                   haszero_byte(w.z) | haszero_byte(w.w);
        }
    }
    if (any) g_mask_allones = 0;
}

// ============================ attention via mma.sync ========================
// 256 threads (8 warps), 128 query rows, chunks of 64 keys, double-buffered
// cp.async K/V. All operands single tf32. P stays in REGISTERS — the PV MMA
// enumerates keys in permuted order (k-pos tq -> key 2tq, k-pos tq+4 -> key
// 2tq+1) so the S-accumulator layout IS the PV a-fragment layout.
// smem floats per stage s: K @ s*9216 [64][68]; V @ s*9216+4352 [64][76].
// Total 18432 fl = 73728 B -> 2 CTAs/SM.
#define AT4_BYTES (18432 * 4)

__global__ void __launch_bounds__(256, 2)
attn_mma_kernel(const uint32_t* __restrict__ qtf, const uint32_t* __restrict__ ktf,
                const uint32_t* __restrict__ vtf,
                const void* __restrict__ mask,
                uint32_t* __restrict__ atttf) {
    extern __shared__ float sh[];
    const uint32_t sb = (uint32_t)__cvta_generic_to_shared(sh);

    const int tid = threadIdx.x;
    const int wid = tid >> 5;
    const int lane = tid & 31;
    const int g  = lane >> 2;
    const int tq = lane & 3;
    const int wq = wid * 16;
    const int q0 = blockIdx.x * 128;
    const int h  = blockIdx.y;
    const int b  = blockIdx.z;

    const int mask_allones = g_mask_allones;
    const int mask_esize   = g_mask_esize;
    const size_t rbase = (size_t)b * SEQ;
    const int hoff = h * DIM;
    const size_t mask_base = (size_t)b * SEQ * SEQ;

    auto issue_kv = [&](int s, int kt) {
        const int k0 = kt * 64;
#pragma unroll
        for (int p = 0; p < 4; p++) {          // K: 64 rows x 16 chunks
            int idx = p * 256 + tid;
            int key = idx >> 4, c = idx & 15;
            const uint32_t* src = ktf + (rbase + k0 + key) * EMB + hoff + c * 4;
            uint32_t dst = sb + (s * 9216 + key * 68 + c * 4) * 4;
            CP16(dst, src);
        }
#pragma unroll
        for (int p = 0; p < 4; p++) {          // V: 64 rows x 16 chunks
            int idx = p * 256 + tid;
            int key = idx >> 4, c = idx & 15;
            const uint32_t* src = vtf + (rbase + k0 + key) * EMB + hoff + c * 4;
            uint32_t dst = sb + (s * 9216 + 4352 + key * 76 + c * 4) * 4;
            CP16(dst, src);
        }
        CP_COMMIT();
    };

    // ---- stage Q into stage-1 region, read fragments, then start K/V ----
#pragma unroll
    for (int p = 0; p < 8; p++) {
        int idx = p * 256 + tid;
        int r = idx >> 4, c = idx & 15;
        const uint32_t* src = qtf + (rbase + q0 + r) * EMB + hoff + c * 4;
        uint32_t dst = sb + (9216 + r * 68 + c * 4) * 4;
        CP16(dst, src);
    }
    CP_COMMIT();
    CP_WAIT0();
    __syncthreads();

    const uint32_t* Qstage = reinterpret_cast<const uint32_t*>(sh + 9216);
    uint32_t qf[8][4];
#pragma unroll
    for (int kb = 0; kb < 8; kb++) {
        const int r0 = (wq + g) * 68 + kb * 8 + tq;
        const int r1 = (wq + g + 8) * 68 + kb * 8 + tq;
        qf[kb][0] = Qstage[r0];
        qf[kb][1] = Qstage[r1];
        qf[kb][2] = Qstage[r0 + 4];
        qf[kb][3] = Qstage[r1 + 4];
    }
    __syncthreads();
    issue_kv(0, 0);

    float o[8][4];
#pragma unroll
    for (int nt = 0; nt < 8; nt++)
#pragma unroll
        for (int r = 0; r < 4; r++) o[nt][r] = 0.0f;
    float m0r = -1e30f, m1r = -1e30f, l0r = 0.0f, l1r = 0.0f;

    const int nkt = SEQ / 64;
    for (int kt = 0; kt < nkt; kt++) {
        const int s = kt & 1;
        const int k0 = kt * 64;
        if (kt + 1 < nkt) {
            issue_kv(1 - s, kt + 1);
            CP_WAIT1();
        } else {
            CP_WAIT0();
        }
        __syncthreads();

        const uint32_t* Ktf_s = reinterpret_cast<const uint32_t*>(sh + s * 9216);
        const uint32_t* Vtf_s = reinterpret_cast<const uint32_t*>(sh + s * 9216 + 4352);

        // ---- S = (Q/8) K^T ----
        float s4[8][4];
#pragma unroll
        for (int nt = 0; nt < 8; nt++)
#pragma unroll
            for (int r = 0; r < 4; r++) s4[nt][r] = 0.0f;
#pragma unroll
        for (int kb = 0; kb < 8; kb++) {
#pragma unroll
            for (int nt = 0; nt < 8; nt++) {
                uint32_t b0 = Ktf_s[(nt * 8 + g) * 68 + kb * 8 + tq];
                uint32_t b1 = Ktf_s[(nt * 8 + g) * 68 + kb * 8 + tq + 4];
                mma_tf32(s4[nt], qf[kb][0], qf[kb][1], qf[kb][2], qf[kb][3], b0, b1);
            }
        }

        // ---- mask ----
        if (!mask_allones) {
            const int qg0 = q0 + wq + g, qg1 = qg0 + 8;
#pragma unroll
            for (int nt = 0; nt < 8; nt++) {
                int kcol = k0 + nt * 8 + 2 * tq;
                bool mk[4];
                if (mask_esize == 4) {
                    const unsigned int* mm = (const unsigned int*)mask;
                    mk[0] = mm[mask_base + (size_t)qg0 * SEQ + kcol] != 0;
                    mk[1] = mm[mask_base + (size_t)qg0 * SEQ + kcol + 1] != 0;
                    mk[2] = mm[mask_base + (size_t)qg1 * SEQ + kcol] != 0;
                    mk[3] = mm[mask_base + (size_t)qg1 * SEQ + kcol + 1] != 0;
                } else {
                    const unsigned char* mm = (const unsigned char*)mask;
                    mk[0] = mm[mask_base + (size_t)qg0 * SEQ + kcol] != 0;
                    mk[1] = mm[mask_base + (size_t)qg0 * SEQ + kcol + 1] != 0;
                    mk[2] = mm[mask_base + (size_t)qg1 * SEQ + kcol] != 0;
                    mk[3] = mm[mask_base + (size_t)qg1 * SEQ + kcol + 1] != 0;
                }
#pragma unroll
                for (int r = 0; r < 4; r++)
                    if (!mk[r]) s4[nt][r] = -1e9f;
            }
        }

        // ---- online softmax ----
        float mt0 = -1e30f, mt1 = -1e30f;
#pragma unroll
        for (int nt = 0; nt < 8; nt++) {
            mt0 = fmaxf(mt0, fmaxf(s4[nt][0], s4[nt][1]));
            mt1 = fmaxf(mt1, fmaxf(s4[nt][2], s4[nt][3]));
        }
        mt0 = fmaxf(mt0, __shfl_xor_sync(0xffffffff, mt0, 1));
        mt0 = fmaxf(mt0, __shfl_xor_sync(0xffffffff, mt0, 2));
        mt1 = fmaxf(mt1, __shfl_xor_sync(0xffffffff, mt1, 1));
        mt1 = fmaxf(mt1, __shfl_xor_sync(0xffffffff, mt1, 2));

        float mn0 = fmaxf(m0r, mt0), mn1 = fmaxf(m1r, mt1);
        float a0 = __expf(m0r - mn0), a1 = __expf(m1r - mn1);
        m0r = mn0; m1r = mn1;

        float lt0 = 0.0f, lt1 = 0.0f;
#pragma unroll
        for (int nt = 0; nt < 8; nt++) {
            s4[nt][0] = __expf(s4[nt][0] - mn0);
            s4[nt][1] = __expf(s4[nt][1] - mn0);
            s4[nt][2] = __expf(s4[nt][2] - mn1);
            s4[nt][3] = __expf(s4[nt][3] - mn1);
            lt0 += s4[nt][0] + s4[nt][1];
            lt1 += s4[nt][2] + s4[nt][3];
        }
        lt0 += __shfl_xor_sync(0xffffffff, lt0, 1);
        lt0 += __shfl_xor_sync(0xffffffff, lt0, 2);
        lt1 += __shfl_xor_sync(0xffffffff, lt1, 1);
        lt1 += __shfl_xor_sync(0xffffffff, lt1, 2);
        l0r = l0r * a0 + lt0;
        l1r = l1r * a1 + lt1;

#pragma unroll
        for (int nt = 0; nt < 8; nt++) {
            o[nt][0] *= a0; o[nt][1] *= a0;
            o[nt][2] *= a1; o[nt][3] *= a1;
        }

        // ---- O += P @ V  (P in registers; keys permuted per 8-block:
        //      k-pos tq -> key 2tq, k-pos tq+4 -> key 2tq+1) ----
#pragma unroll
        for (int kb = 0; kb < 8; kb++) {
            // a-frag = (c0, c2, c1, c3) of the exp'd accumulator
            uint32_t pa0 = to_tf32(s4[kb][0]);
            uint32_t pa1 = to_tf32(s4[kb][2]);
            uint32_t pa2 = to_tf32(s4[kb][1]);
            uint32_t pa3 = to_tf32(s4[kb][3]);
            const int vr0 = (kb * 8 + 2 * tq) * 76;      // key 2tq
            const int vr1 = (kb * 8 + 2 * tq + 1) * 76;  // key 2tq+1
#pragma unroll
            for (int nt = 0; nt < 8; nt++) {
                const int d = nt * 8 + g;
                mma_tf32(o[nt], pa0, pa1, pa2, pa3,
                         Vtf_s[vr0 + d], Vtf_s[vr1 + d]);
            }
        }
        __syncthreads();   // protect buffer 1-s before next issue
    }

    // ---- write output as single tf32 ----
    const float inv0 = 1.0f / l0r, inv1 = 1.0f / l1r;
    const size_t row0 = rbase + q0 + wq + g;
    const size_t row1 = row0 + 8;
#pragma unroll
    for (int nt = 0; nt < 8; nt++) {
        const int col = hoff + nt * 8 + 2 * tq;
        *reinterpret_cast<uint2*>(&atttf[row0 * EMB + col]) =
            make_uint2(to_tf32(o[nt][0] * inv0), to_tf32(o[nt][1] * inv0));
        *reinterpret_cast<uint2*>(&atttf[row1 * EMB + col]) =
            make_uint2(to_tf32(o[nt][2] * inv1), to_tf32(o[nt][3] * inv1));
    }
}

// ============================================================================
extern "C" void kernel_launch(void* const* d_in, const int* in_sizes, int n_in,
                              void* d_out, int out_size) {
    const float* x      = (const float*)d_in[0];
    const void*  mask   = d_in[1];
    const float* W_pre  = (const float*)d_in[2];
    const float* b_pre  = (const float*)d_in[3];
    const float* W_proj = (const float*)d_in[4];
    const float* b_proj = (const float*)d_in[5];
    float* out = (float*)d_out;

    uint32_t *qtf, *ktf, *vtf, *xtf, *atttf, *wpretf, *wprojtf;
    cudaGetSymbolAddress((void**)&qtf, g_qtf);
    cudaGetSymbolAddress((void**)&ktf, g_ktf);
    cudaGetSymbolAddress((void**)&vtf, g_vtf);
    cudaGetSymbolAddress((void**)&xtf, g_xtf);
    cudaGetSymbolAddress((void**)&atttf, g_atttf);
    cudaGetSymbolAddress((void**)&wpretf, g_wpretf);
    cudaGetSymbolAddress((void**)&wprojtf, g_wprojtf);

    mask_detect_kernel<<<1, 1>>>((const unsigned int*)mask);
    mask_scan_kernel<<<512, 256>>>((const uint4*)mask);

    cvt_kernel<<<512, 256>>>((const float4*)x, (uint4*)xtf, ROWS * EMB / 4);
    cvt_kernel<<<1024, 256>>>((const float4*)W_pre, (uint4*)wpretf,
                              EMB * QKVN / 4);
    cvt_kernel<<<512, 256>>>((const float4*)W_proj, (uint4*)wprojtf,
                             EMB * EMB / 4);

    cudaFuncSetAttribute(gemm_tf_kernel<0>,
                         cudaFuncAttributeMaxDynamicSharedMemorySize, G4_BYTES);
    cudaFuncSetAttribute(gemm_tf_kernel<1>,
                         cudaFuncAttributeMaxDynamicSharedMemorySize, G4_BYTES);
    cudaFuncSetAttribute(attn_mma_kernel,
                         cudaFuncAttributeMaxDynamicSharedMemorySize, AT4_BYTES);

    // 1) QKV GEMM -> attention-ready operands
    {
        dim3 grid(QKVN / 64, ROWS / 128);
        gemm_tf_kernel<1><<<grid, 256, G4_BYTES>>>(
            xtf, wpretf, b_pre, nullptr, qtf, ktf, vtf, ROWS, QKVN, EMB);
    }
    // 2) Attention (P register-resident via permuted-key PV)
    {
        dim3 grid(SEQ / 128, HEADS, BATCH);
        attn_mma_kernel<<<grid, 256, AT4_BYTES>>>(qtf, ktf, vtf, mask, atttf);
    }
    // 3) Projection GEMM
    {
        dim3 grid(EMB / 64, ROWS / 128);
        gemm_tf_kernel<0><<<grid, 256, G4_BYTES>>>(
            atttf, wprojtf, b_proj, out, nullptr, nullptr, nullptr,
            ROWS, EMB, EMB);
    }
}

// round 13
// speedup vs baseline: 3.9116x; 1.0610x over previous
#include <cuda_runtime.h>
#include <math.h>
#include <stdint.h>

#define HEADS 12
#define DIM   64
#define BATCH 2
#define SEQ   2048
#define EMB   768
#define QKVN  (3 * HEADS * DIM)   // 2304
#define ROWS  (BATCH * SEQ)       // 4096
#define MASKN (BATCH * SEQ * SEQ) // 8388608

// ----- device scratch (all tf32-as-uint32) -----
__device__ uint32_t g_qtf[ROWS * EMB];
__device__ uint32_t g_ktf[ROWS * EMB];
__device__ uint32_t g_vtf[ROWS * EMB];
__device__ uint32_t g_xtf[ROWS * EMB];
__device__ uint32_t g_atttf[ROWS * EMB];
__device__ uint32_t g_wpretf[EMB * QKVN];
__device__ uint32_t g_wprojtf[EMB * EMB];
__device__ int   g_mask_esize;
__device__ int   g_mask_allones;

// ============================ helpers =======================================
__device__ __forceinline__ uint32_t to_tf32(float x) {
    uint32_t r;
    asm("cvt.rna.tf32.f32 %0, %1;" : "=r"(r) : "f"(x));
    return r;
}
__device__ __forceinline__ void mma_tf32(float c[4],
                                         uint32_t a0, uint32_t a1, uint32_t a2, uint32_t a3,
                                         uint32_t b0, uint32_t b1) {
    asm volatile(
        "mma.sync.aligned.m16n8k8.row.col.f32.tf32.tf32.f32 "
        "{%0,%1,%2,%3}, {%4,%5,%6,%7}, {%8,%9}, {%0,%1,%2,%3};"
        : "+f"(c[0]), "+f"(c[1]), "+f"(c[2]), "+f"(c[3])
        : "r"(a0), "r"(a1), "r"(a2), "r"(a3), "r"(b0), "r"(b1));
}
#define CP16(dst, src) \
    asm volatile("cp.async.ca.shared.global [%0], [%1], 16;" :: "r"(dst), "l"(src) : "memory")
#define CP_COMMIT() asm volatile("cp.async.commit_group;" ::: "memory")
#define CP_WAIT1() asm volatile("cp.async.wait_group 1;" ::: "memory")
#define CP_WAIT0() asm volatile("cp.async.wait_group 0;" ::: "memory")

// ============================ prepass: fp32 -> tf32 =========================
__global__ void cvt_kernel(const float4* __restrict__ in,
                           uint4* __restrict__ out, int n4) {
    for (int i = blockIdx.x * blockDim.x + threadIdx.x; i < n4;
         i += gridDim.x * blockDim.x) {
        float4 v = in[i];
        out[i] = make_uint4(to_tf32(v.x), to_tf32(v.y), to_tf32(v.z), to_tf32(v.w));
    }
}

// ============================ GEMM 128x128 tile (single tf32) ===============
// smem bytes: A stage s @ s*18432 ([128][36] u32); B stage s @ 36864+s*17408
// ([32][136] u32). Total 71680.
#define G5_BYTES 71680

template <int MODE>
__global__ void __launch_bounds__(256, 2)
gemm_tf_kernel(const uint32_t* __restrict__ Atf, const uint32_t* __restrict__ Btf,
               const float* __restrict__ bias, float* __restrict__ C,
               uint32_t* __restrict__ qtf, uint32_t* __restrict__ ktf,
               uint32_t* __restrict__ vtf,
               int M, int N, int K) {
    extern __shared__ char smraw[];
    uint32_t* usm = reinterpret_cast<uint32_t*>(smraw);
    const uint32_t sb = (uint32_t)__cvta_generic_to_shared(smraw);

    const int tid = threadIdx.x;
    const int wid = tid >> 5;
    const int lane = tid & 31;
    const int g  = lane >> 2;
    const int tq = lane & 3;
    const int wm = wid >> 1;          // 0..3 -> 32 rows each
    const int wn = wid & 1;           // 0..1 -> 64 cols each
    const int m0 = blockIdx.y * 128;
    const int n0 = blockIdx.x * 128;
    const int nkt = K / 32;

    float acc[2][8][4];
#pragma unroll
    for (int i = 0; i < 2; i++)
#pragma unroll
        for (int j = 0; j < 8; j++)
#pragma unroll
            for (int r = 0; r < 4; r++) acc[i][j][r] = 0.0f;

    auto issue_tile = [&](int s, int kt) {
#pragma unroll
        for (int p = 0; p < 4; p++) {          // A: 128x32 = 1024 chunks
            int idx = p * 256 + tid;
            int r = idx >> 3, ch = idx & 7;
            const uint32_t* src = Atf + (size_t)(m0 + r) * K + kt * 32 + ch * 4;
            uint32_t dst = sb + s * 18432 + (r * 36 + ch * 4) * 4;
            CP16(dst, src);
        }
#pragma unroll
        for (int p = 0; p < 4; p++) {          // B: 32x128 = 1024 chunks
            int idx = p * 256 + tid;
            int r = idx >> 5, ch = idx & 31;
            const uint32_t* src = Btf + (size_t)(kt * 32 + r) * N + n0 + ch * 4;
            uint32_t dst = sb + 36864 + s * 17408 + (r * 136 + ch * 4) * 4;
            CP16(dst, src);
        }
        CP_COMMIT();
    };

    issue_tile(0, 0);

    for (int kt = 0; kt < nkt; kt++) {
        const int s = kt & 1;
        if (kt + 1 < nkt) {
            issue_tile(1 - s, kt + 1);
            CP_WAIT1();
        } else {
            CP_WAIT0();
        }
        __syncthreads();

        const uint32_t* sA = usm + s * 4608;
        const uint32_t* sB = usm + 9216 + s * 4352;

#pragma unroll
        for (int ks = 0; ks < 4; ks++) {
            const int kb = ks * 8;
            uint32_t af[2][4];
#pragma unroll
            for (int i = 0; i < 2; i++) {
                const int rbase = (wm * 32 + i * 16 + g) * 36 + kb + tq;
                af[i][0] = sA[rbase];
                af[i][1] = sA[rbase + 8 * 36];
                af[i][2] = sA[rbase + 4];
                af[i][3] = sA[rbase + 8 * 36 + 4];
            }
            uint32_t bf[8][2];
#pragma unroll
            for (int j = 0; j < 8; j++) {
                const int col = wn * 64 + j * 8 + g;
                bf[j][0] = sB[(kb + tq) * 136 + col];
                bf[j][1] = sB[(kb + tq + 4) * 136 + col];
            }
#pragma unroll
            for (int i = 0; i < 2; i++)
#pragma unroll
                for (int j = 0; j < 8; j++)
                    mma_tf32(acc[i][j], af[i][0], af[i][1], af[i][2], af[i][3],
                             bf[j][0], bf[j][1]);
        }
        __syncthreads();
    }

    // ---- epilogue ----
    const int region = n0 / EMB;   // block-uniform: 128 | 768 boundaries align
#pragma unroll
    for (int i = 0; i < 2; i++) {
        const int row = m0 + wm * 32 + i * 16 + g;
#pragma unroll
        for (int j = 0; j < 8; j++) {
            const int col = n0 + wn * 64 + j * 8 + 2 * tq;
            const float b0 = bias[col], b1 = bias[col + 1];
            float v00 = acc[i][j][0] + b0, v01 = acc[i][j][1] + b1;
            float v10 = acc[i][j][2] + b0, v11 = acc[i][j][3] + b1;
            if (MODE == 0) {
                *reinterpret_cast<float2*>(&C[(size_t)row * N + col]) =
                    make_float2(v00, v01);
                *reinterpret_cast<float2*>(&C[(size_t)(row + 8) * N + col]) =
                    make_float2(v10, v11);
            } else {
                const int cemb = col - region * EMB;
                const size_t a0 = (size_t)row * EMB + cemb;
                const size_t a1 = (size_t)(row + 8) * EMB + cemb;
                uint32_t* dst = (region == 0) ? qtf : (region == 1) ? ktf : vtf;
                const float sc = (region == 0) ? 0.125f : 1.0f;
                *reinterpret_cast<uint2*>(&dst[a0]) =
                    make_uint2(to_tf32(sc * v00), to_tf32(sc * v01));
                *reinterpret_cast<uint2*>(&dst[a1]) =
                    make_uint2(to_tf32(sc * v10), to_tf32(sc * v11));
            }
        }
    }
}

// ============================ mask handling =================================
__global__ void mask_detect_kernel(const unsigned int* __restrict__ mask) {
    unsigned int w0 = mask[0];
    int esize;
    if (w0 == 0x01010101u) esize = 1;
    else if (w0 == 1u || w0 == 0x3f800000u) esize = 4;
    else if ((w0 & 0xFFu) != 0u || (w0 >> 8) == 0u) esize = 1;
    else esize = 4;
    g_mask_esize = esize;
    g_mask_allones = 1;
}

__device__ __forceinline__ unsigned int haszero_byte(unsigned int v) {
    return (v - 0x01010101u) & ~v & 0x80808080u;
}

__global__ void mask_scan_kernel(const uint4* __restrict__ mask) {
    const int esize = g_mask_esize;
    unsigned int any = 0;
    if (esize == 4) {
        const int n = MASKN / 4;
        for (int i = blockIdx.x * blockDim.x + threadIdx.x; i < n;
             i += gridDim.x * blockDim.x) {
            uint4 w = mask[i];
            any |= (w.x == 0u) | (w.y == 0u) | (w.z == 0u) | (w.w == 0u);
        }
    } else {
        const int n = MASKN / 16;
        for (int i = blockIdx.x * blockDim.x + threadIdx.x; i < n;
             i += gridDim.x * blockDim.x) {
            uint4 w = mask[i];
            any |= haszero_byte(w.x) | haszero_byte(w.y) |
                   haszero_byte(w.z) | haszero_byte(w.w);
        }
    }
    if (any) g_mask_allones = 0;
}

// ============================ attention (unchanged from R11 winner) =========
#define AT4_BYTES (18432 * 4)

__global__ void __launch_bounds__(256, 2)
attn_mma_kernel(const uint32_t* __restrict__ qtf, const uint32_t* __restrict__ ktf,
                const uint32_t* __restrict__ vtf,
                const void* __restrict__ mask,
                uint32_t* __restrict__ atttf) {
    extern __shared__ float sh[];
    const uint32_t sb = (uint32_t)__cvta_generic_to_shared(sh);

    const int tid = threadIdx.x;
    const int wid = tid >> 5;
    const int lane = tid & 31;
    const int g  = lane >> 2;
    const int tq = lane & 3;
    const int wq = wid * 16;
    const int q0 = blockIdx.x * 128;
    const int h  = blockIdx.y;
    const int b  = blockIdx.z;

    const int mask_allones = g_mask_allones;
    const int mask_esize   = g_mask_esize;
    const size_t rbase = (size_t)b * SEQ;
    const int hoff = h * DIM;
    const size_t mask_base = (size_t)b * SEQ * SEQ;

    auto issue_kv = [&](int s, int kt) {
        const int k0 = kt * 64;
#pragma unroll
        for (int p = 0; p < 4; p++) {
            int idx = p * 256 + tid;
            int key = idx >> 4, c = idx & 15;
            const uint32_t* src = ktf + (rbase + k0 + key) * EMB + hoff + c * 4;
            uint32_t dst = sb + (s * 9216 + key * 68 + c * 4) * 4;
            CP16(dst, src);
        }
#pragma unroll
        for (int p = 0; p < 4; p++) {
            int idx = p * 256 + tid;
            int key = idx >> 4, c = idx & 15;
            const uint32_t* src = vtf + (rbase + k0 + key) * EMB + hoff + c * 4;
            uint32_t dst = sb + (s * 9216 + 4352 + key * 76 + c * 4) * 4;
            CP16(dst, src);
        }
        CP_COMMIT();
    };

#pragma unroll
    for (int p = 0; p < 8; p++) {
        int idx = p * 256 + tid;
        int r = idx >> 4, c = idx & 15;
        const uint32_t* src = qtf + (rbase + q0 + r) * EMB + hoff + c * 4;
        uint32_t dst = sb + (9216 + r * 68 + c * 4) * 4;
        CP16(dst, src);
    }
    CP_COMMIT();
    CP_WAIT0();
    __syncthreads();

    const uint32_t* Qstage = reinterpret_cast<const uint32_t*>(sh + 9216);
    uint32_t qf[8][4];
#pragma unroll
    for (int kb = 0; kb < 8; kb++) {
        const int r0 = (wq + g) * 68 + kb * 8 + tq;
        const int r1 = (wq + g + 8) * 68 + kb * 8 + tq;
        qf[kb][0] = Qstage[r0];
        qf[kb][1] = Qstage[r1];
        qf[kb][2] = Qstage[r0 + 4];
        qf[kb][3] = Qstage[r1 + 4];
    }
    __syncthreads();
    issue_kv(0, 0);

    float o[8][4];
#pragma unroll
    for (int nt = 0; nt < 8; nt++)
#pragma unroll
        for (int r = 0; r < 4; r++) o[nt][r] = 0.0f;
    float m0r = -1e30f, m1r = -1e30f, l0r = 0.0f, l1r = 0.0f;

    const int nkt = SEQ / 64;
    for (int kt = 0; kt < nkt; kt++) {
        const int s = kt & 1;
        const int k0 = kt * 64;
        if (kt + 1 < nkt) {
            issue_kv(1 - s, kt + 1);
            CP_WAIT1();
        } else {
            CP_WAIT0();
        }
        __syncthreads();

        const uint32_t* Ktf_s = reinterpret_cast<const uint32_t*>(sh + s * 9216);
        const uint32_t* Vtf_s = reinterpret_cast<const uint32_t*>(sh + s * 9216 + 4352);

        float s4[8][4];
#pragma unroll
        for (int nt = 0; nt < 8; nt++)
#pragma unroll
            for (int r = 0; r < 4; r++) s4[nt][r] = 0.0f;
#pragma unroll
        for (int kb = 0; kb < 8; kb++) {
#pragma unroll
            for (int nt = 0; nt < 8; nt++) {
                uint32_t b0 = Ktf_s[(nt * 8 + g) * 68 + kb * 8 + tq];
                uint32_t b1 = Ktf_s[(nt * 8 + g) * 68 + kb * 8 + tq + 4];
                mma_tf32(s4[nt], qf[kb][0], qf[kb][1], qf[kb][2], qf[kb][3], b0, b1);
            }
        }

        if (!mask_allones) {
            const int qg0 = q0 + wq + g, qg1 = qg0 + 8;
#pragma unroll
            for (int nt = 0; nt < 8; nt++) {
                int kcol = k0 + nt * 8 + 2 * tq;
                bool mk[4];
                if (mask_esize == 4) {
                    const unsigned int* mm = (const unsigned int*)mask;
                    mk[0] = mm[mask_base + (size_t)qg0 * SEQ + kcol] != 0;
                    mk[1] = mm[mask_base + (size_t)qg0 * SEQ + kcol + 1] != 0;
                    mk[2] = mm[mask_base + (size_t)qg1 * SEQ + kcol] != 0;
                    mk[3] = mm[mask_base + (size_t)qg1 * SEQ + kcol + 1] != 0;
                } else {
                    const unsigned char* mm = (const unsigned char*)mask;
                    mk[0] = mm[mask_base + (size_t)qg0 * SEQ + kcol] != 0;
                    mk[1] = mm[mask_base + (size_t)qg0 * SEQ + kcol + 1] != 0;
                    mk[2] = mm[mask_base + (size_t)qg1 * SEQ + kcol] != 0;
                    mk[3] = mm[mask_base + (size_t)qg1 * SEQ + kcol + 1] != 0;
                }
#pragma unroll
                for (int r = 0; r < 4; r++)
                    if (!mk[r]) s4[nt][r] = -1e9f;
            }
        }

        float mt0 = -1e30f, mt1 = -1e30f;
#pragma unroll
        for (int nt = 0; nt < 8; nt++) {
            mt0 = fmaxf(mt0, fmaxf(s4[nt][0], s4[nt][1]));
            mt1 = fmaxf(mt1, fmaxf(s4[nt][2], s4[nt][3]));
        }
        mt0 = fmaxf(mt0, __shfl_xor_sync(0xffffffff, mt0, 1));
        mt0 = fmaxf(mt0, __shfl_xor_sync(0xffffffff, mt0, 2));
        mt1 = fmaxf(mt1, __shfl_xor_sync(0xffffffff, mt1, 1));
        mt1 = fmaxf(mt1, __shfl_xor_sync(0xffffffff, mt1, 2));

        float mn0 = fmaxf(m0r, mt0), mn1 = fmaxf(m1r, mt1);
        float a0 = __expf(m0r - mn0), a1 = __expf(m1r - mn1);
        m0r = mn0; m1r = mn1;

        float lt0 = 0.0f, lt1 = 0.0f;
#pragma unroll
        for (int nt = 0; nt < 8; nt++) {
            s4[nt][0] = __expf(s4[nt][0] - mn0);
            s4[nt][1] = __expf(s4[nt][1] - mn0);
            s4[nt][2] = __expf(s4[nt][2] - mn1);
            s4[nt][3] = __expf(s4[nt][3] - mn1);
            lt0 += s4[nt][0] + s4[nt][1];
            lt1 += s4[nt][2] + s4[nt][3];
        }
        lt0 += __shfl_xor_sync(0xffffffff, lt0, 1);
        lt0 += __shfl_xor_sync(0xffffffff, lt0, 2);
        lt1 += __shfl_xor_sync(0xffffffff, lt1, 1);
        lt1 += __shfl_xor_sync(0xffffffff, lt1, 2);
        l0r = l0r * a0 + lt0;
        l1r = l1r * a1 + lt1;

#pragma unroll
        for (int nt = 0; nt < 8; nt++) {
            o[nt][0] *= a0; o[nt][1] *= a0;
            o[nt][2] *= a1; o[nt][3] *= a1;
        }

#pragma unroll
        for (int kb = 0; kb < 8; kb++) {
            uint32_t pa0 = to_tf32(s4[kb][0]);
            uint32_t pa1 = to_tf32(s4[kb][2]);
            uint32_t pa2 = to_tf32(s4[kb][1]);
            uint32_t pa3 = to_tf32(s4[kb][3]);
            const int vr0 = (kb * 8 + 2 * tq) * 76;
            const int vr1 = (kb * 8 + 2 * tq + 1) * 76;
#pragma unroll
            for (int nt = 0; nt < 8; nt++) {
                const int d = nt * 8 + g;
                mma_tf32(o[nt], pa0, pa1, pa2, pa3,
                         Vtf_s[vr0 + d], Vtf_s[vr1 + d]);
            }
        }
        __syncthreads();
    }

    const float inv0 = 1.0f / l0r, inv1 = 1.0f / l1r;
    const size_t row0 = rbase + q0 + wq + g;
    const size_t row1 = row0 + 8;
#pragma unroll
    for (int nt = 0; nt < 8; nt++) {
        const int col = hoff + nt * 8 + 2 * tq;
        *reinterpret_cast<uint2*>(&atttf[row0 * EMB + col]) =
            make_uint2(to_tf32(o[nt][0] * inv0), to_tf32(o[nt][1] * inv0));
        *reinterpret_cast<uint2*>(&atttf[row1 * EMB + col]) =
            make_uint2(to_tf32(o[nt][2] * inv1), to_tf32(o[nt][3] * inv1));
    }
}

// ============================================================================
extern "C" void kernel_launch(void* const* d_in, const int* in_sizes, int n_in,
                              void* d_out, int out_size) {
    const float* x      = (const float*)d_in[0];
    const void*  mask   = d_in[1];
    const float* W_pre  = (const float*)d_in[2];
    const float* b_pre  = (const float*)d_in[3];
    const float* W_proj = (const float*)d_in[4];
    const float* b_proj = (const float*)d_in[5];
    float* out = (float*)d_out;

    uint32_t *qtf, *ktf, *vtf, *xtf, *atttf, *wpretf, *wprojtf;
    cudaGetSymbolAddress((void**)&qtf, g_qtf);
    cudaGetSymbolAddress((void**)&ktf, g_ktf);
    cudaGetSymbolAddress((void**)&vtf, g_vtf);
    cudaGetSymbolAddress((void**)&xtf, g_xtf);
    cudaGetSymbolAddress((void**)&atttf, g_atttf);
    cudaGetSymbolAddress((void**)&wpretf, g_wpretf);
    cudaGetSymbolAddress((void**)&wprojtf, g_wprojtf);

    mask_detect_kernel<<<1, 1>>>((const unsigned int*)mask);
    mask_scan_kernel<<<512, 256>>>((const uint4*)mask);

    cvt_kernel<<<512, 256>>>((const float4*)x, (uint4*)xtf, ROWS * EMB / 4);
    cvt_kernel<<<1024, 256>>>((const float4*)W_pre, (uint4*)wpretf,
                              EMB * QKVN / 4);
    cvt_kernel<<<512, 256>>>((const float4*)W_proj, (uint4*)wprojtf,
                             EMB * EMB / 4);

    cudaFuncSetAttribute(gemm_tf_kernel<0>,
                         cudaFuncAttributeMaxDynamicSharedMemorySize, G5_BYTES);
    cudaFuncSetAttribute(gemm_tf_kernel<1>,
                         cudaFuncAttributeMaxDynamicSharedMemorySize, G5_BYTES);
    cudaFuncSetAttribute(attn_mma_kernel,
                         cudaFuncAttributeMaxDynamicSharedMemorySize, AT4_BYTES);

    // 1) QKV GEMM -> attention-ready operands
    {
        dim3 grid(QKVN / 128, ROWS / 128);
        gemm_tf_kernel<1><<<grid, 256, G5_BYTES>>>(
            xtf, wpretf, b_pre, nullptr, qtf, ktf, vtf, ROWS, QKVN, EMB);
    }
    // 2) Attention
    {
        dim3 grid(SEQ / 128, HEADS, BATCH);
        attn_mma_kernel<<<grid, 256, AT4_BYTES>>>(qtf, ktf, vtf, mask, atttf);
    }
    // 3) Projection GEMM (single wave: 192 CTAs @ 2/SM)
    {
        dim3 grid(EMB / 128, ROWS / 128);
        gemm_tf_kernel<0><<<grid, 256, G5_BYTES>>>(
            atttf, wprojtf, b_proj, out, nullptr, nullptr, nullptr,
            ROWS, EMB, EMB);
    }
}